// round 1
// baseline (speedup 1.0000x reference)
#include <cuda_runtime.h>

#define BB   8
#define SEQ  1024
#define CC   768
#define NH   12
#define HD   64
#define MM   (BB*SEQ)     // 8192 rows

#define BK   16
#define TP   68           // padded tile row stride (floats), 272B = 16B-aligned
#define AP   68

// Scratch (device-global: allocation-free per harness rules)
__device__ float g_y2[MM*CC];
__device__ float g_q [MM*CC];
__device__ float g_k [MM*CC];
__device__ float g_v [MM*CC];
__device__ float g_ao[MM*CC];

__device__ __forceinline__ float sigmoidf_(float x) { return 1.f/(1.f+__expf(-x)); }

// ---------------------------------------------------------------------------
// Kernel 1: y [B,C,H*W] -> transpose -> layernorm -> g_y2 [B,N,C]
// One block per (b,n) row; C=768 = 3*256.
// ---------------------------------------------------------------------------
__global__ void ln_kernel(const float* __restrict__ y,
                          const float* __restrict__ gam,
                          const float* __restrict__ bet) {
    int m  = blockIdx.x;
    int bb = m >> 10, n = m & 1023;
    const float* yp = y + (size_t)bb*CC*SEQ + n;   // element c at yp[c*SEQ]
    float v[3]; float s = 0.f, s2 = 0.f;
#pragma unroll
    for (int i = 0; i < 3; i++) {
        int c = threadIdx.x + i*256;
        float t = yp[(size_t)c*SEQ];
        v[i] = t; s += t; s2 += t*t;
    }
#pragma unroll
    for (int o = 16; o > 0; o >>= 1) {
        s  += __shfl_xor_sync(0xffffffffu, s,  o);
        s2 += __shfl_xor_sync(0xffffffffu, s2, o);
    }
    __shared__ float rb[2][8];
    if ((threadIdx.x & 31) == 0) { rb[0][threadIdx.x>>5] = s; rb[1][threadIdx.x>>5] = s2; }
    __syncthreads();
    float ts = 0.f, ts2 = 0.f;
#pragma unroll
    for (int i = 0; i < 8; i++) { ts += rb[0][i]; ts2 += rb[1][i]; }
    float mean = ts * (1.f/CC);
    float var  = ts2 * (1.f/CC) - mean*mean;
    float rstd = rsqrtf(var + 1e-5f);
    float* o = g_y2 + (size_t)m*CC;
#pragma unroll
    for (int i = 0; i < 3; i++) {
        int c = threadIdx.x + i*256;
        o[c] = (v[i]-mean)*rstd*gam[c] + bet[c];
    }
}

// ---------------------------------------------------------------------------
// Kernel 2: fused QKV GEMM with gating.
// Computes accx = x@W^T and accy = y2@W^T simultaneously (shared weight tile),
// W = concat(q_w, kv_w) rows. Epilogue applies bias + sigmoid gating and
// scatters to g_q / g_k / g_v in [b][h][n][d] layout.
// Grid: (2304/64, 8192/64) = (36, 128). 256 threads, 4x4 micro-tile (x2 accs).
// ---------------------------------------------------------------------------
__global__ __launch_bounds__(256, 2)
void qkv_kernel(const float* __restrict__ x,
                const float* __restrict__ q_w, const float* __restrict__ q_b,
                const float* __restrict__ kv_w, const float* __restrict__ kv_b) {
    __shared__ float Xs[BK][TP], Ys[BK][TP], Ws[BK][TP];
    int j0 = blockIdx.x * 64, m0 = blockIdx.y * 64;
    const float* wbase = (j0 < CC) ? (q_w + (size_t)j0*CC)
                                   : (kv_w + (size_t)(j0-CC)*CC);
    int t = threadIdx.x, tx = t & 15, ty = t >> 4;
    int lr = t >> 2, lc = (t & 3) * 4;
    const float* xg = x    + (size_t)(m0+lr)*CC + lc;
    const float* yg = g_y2 + (size_t)(m0+lr)*CC + lc;
    const float* wg = wbase + (size_t)lr*CC + lc;

    float accx[4][4], accy[4][4];
#pragma unroll
    for (int i = 0; i < 4; i++)
#pragma unroll
        for (int j = 0; j < 4; j++) { accx[i][j] = 0.f; accy[i][j] = 0.f; }

    for (int k0 = 0; k0 < CC; k0 += BK) {
        float4 xv = *(const float4*)(xg + k0);
        float4 yv = *(const float4*)(yg + k0);
        float4 wv = *(const float4*)(wg + k0);
        Xs[lc+0][lr]=xv.x; Xs[lc+1][lr]=xv.y; Xs[lc+2][lr]=xv.z; Xs[lc+3][lr]=xv.w;
        Ys[lc+0][lr]=yv.x; Ys[lc+1][lr]=yv.y; Ys[lc+2][lr]=yv.z; Ys[lc+3][lr]=yv.w;
        Ws[lc+0][lr]=wv.x; Ws[lc+1][lr]=wv.y; Ws[lc+2][lr]=wv.z; Ws[lc+3][lr]=wv.w;
        __syncthreads();
#pragma unroll
        for (int kk = 0; kk < BK; kk++) {
            float4 a4 = *(const float4*)&Xs[kk][ty*4];
            float4 b4 = *(const float4*)&Ys[kk][ty*4];
            float4 w4 = *(const float4*)&Ws[kk][tx*4];
            float av[4] = {a4.x,a4.y,a4.z,a4.w};
            float bv[4] = {b4.x,b4.y,b4.z,b4.w};
            float wr[4] = {w4.x,w4.y,w4.z,w4.w};
#pragma unroll
            for (int i = 0; i < 4; i++)
#pragma unroll
                for (int j = 0; j < 4; j++) {
                    accx[i][j] += av[i]*wr[j];
                    accy[i][j] += bv[i]*wr[j];
                }
        }
        __syncthreads();
    }

#pragma unroll
    for (int i = 0; i < 4; i++) {
        int m  = m0 + ty*4 + i;
        int bb = m >> 10, n = m & 1023;
#pragma unroll
        for (int j = 0; j < 4; j++) {
            int cc = j0 + tx*4 + j;
            if (cc < CC) {
                float bia = q_b[cc];
                float q0  = accx[i][j] + bia;
                float yq  = sigmoidf_(accy[i][j] + bia);
                int h = cc >> 6, d = cc & 63;
                g_q[(((size_t)bb*NH + h)*SEQ + n)*HD + d] = q0*(1.f + yq);
            } else {
                int jc = cc - CC;                  // 0..1535 (kv index)
                float bia = kv_b[jc];
                float kv0 = accx[i][j] + bia;
                float sg  = sigmoidf_(accy[i][j] + bia);
                float val = sg*(kv0 + 1.f);
                if (jc < CC) { int h=jc>>6, d=jc&63;
                    g_k[(((size_t)bb*NH + h)*SEQ + n)*HD + d] = val; }
                else { int jv=jc-CC; int h=jv>>6, d=jv&63;
                    g_v[(((size_t)bb*NH + h)*SEQ + n)*HD + d] = val; }
            }
        }
    }
}

// ---------------------------------------------------------------------------
// Kernel 3: flash-style attention per (b,h). Block = 64-query tile, loops over
// 16 key tiles of 64. Q/K stored d-major (transposed) in smem for conflict-free
// LDS.128; online softmax; output scattered to g_ao [b][n][c].
// Grid: (16 qtiles, 96 bh). 256 threads, 4x4 micro-tiles. ~69.6KB dyn smem.
// ---------------------------------------------------------------------------
__global__ __launch_bounds__(256, 2)
void attn_kernel() {
    extern __shared__ float sm[];
    float* Qt = sm;                 // [64 d][AP]  Qt[d][q]
    float* Kt = sm + 64*AP;         // [64 d][AP]  Kt[d][k]
    float* Vs = sm + 2*64*AP;       // [64 k][AP]  Vs[k][d]
    float* Ps = sm + 3*64*AP;       // [64 q][AP]  Ps[q][k]

    int qt = blockIdx.x, bh = blockIdx.y;
    const float* qp = g_q + (size_t)bh*SEQ*HD;
    const float* kp = g_k + (size_t)bh*SEQ*HD;
    const float* vp = g_v + (size_t)bh*SEQ*HD;
    int t = threadIdx.x, tx = t & 15, ty = t >> 4;
    int r = t >> 2, c4 = t & 3;

    // Load Q tile transposed
#pragma unroll
    for (int i = 0; i < 4; i++) {
        int c = c4*16 + i*4;
        float4 qv = *(const float4*)(qp + (size_t)(qt*64 + r)*HD + c);
        Qt[(c+0)*AP+r]=qv.x; Qt[(c+1)*AP+r]=qv.y; Qt[(c+2)*AP+r]=qv.z; Qt[(c+3)*AP+r]=qv.w;
    }

    float O[4][4], mI[4], lI[4];
#pragma unroll
    for (int i = 0; i < 4; i++) {
        mI[i] = -1e30f; lI[i] = 0.f;
#pragma unroll
        for (int j = 0; j < 4; j++) O[i][j] = 0.f;
    }

    for (int kt = 0; kt < 16; kt++) {
#pragma unroll
        for (int i = 0; i < 4; i++) {
            int c = c4*16 + i*4;
            float4 kvv = *(const float4*)(kp + (size_t)(kt*64 + r)*HD + c);
            Kt[(c+0)*AP+r]=kvv.x; Kt[(c+1)*AP+r]=kvv.y; Kt[(c+2)*AP+r]=kvv.z; Kt[(c+3)*AP+r]=kvv.w;
            float4 vv = *(const float4*)(vp + (size_t)(kt*64 + r)*HD + c);
            *(float4*)&Vs[r*AP + c] = vv;
        }
        __syncthreads();

        float s[4][4];
#pragma unroll
        for (int i = 0; i < 4; i++)
#pragma unroll
            for (int j = 0; j < 4; j++) s[i][j] = 0.f;

#pragma unroll 8
        for (int dd = 0; dd < 64; dd++) {
            float4 q4 = *(const float4*)&Qt[dd*AP + ty*4];
            float4 k4 = *(const float4*)&Kt[dd*AP + tx*4];
            float qa[4] = {q4.x,q4.y,q4.z,q4.w};
            float ka[4] = {k4.x,k4.y,k4.z,k4.w};
#pragma unroll
            for (int i = 0; i < 4; i++)
#pragma unroll
                for (int j = 0; j < 4; j++) s[i][j] += qa[i]*ka[j];
        }

#pragma unroll
        for (int i = 0; i < 4; i++) {
            float s0 = s[i][0]*0.125f, s1 = s[i][1]*0.125f;
            float s2 = s[i][2]*0.125f, s3 = s[i][3]*0.125f;
            float rm = fmaxf(fmaxf(s0,s1), fmaxf(s2,s3));
#pragma unroll
            for (int o = 1; o < 16; o <<= 1)
                rm = fmaxf(rm, __shfl_xor_sync(0xffffffffu, rm, o));
            float mnew = fmaxf(mI[i], rm);
            float al = __expf(mI[i] - mnew);
            float p0 = __expf(s0 - mnew), p1 = __expf(s1 - mnew);
            float p2 = __expf(s2 - mnew), p3 = __expf(s3 - mnew);
            float rs = p0 + p1 + p2 + p3;
#pragma unroll
            for (int o = 1; o < 16; o <<= 1)
                rs += __shfl_xor_sync(0xffffffffu, rs, o);
            lI[i] = lI[i]*al + rs;
            mI[i] = mnew;
            O[i][0]*=al; O[i][1]*=al; O[i][2]*=al; O[i][3]*=al;
            *(float4*)&Ps[(ty*4+i)*AP + tx*4] = make_float4(p0,p1,p2,p3);
        }
        __syncthreads();

#pragma unroll 8
        for (int kk = 0; kk < 64; kk++) {
            float4 v4 = *(const float4*)&Vs[kk*AP + tx*4];
#pragma unroll
            for (int i = 0; i < 4; i++) {
                float p = Ps[(ty*4+i)*AP + kk];
                O[i][0] += p*v4.x; O[i][1] += p*v4.y;
                O[i][2] += p*v4.z; O[i][3] += p*v4.w;
            }
        }
        __syncthreads();
    }

    int bb = bh / NH, h = bh - bb*NH;
#pragma unroll
    for (int i = 0; i < 4; i++) {
        int n = qt*64 + ty*4 + i;
        float inv = 1.f / lI[i];
        *(float4*)(g_ao + ((size_t)bb*SEQ + n)*CC + h*HD + tx*4) =
            make_float4(O[i][0]*inv, O[i][1]*inv, O[i][2]*inv, O[i][3]*inv);
    }
}

// ---------------------------------------------------------------------------
// Kernel 4: projection GEMM  out = g_ao @ proj_w^T + proj_b
// Grid: (768/64, 8192/64) = (12, 128).
// ---------------------------------------------------------------------------
__global__ __launch_bounds__(256, 2)
void proj_kernel(const float* __restrict__ W, const float* __restrict__ bias,
                 float* __restrict__ out) {
    __shared__ float As[BK][TP], Ws2[BK][TP];
    int j0 = blockIdx.x * 64, m0 = blockIdx.y * 64;
    int t = threadIdx.x, tx = t & 15, ty = t >> 4;
    int lr = t >> 2, lc = (t & 3) * 4;
    const float* ag = g_ao + (size_t)(m0+lr)*CC + lc;
    const float* wg = W    + (size_t)(j0+lr)*CC + lc;
    float acc[4][4];
#pragma unroll
    for (int i = 0; i < 4; i++)
#pragma unroll
        for (int j = 0; j < 4; j++) acc[i][j] = 0.f;

    for (int k0 = 0; k0 < CC; k0 += BK) {
        float4 av = *(const float4*)(ag + k0);
        float4 wv = *(const float4*)(wg + k0);
        As [lc+0][lr]=av.x; As [lc+1][lr]=av.y; As [lc+2][lr]=av.z; As [lc+3][lr]=av.w;
        Ws2[lc+0][lr]=wv.x; Ws2[lc+1][lr]=wv.y; Ws2[lc+2][lr]=wv.z; Ws2[lc+3][lr]=wv.w;
        __syncthreads();
#pragma unroll
        for (int kk = 0; kk < BK; kk++) {
            float4 a4 = *(const float4*)&As[kk][ty*4];
            float4 w4 = *(const float4*)&Ws2[kk][tx*4];
            float aa[4] = {a4.x,a4.y,a4.z,a4.w};
            float wr[4] = {w4.x,w4.y,w4.z,w4.w};
#pragma unroll
            for (int i = 0; i < 4; i++)
#pragma unroll
                for (int j = 0; j < 4; j++) acc[i][j] += aa[i]*wr[j];
        }
        __syncthreads();
    }

#pragma unroll
    for (int i = 0; i < 4; i++) {
        int m = m0 + ty*4 + i;
        int cb = j0 + tx*4;
        float4 o4 = make_float4(acc[i][0] + bias[cb+0], acc[i][1] + bias[cb+1],
                                acc[i][2] + bias[cb+2], acc[i][3] + bias[cb+3]);
        *(float4*)(out + (size_t)m*CC + cb) = o4;
    }
}

// ---------------------------------------------------------------------------
extern "C" void kernel_launch(void* const* d_in, const int* in_sizes, int n_in,
                              void* d_out, int out_size) {
    const float* x      = (const float*)d_in[0];
    const float* y      = (const float*)d_in[1];
    const float* q_w    = (const float*)d_in[2];
    const float* q_b    = (const float*)d_in[3];
    const float* kv_w   = (const float*)d_in[4];
    const float* kv_b   = (const float*)d_in[5];
    const float* proj_w = (const float*)d_in[6];
    const float* proj_b = (const float*)d_in[7];
    const float* ln_g   = (const float*)d_in[8];
    const float* ln_b   = (const float*)d_in[9];
    float* out = (float*)d_out;

    ln_kernel<<<MM, 256>>>(y, ln_g, ln_b);

    dim3 gq(36, 128);
    qkv_kernel<<<gq, 256>>>(x, q_w, q_b, kv_w, kv_b);

    int smem = 4 * 64 * AP * (int)sizeof(float);   // 69632 B
    cudaFuncSetAttribute(attn_kernel, cudaFuncAttributeMaxDynamicSharedMemorySize, smem);
    dim3 ga(16, 96);
    attn_kernel<<<ga, 256, smem>>>();

    dim3 gp(12, 128);
    proj_kernel<<<gp, 256>>>(proj_w, proj_b, out);
}

// round 5
// speedup vs baseline: 1.5060x; 1.5060x over previous
#include <cuda_runtime.h>
#include <cuda_bf16.h>
#include <cstdint>

#define SEQ  1024
#define CC   768
#define NH   12
#define HD   64
#define MM   8192          // B*N rows
#define NQKV 2304

// ---------------- scratch (device globals) ----------------------------------
__device__ __nv_bfloat16 g_ah[2*MM*CC], g_al[2*MM*CC];     // rows 0..8191: x, 8192..: y2
__device__ __nv_bfloat16 g_wh[NQKV*CC], g_wl[NQKV*CC];     // concat(q_w, kv_w)
__device__ __nv_bfloat16 g_ph[CC*CC],  g_pl[CC*CC];        // proj_w
__device__ float g_c[2*MM*NQKV];                           // qkv GEMM output (fp32)
__device__ float g_q[MM*CC], g_k[MM*CC], g_v[MM*CC];
__device__ __nv_bfloat16 g_aoh[MM*CC], g_aol[MM*CC];       // attention out hi/lo

// ---------------- helpers ----------------------------------------------------
__device__ __forceinline__ uint32_t smem_u32(const void* p) {
    uint32_t a;
    asm("{ .reg .u64 t; cvta.to.shared.u64 t, %1; cvt.u32.u64 %0, t; }" : "=r"(a) : "l"(p));
    return a;
}
__device__ __forceinline__ void cpa16(uint32_t s, const void* g) {
    asm volatile("cp.async.cg.shared.global [%0], [%1], 16;" :: "r"(s), "l"(g));
}
__device__ __forceinline__ void cpa_commit() { asm volatile("cp.async.commit_group;"); }
template<int N> __device__ __forceinline__ void cpa_wait() {
    asm volatile("cp.async.wait_group %0;" :: "n"(N));
}
__device__ __forceinline__ void ldsm4(uint32_t& r0, uint32_t& r1, uint32_t& r2, uint32_t& r3,
                                      uint32_t addr) {
    asm volatile("ldmatrix.sync.aligned.m8n8.x4.shared.b16 {%0,%1,%2,%3}, [%4];"
                 : "=r"(r0), "=r"(r1), "=r"(r2), "=r"(r3) : "r"(addr));
}
__device__ __forceinline__ void mma16816(float* c, const uint32_t* a, const uint32_t* b) {
    asm volatile("mma.sync.aligned.m16n8k16.row.col.f32.bf16.bf16.f32 "
                 "{%0,%1,%2,%3}, {%4,%5,%6,%7}, {%8,%9}, {%0,%1,%2,%3};"
                 : "+f"(c[0]), "+f"(c[1]), "+f"(c[2]), "+f"(c[3])
                 : "r"(a[0]), "r"(a[1]), "r"(a[2]), "r"(a[3]), "r"(b[0]), "r"(b[1]));
}
__device__ __forceinline__ void bsplit(float f, __nv_bfloat16& h, __nv_bfloat16& l) {
    h = __float2bfloat16(f);
    l = __float2bfloat16(f - __bfloat162float(h));
}
__device__ __forceinline__ float sigmoidf_(float x) { return 1.f/(1.f+__expf(-x)); }

// ---------------------------------------------------------------------------
// prep: fp32 -> bf16 hi/lo splits
// ---------------------------------------------------------------------------
__global__ void prep_x(const float* __restrict__ x) {
    for (int i = blockIdx.x*blockDim.x + threadIdx.x; i < MM*CC; i += gridDim.x*blockDim.x)
        bsplit(x[i], g_ah[i], g_al[i]);
}
__global__ void prep_w(const float* __restrict__ qw, const float* __restrict__ kvw,
                       const float* __restrict__ pw) {
    const int QW = CC*CC, WCAT = NQKV*CC, TOT = WCAT + CC*CC;
    for (int i = blockIdx.x*blockDim.x + threadIdx.x; i < TOT; i += gridDim.x*blockDim.x) {
        if (i < QW)        bsplit(qw[i],     g_wh[i], g_wl[i]);
        else if (i < WCAT) bsplit(kvw[i-QW], g_wh[i], g_wl[i]);
        else { int j = i - WCAT; bsplit(pw[j], g_ph[j], g_pl[j]); }
    }
}

// ---------------------------------------------------------------------------
// LN: y [B,C,HW] -> transpose -> layernorm -> bf16 hi/lo into stacked rows
// ---------------------------------------------------------------------------
__global__ void ln_kernel(const float* __restrict__ y,
                          const float* __restrict__ gam, const float* __restrict__ bet) {
    int m = blockIdx.x, bb = m >> 10, n = m & 1023;
    const float* yp = y + (size_t)bb*CC*SEQ + n;
    float v[3]; float s = 0.f, s2 = 0.f;
#pragma unroll
    for (int i = 0; i < 3; i++) {
        int c = threadIdx.x + i*256;
        float t = yp[(size_t)c*SEQ];
        v[i] = t; s += t; s2 += t*t;
    }
#pragma unroll
    for (int o = 16; o > 0; o >>= 1) {
        s  += __shfl_xor_sync(0xffffffffu, s,  o);
        s2 += __shfl_xor_sync(0xffffffffu, s2, o);
    }
    __shared__ float rb[2][8];
    if ((threadIdx.x & 31) == 0) { rb[0][threadIdx.x>>5] = s; rb[1][threadIdx.x>>5] = s2; }
    __syncthreads();
    float ts = 0.f, ts2 = 0.f;
#pragma unroll
    for (int i = 0; i < 8; i++) { ts += rb[0][i]; ts2 += rb[1][i]; }
    float mean = ts*(1.f/CC), var = ts2*(1.f/CC) - mean*mean;
    float rstd = rsqrtf(var + 1e-5f);
    size_t base = (size_t)(MM + m)*CC;
#pragma unroll
    for (int i = 0; i < 3; i++) {
        int c = threadIdx.x + i*256;
        float o = (v[i]-mean)*rstd*gam[c] + bet[c];
        bsplit(o, g_ah[base + c], g_al[base + c]);
    }
}

// ---------------------------------------------------------------------------
// HMMA GEMM: C[M,N] = A[M,K] @ W[N,K]^T with bf16 hi/lo 3-pass split.
// Block tile 128x128, K staged 32, double-buffered cp.async.
// ---------------------------------------------------------------------------
#define PITCH 80            // bytes per 32-bf16 row (padded from 64)
#define BUFB  10240
#define STGB  40960

template<bool BIAS>
__global__ __launch_bounds__(256, 1)
void hgemm(const __nv_bfloat16* __restrict__ Ah, const __nv_bfloat16* __restrict__ Al,
           const __nv_bfloat16* __restrict__ Wh, const __nv_bfloat16* __restrict__ Wl,
           float* __restrict__ C, const float* __restrict__ bias, int ldc) {
    extern __shared__ __align__(16) char smraw[];
    uint32_t smb = smem_u32(smraw);
    int t = threadIdx.x, lane = t & 31, w = t >> 5;
    int wm = w >> 1, wn = w & 1;
    int am0 = blockIdx.y * 128, wn0 = blockIdx.x * 128;

    const __nv_bfloat16* srcs[4] = {
        Ah + (size_t)am0*CC, Al + (size_t)am0*CC,
        Wh + (size_t)wn0*CC, Wl + (size_t)wn0*CC };

    int r0 = t >> 2, c0 = t & 3;
    int r1 = (t + 256) >> 2, c1 = t & 3;

    auto load_stage = [&](int s, int k0) {
        uint32_t base = smb + (s & 1)*STGB;
#pragma unroll
        for (int b = 0; b < 4; b++) {
            cpa16(base + b*BUFB + r0*PITCH + c0*16, srcs[b] + (size_t)r0*CC + k0 + c0*8);
            cpa16(base + b*BUFB + r1*PITCH + c1*16, srcs[b] + (size_t)r1*CC + k0 + c1*8);
        }
        cpa_commit();
    };

    float acc[2][8][4];
#pragma unroll
    for (int mi = 0; mi < 2; mi++)
#pragma unroll
        for (int ni = 0; ni < 8; ni++)
#pragma unroll
            for (int e = 0; e < 4; e++) acc[mi][ni][e] = 0.f;

    load_stage(0, 0);

    const int NSTG = CC/32;   // 24
    int a_row  = wm*32 + (lane & 15);
    int a_coff = (lane >> 4) * 16;
    int b_row  = (lane & 7) + ((lane >> 1) & 8);
    int b_coff = (lane & 8) * 2;

#pragma unroll 1
    for (int s = 0; s < NSTG; s++) {
        if (s + 1 < NSTG) load_stage(s + 1, (s + 1)*32);
        if (s + 1 < NSTG) cpa_wait<1>(); else cpa_wait<0>();
        __syncthreads();
        uint32_t bAh = smb + (s & 1)*STGB;
        uint32_t bAl = bAh + BUFB, bWh = bAh + 2*BUFB, bWl = bAh + 3*BUFB;
#pragma unroll
        for (int ks = 0; ks < 2; ks++) {
            int kb = ks*32;
            uint32_t ah[2][4], al[2][4], bh[8][2], bl[8][2];
            ldsm4(ah[0][0], ah[0][1], ah[0][2], ah[0][3], bAh + (a_row)*PITCH     + kb + a_coff);
            ldsm4(ah[1][0], ah[1][1], ah[1][2], ah[1][3], bAh + (a_row+16)*PITCH + kb + a_coff);
            ldsm4(al[0][0], al[0][1], al[0][2], al[0][3], bAl + (a_row)*PITCH     + kb + a_coff);
            ldsm4(al[1][0], al[1][1], al[1][2], al[1][3], bAl + (a_row+16)*PITCH + kb + a_coff);
#pragma unroll
            for (int p = 0; p < 4; p++) {
                int nr = wn*64 + p*16 + b_row;
                ldsm4(bh[2*p][0], bh[2*p][1], bh[2*p+1][0], bh[2*p+1][1],
                      bWh + nr*PITCH + kb + b_coff);
                ldsm4(bl[2*p][0], bl[2*p][1], bl[2*p+1][0], bl[2*p+1][1],
                      bWl + nr*PITCH + kb + b_coff);
            }
#pragma unroll
            for (int mi = 0; mi < 2; mi++)
#pragma unroll
                for (int ni = 0; ni < 8; ni++) {
                    mma16816(acc[mi][ni], ah[mi], bh[ni]);
                    mma16816(acc[mi][ni], ah[mi], bl[ni]);
                    mma16816(acc[mi][ni], al[mi], bh[ni]);
                }
        }
        __syncthreads();
    }

#pragma unroll
    for (int mi = 0; mi < 2; mi++) {
        int row = am0 + wm*32 + mi*16 + (lane >> 2);
#pragma unroll
        for (int ni = 0; ni < 8; ni++) {
            int col = wn0 + wn*64 + ni*8 + 2*(lane & 3);
            float b0 = 0.f, b1 = 0.f;
            if (BIAS) { b0 = bias[col]; b1 = bias[col+1]; }
            *(float2*)(C + (size_t)row*ldc + col)     = make_float2(acc[mi][ni][0]+b0, acc[mi][ni][1]+b1);
            *(float2*)(C + (size_t)(row+8)*ldc + col) = make_float2(acc[mi][ni][2]+b0, acc[mi][ni][3]+b1);
        }
    }
}

// ---------------------------------------------------------------------------
// gate: read Cx (rows 0..8191), Cy (rows 8192..), apply gating, scatter q/k/v
// ---------------------------------------------------------------------------
__global__ void gate_kernel(const float* __restrict__ qb, const float* __restrict__ kvb) {
    int i = blockIdx.x*blockDim.x + threadIdx.x;
    int m = i / 576, j = (i - m*576) * 4;
    float4 x4 = *(const float4*)(g_c + (size_t)m*NQKV + j);
    float4 y4 = *(const float4*)(g_c + (size_t)(m + MM)*NQKV + j);
    int bb = m >> 10, n = m & 1023;
    float o[4];
    float* dst; int h, d;
    if (j < CC) {
        float4 b4 = *(const float4*)(qb + j);
        float xx[4] = {x4.x+b4.x, x4.y+b4.y, x4.z+b4.z, x4.w+b4.w};
        float yy[4] = {y4.x+b4.x, y4.y+b4.y, y4.z+b4.z, y4.w+b4.w};
#pragma unroll
        for (int e = 0; e < 4; e++) o[e] = xx[e]*(1.f + sigmoidf_(yy[e]));
        dst = g_q; h = j >> 6; d = j & 63;
    } else {
        float4 b4 = *(const float4*)(kvb + j - CC);
        float xx[4] = {x4.x+b4.x, x4.y+b4.y, x4.z+b4.z, x4.w+b4.w};
        float yy[4] = {y4.x+b4.x, y4.y+b4.y, y4.z+b4.z, y4.w+b4.w};
#pragma unroll
        for (int e = 0; e < 4; e++) o[e] = sigmoidf_(yy[e])*(xx[e] + 1.f);
        if (j < 2*CC) { dst = g_k; h = (j - CC) >> 6; d = j & 63; }
        else          { dst = g_v; h = (j - 2*CC) >> 6; d = j & 63; }
    }
    *(float4*)(dst + (((size_t)bb*NH + h)*SEQ + n)*HD + d) = make_float4(o[0],o[1],o[2],o[3]);
}

// ---------------------------------------------------------------------------
// Attention (fp32 SIMT) -> writes bf16 hi/lo for proj.
// ---------------------------------------------------------------------------
#define AP 68
__global__ __launch_bounds__(256, 2)
void attn_kernel() {
    extern __shared__ float smf[];
    float* Qt = smf;
    float* Kt = smf + 64*AP;
    float* Vs = smf + 2*64*AP;
    float* Ps = smf + 3*64*AP;

    int qt = blockIdx.x, bh = blockIdx.y;
    const float* qp = g_q + (size_t)bh*SEQ*HD;
    const float* kp = g_k + (size_t)bh*SEQ*HD;
    const float* vp = g_v + (size_t)bh*SEQ*HD;
    int t = threadIdx.x, tx = t & 15, ty = t >> 4;
    int r = t >> 2, c4 = t & 3;

#pragma unroll
    for (int i = 0; i < 4; i++) {
        int c = c4*16 + i*4;
        float4 qv = *(const float4*)(qp + (size_t)(qt*64 + r)*HD + c);
        Qt[(c+0)*AP+r]=qv.x; Qt[(c+1)*AP+r]=qv.y; Qt[(c+2)*AP+r]=qv.z; Qt[(c+3)*AP+r]=qv.w;
    }
    float O[4][4], mI[4], lI[4];
#pragma unroll
    for (int i = 0; i < 4; i++) {
        mI[i] = -1e30f; lI[i] = 0.f;
#pragma unroll
        for (int j = 0; j < 4; j++) O[i][j] = 0.f;
    }
    for (int kt = 0; kt < 16; kt++) {
#pragma unroll
        for (int i = 0; i < 4; i++) {
            int c = c4*16 + i*4;
            float4 kvv = *(const float4*)(kp + (size_t)(kt*64 + r)*HD + c);
            Kt[(c+0)*AP+r]=kvv.x; Kt[(c+1)*AP+r]=kvv.y; Kt[(c+2)*AP+r]=kvv.z; Kt[(c+3)*AP+r]=kvv.w;
            float4 vv = *(const float4*)(vp + (size_t)(kt*64 + r)*HD + c);
            *(float4*)&Vs[r*AP + c] = vv;
        }
        __syncthreads();
        float s[4][4];
#pragma unroll
        for (int i = 0; i < 4; i++)
#pragma unroll
            for (int j = 0; j < 4; j++) s[i][j] = 0.f;
#pragma unroll 8
        for (int dd = 0; dd < 64; dd++) {
            float4 q4 = *(const float4*)&Qt[dd*AP + ty*4];
            float4 k4 = *(const float4*)&Kt[dd*AP + tx*4];
            float qa[4] = {q4.x,q4.y,q4.z,q4.w};
            float ka[4] = {k4.x,k4.y,k4.z,k4.w};
#pragma unroll
            for (int i = 0; i < 4; i++)
#pragma unroll
                for (int j = 0; j < 4; j++) s[i][j] += qa[i]*ka[j];
        }
#pragma unroll
        for (int i = 0; i < 4; i++) {
            float s0 = s[i][0]*0.125f, s1 = s[i][1]*0.125f;
            float s2 = s[i][2]*0.125f, s3 = s[i][3]*0.125f;
            float rm = fmaxf(fmaxf(s0,s1), fmaxf(s2,s3));
#pragma unroll
            for (int o = 1; o < 16; o <<= 1) rm = fmaxf(rm, __shfl_xor_sync(0xffffffffu, rm, o));
            float mnew = fmaxf(mI[i], rm);
            float al = __expf(mI[i] - mnew);
            float p0 = __expf(s0 - mnew), p1 = __expf(s1 - mnew);
            float p2 = __expf(s2 - mnew), p3 = __expf(s3 - mnew);
            float rs = p0 + p1 + p2 + p3;
#pragma unroll
            for (int o = 1; o < 16; o <<= 1) rs += __shfl_xor_sync(0xffffffffu, rs, o);
            lI[i] = lI[i]*al + rs;
            mI[i] = mnew;
            O[i][0]*=al; O[i][1]*=al; O[i][2]*=al; O[i][3]*=al;
            *(float4*)&Ps[(ty*4+i)*AP + tx*4] = make_float4(p0,p1,p2,p3);
        }
        __syncthreads();
#pragma unroll 8
        for (int kk = 0; kk < 64; kk++) {
            float4 v4 = *(const float4*)&Vs[kk*AP + tx*4];
#pragma unroll
            for (int i = 0; i < 4; i++) {
                float p = Ps[(ty*4+i)*AP + kk];
                O[i][0] += p*v4.x; O[i][1] += p*v4.y;
                O[i][2] += p*v4.z; O[i][3] += p*v4.w;
            }
        }
        __syncthreads();
    }
    int bb = bh / NH, h = bh - bb*NH;
#pragma unroll
    for (int i = 0; i < 4; i++) {
        int n = qt*64 + ty*4 + i;
        float inv = 1.f / lI[i];
        size_t off = ((size_t)bb*SEQ + n)*CC + h*HD + tx*4;
        __nv_bfloat16 hh[4], ll[4];
#pragma unroll
        for (int j = 0; j < 4; j++) bsplit(O[i][j]*inv, hh[j], ll[j]);
        *(__nv_bfloat162*)(g_aoh + off)     = __nv_bfloat162(hh[0], hh[1]);
        *(__nv_bfloat162*)(g_aoh + off + 2) = __nv_bfloat162(hh[2], hh[3]);
        *(__nv_bfloat162*)(g_aol + off)     = __nv_bfloat162(ll[0], ll[1]);
        *(__nv_bfloat162*)(g_aol + off + 2) = __nv_bfloat162(ll[2], ll[3]);
    }
}

// ---------------------------------------------------------------------------
extern "C" void kernel_launch(void* const* d_in, const int* in_sizes, int n_in,
                              void* d_out, int out_size) {
    const float* x      = (const float*)d_in[0];
    const float* y      = (const float*)d_in[1];
    const float* q_w    = (const float*)d_in[2];
    const float* q_b    = (const float*)d_in[3];
    const float* kv_w   = (const float*)d_in[4];
    const float* kv_b   = (const float*)d_in[5];
    const float* proj_w = (const float*)d_in[6];
    const float* proj_b = (const float*)d_in[7];
    const float* ln_g   = (const float*)d_in[8];
    const float* ln_b   = (const float*)d_in[9];
    float* out = (float*)d_out;

    // Resolve REAL device addresses of __device__ globals (host shadows are invalid
    // as kernel args). Pure query API: no allocation, graph-capture-safe.
    void *pah, *pal, *pwh, *pwl, *pph, *ppl, *pc, *paoh, *paol;
    cudaGetSymbolAddress(&pah,  g_ah);
    cudaGetSymbolAddress(&pal,  g_al);
    cudaGetSymbolAddress(&pwh,  g_wh);
    cudaGetSymbolAddress(&pwl,  g_wl);
    cudaGetSymbolAddress(&pph,  g_ph);
    cudaGetSymbolAddress(&ppl,  g_pl);
    cudaGetSymbolAddress(&pc,   g_c);
    cudaGetSymbolAddress(&paoh, g_aoh);
    cudaGetSymbolAddress(&paol, g_aol);

    prep_x<<<1184, 256>>>(x);
    prep_w<<<1184, 256>>>(q_w, kv_w, proj_w);
    ln_kernel<<<MM, 256>>>(y, ln_g, ln_b);

    int smg = 2*STGB;   // 81920
    cudaFuncSetAttribute(hgemm<false>, cudaFuncAttributeMaxDynamicSharedMemorySize, smg);
    cudaFuncSetAttribute(hgemm<true>,  cudaFuncAttributeMaxDynamicSharedMemorySize, smg);

    // qkv: A = [x; y2] (16384 x 768), W = concat (2304 x 768) -> g_c
    hgemm<false><<<dim3(18, 128), 256, smg>>>(
        (const __nv_bfloat16*)pah, (const __nv_bfloat16*)pal,
        (const __nv_bfloat16*)pwh, (const __nv_bfloat16*)pwl,
        (float*)pc, nullptr, NQKV);

    gate_kernel<<<18432, 256>>>(q_b, kv_b);

    int sma = 4 * 64 * AP * (int)sizeof(float);
    cudaFuncSetAttribute(attn_kernel, cudaFuncAttributeMaxDynamicSharedMemorySize, sma);
    attn_kernel<<<dim3(16, 96), 256, sma>>>();

    // proj: A = ao (8192 x 768), W = proj_w (768 x 768) -> out (+bias)
    hgemm<true><<<dim3(6, 64), 256, smg>>>(
        (const __nv_bfloat16*)paoh, (const __nv_bfloat16*)paol,
        (const __nv_bfloat16*)pph, (const __nv_bfloat16*)ppl,
        out, proj_b, CC);
}

// round 6
// speedup vs baseline: 2.7404x; 1.8197x over previous
#include <cuda_runtime.h>
#include <cuda_bf16.h>
#include <cuda_fp16.h>
#include <cstdint>

#define SEQ  1024
#define CC   768
#define NH   12
#define HD   64
#define MM   8192
#define NQKV 2304

// ---------------- scratch (device globals) ----------------------------------
__device__ __nv_bfloat16 g_ah[2*MM*CC], g_al[2*MM*CC];
__device__ __nv_bfloat16 g_wh[NQKV*CC], g_wl[NQKV*CC];
__device__ __nv_bfloat16 g_ph[CC*CC],  g_pl[CC*CC];
__device__ float g_c[2*MM*NQKV];
__device__ __nv_bfloat16 g_qh[MM*CC], g_ql[MM*CC];   // q (pre-scaled by 0.125) hi/lo
__device__ __nv_bfloat16 g_kh[MM*CC], g_kl[MM*CC];
__device__ __half        g_vh[MM*CC], g_vl[MM*CC];   // v in f16 hi/lo
__device__ __nv_bfloat16 g_aoh[MM*CC], g_aol[MM*CC];

// ---------------- helpers ----------------------------------------------------
__device__ __forceinline__ uint32_t smem_u32(const void* p) {
    uint32_t a;
    asm("{ .reg .u64 t; cvta.to.shared.u64 t, %1; cvt.u32.u64 %0, t; }" : "=r"(a) : "l"(p));
    return a;
}
__device__ __forceinline__ void cpa16(uint32_t s, const void* g) {
    asm volatile("cp.async.cg.shared.global [%0], [%1], 16;" :: "r"(s), "l"(g));
}
__device__ __forceinline__ void cpa_commit() { asm volatile("cp.async.commit_group;"); }
template<int N> __device__ __forceinline__ void cpa_wait() {
    asm volatile("cp.async.wait_group %0;" :: "n"(N));
}
__device__ __forceinline__ void ldsm4(uint32_t& r0, uint32_t& r1, uint32_t& r2, uint32_t& r3,
                                      uint32_t addr) {
    asm volatile("ldmatrix.sync.aligned.m8n8.x4.shared.b16 {%0,%1,%2,%3}, [%4];"
                 : "=r"(r0), "=r"(r1), "=r"(r2), "=r"(r3) : "r"(addr));
}
__device__ __forceinline__ void ldsm4t(uint32_t& r0, uint32_t& r1, uint32_t& r2, uint32_t& r3,
                                       uint32_t addr) {
    asm volatile("ldmatrix.sync.aligned.m8n8.x4.trans.shared.b16 {%0,%1,%2,%3}, [%4];"
                 : "=r"(r0), "=r"(r1), "=r"(r2), "=r"(r3) : "r"(addr));
}
__device__ __forceinline__ void mma16816(float* c, const uint32_t* a, const uint32_t* b) {
    asm volatile("mma.sync.aligned.m16n8k16.row.col.f32.bf16.bf16.f32 "
                 "{%0,%1,%2,%3}, {%4,%5,%6,%7}, {%8,%9}, {%0,%1,%2,%3};"
                 : "+f"(c[0]), "+f"(c[1]), "+f"(c[2]), "+f"(c[3])
                 : "r"(a[0]), "r"(a[1]), "r"(a[2]), "r"(a[3]), "r"(b[0]), "r"(b[1]));
}
__device__ __forceinline__ void mmaf16(float* c, const uint32_t* a, const uint32_t* b) {
    asm volatile("mma.sync.aligned.m16n8k16.row.col.f32.f16.f16.f32 "
                 "{%0,%1,%2,%3}, {%4,%5,%6,%7}, {%8,%9}, {%0,%1,%2,%3};"
                 : "+f"(c[0]), "+f"(c[1]), "+f"(c[2]), "+f"(c[3])
                 : "r"(a[0]), "r"(a[1]), "r"(a[2]), "r"(a[3]), "r"(b[0]), "r"(b[1]));
}
__device__ __forceinline__ void bsplit(float f, __nv_bfloat16& h, __nv_bfloat16& l) {
    h = __float2bfloat16(f);
    l = __float2bfloat16(f - __bfloat162float(h));
}
__device__ __forceinline__ void hsplit(float f, __half& h, __half& l) {
    h = __float2half_rn(f);
    l = __float2half_rn(f - __half2float(h));
}
__device__ __forceinline__ uint32_t h2pack(float a, float b) {
    __half2 h = __floats2half2_rn(a, b);
    return *(uint32_t*)&h;
}
__device__ __forceinline__ float sigmoidf_(float x) { return 1.f/(1.f+__expf(-x)); }
// XOR swizzle for 128B-pitch rows: 16B chunk index XOR (row&7)
__device__ __forceinline__ uint32_t swzb(int row, int cb) {
    return (uint32_t)(row*128 + ((((cb) >> 4) ^ (row & 7)) << 4));
}

// ---------------------------------------------------------------------------
__global__ void prep_x(const float* __restrict__ x) {
    for (int i = blockIdx.x*blockDim.x + threadIdx.x; i < MM*CC; i += gridDim.x*blockDim.x)
        bsplit(x[i], g_ah[i], g_al[i]);
}
__global__ void prep_w(const float* __restrict__ qw, const float* __restrict__ kvw,
                       const float* __restrict__ pw) {
    const int QW = CC*CC, WCAT = NQKV*CC, TOT = WCAT + CC*CC;
    for (int i = blockIdx.x*blockDim.x + threadIdx.x; i < TOT; i += gridDim.x*blockDim.x) {
        if (i < QW)        bsplit(qw[i],     g_wh[i], g_wl[i]);
        else if (i < WCAT) bsplit(kvw[i-QW], g_wh[i], g_wl[i]);
        else { int j = i - WCAT; bsplit(pw[j], g_ph[j], g_pl[j]); }
    }
}

__global__ void ln_kernel(const float* __restrict__ y,
                          const float* __restrict__ gam, const float* __restrict__ bet) {
    int m = blockIdx.x, bb = m >> 10, n = m & 1023;
    const float* yp = y + (size_t)bb*CC*SEQ + n;
    float v[3]; float s = 0.f, s2 = 0.f;
#pragma unroll
    for (int i = 0; i < 3; i++) {
        int c = threadIdx.x + i*256;
        float t = yp[(size_t)c*SEQ];
        v[i] = t; s += t; s2 += t*t;
    }
#pragma unroll
    for (int o = 16; o > 0; o >>= 1) {
        s  += __shfl_xor_sync(0xffffffffu, s,  o);
        s2 += __shfl_xor_sync(0xffffffffu, s2, o);
    }
    __shared__ float rb[2][8];
    if ((threadIdx.x & 31) == 0) { rb[0][threadIdx.x>>5] = s; rb[1][threadIdx.x>>5] = s2; }
    __syncthreads();
    float ts = 0.f, ts2 = 0.f;
#pragma unroll
    for (int i = 0; i < 8; i++) { ts += rb[0][i]; ts2 += rb[1][i]; }
    float mean = ts*(1.f/CC), var = ts2*(1.f/CC) - mean*mean;
    float rstd = rsqrtf(var + 1e-5f);
    size_t base = (size_t)(MM + m)*CC;
#pragma unroll
    for (int i = 0; i < 3; i++) {
        int c = threadIdx.x + i*256;
        float o = (v[i]-mean)*rstd*gam[c] + bet[c];
        bsplit(o, g_ah[base + c], g_al[base + c]);
    }
}

// ---------------------------------------------------------------------------
// HMMA GEMM (verified fragments). Now 2 CTAs/SM.
// ---------------------------------------------------------------------------
#define PITCH 80
#define BUFB  10240
#define STGB  40960

template<bool BIAS>
__global__ __launch_bounds__(256, 2)
void hgemm(const __nv_bfloat16* __restrict__ Ah, const __nv_bfloat16* __restrict__ Al,
           const __nv_bfloat16* __restrict__ Wh, const __nv_bfloat16* __restrict__ Wl,
           float* __restrict__ C, const float* __restrict__ bias, int ldc) {
    extern __shared__ __align__(16) char smraw[];
    uint32_t smb = smem_u32(smraw);
    int t = threadIdx.x, lane = t & 31, w = t >> 5;
    int wm = w >> 1, wn = w & 1;
    int am0 = blockIdx.y * 128, wn0 = blockIdx.x * 128;

    const __nv_bfloat16* srcs[4] = {
        Ah + (size_t)am0*CC, Al + (size_t)am0*CC,
        Wh + (size_t)wn0*CC, Wl + (size_t)wn0*CC };

    int r0 = t >> 2, c0 = t & 3;
    int r1 = (t + 256) >> 2, c1 = t & 3;

    auto load_stage = [&](int s, int k0) {
        uint32_t base = smb + (s & 1)*STGB;
#pragma unroll
        for (int b = 0; b < 4; b++) {
            cpa16(base + b*BUFB + r0*PITCH + c0*16, srcs[b] + (size_t)r0*CC + k0 + c0*8);
            cpa16(base + b*BUFB + r1*PITCH + c1*16, srcs[b] + (size_t)r1*CC + k0 + c1*8);
        }
        cpa_commit();
    };

    float acc[2][8][4];
#pragma unroll
    for (int mi = 0; mi < 2; mi++)
#pragma unroll
        for (int ni = 0; ni < 8; ni++)
#pragma unroll
            for (int e = 0; e < 4; e++) acc[mi][ni][e] = 0.f;

    load_stage(0, 0);

    const int NSTG = CC/32;
    int a_row  = wm*32 + (lane & 15);
    int a_coff = (lane >> 4) * 16;
    int b_row  = (lane & 7) + ((lane >> 1) & 8);
    int b_coff = (lane & 8) * 2;

#pragma unroll 1
    for (int s = 0; s < NSTG; s++) {
        if (s + 1 < NSTG) load_stage(s + 1, (s + 1)*32);
        if (s + 1 < NSTG) cpa_wait<1>(); else cpa_wait<0>();
        __syncthreads();
        uint32_t bAh = smb + (s & 1)*STGB;
        uint32_t bAl = bAh + BUFB, bWh = bAh + 2*BUFB, bWl = bAh + 3*BUFB;
#pragma unroll
        for (int ks = 0; ks < 2; ks++) {
            int kb = ks*32;
            uint32_t ah[2][4], al[2][4], bh[8][2], bl[8][2];
            ldsm4(ah[0][0], ah[0][1], ah[0][2], ah[0][3], bAh + (a_row)*PITCH     + kb + a_coff);
            ldsm4(ah[1][0], ah[1][1], ah[1][2], ah[1][3], bAh + (a_row+16)*PITCH + kb + a_coff);
            ldsm4(al[0][0], al[0][1], al[0][2], al[0][3], bAl + (a_row)*PITCH     + kb + a_coff);
            ldsm4(al[1][0], al[1][1], al[1][2], al[1][3], bAl + (a_row+16)*PITCH + kb + a_coff);
#pragma unroll
            for (int p = 0; p < 4; p++) {
                int nr = wn*64 + p*16 + b_row;
                ldsm4(bh[2*p][0], bh[2*p][1], bh[2*p+1][0], bh[2*p+1][1],
                      bWh + nr*PITCH + kb + b_coff);
                ldsm4(bl[2*p][0], bl[2*p][1], bl[2*p+1][0], bl[2*p+1][1],
                      bWl + nr*PITCH + kb + b_coff);
            }
#pragma unroll
            for (int mi = 0; mi < 2; mi++)
#pragma unroll
                for (int ni = 0; ni < 8; ni++) {
                    mma16816(acc[mi][ni], ah[mi], bh[ni]);
                    mma16816(acc[mi][ni], ah[mi], bl[ni]);
                    mma16816(acc[mi][ni], al[mi], bh[ni]);
                }
        }
        __syncthreads();
    }

#pragma unroll
    for (int mi = 0; mi < 2; mi++) {
        int row = am0 + wm*32 + mi*16 + (lane >> 2);
#pragma unroll
        for (int ni = 0; ni < 8; ni++) {
            int col = wn0 + wn*64 + ni*8 + 2*(lane & 3);
            float b0 = 0.f, b1 = 0.f;
            if (BIAS) { b0 = bias[col]; b1 = bias[col+1]; }
            *(float2*)(C + (size_t)row*ldc + col)     = make_float2(acc[mi][ni][0]+b0, acc[mi][ni][1]+b1);
            *(float2*)(C + (size_t)(row+8)*ldc + col) = make_float2(acc[mi][ni][2]+b0, acc[mi][ni][3]+b1);
        }
    }
}

// ---------------------------------------------------------------------------
// gate: apply gating, emit q(*0.125)/k bf16 hi/lo and v f16 hi/lo, [b,h,n,d]
// ---------------------------------------------------------------------------
__global__ void gate_kernel(const float* __restrict__ qb, const float* __restrict__ kvb) {
    int i = blockIdx.x*blockDim.x + threadIdx.x;
    int m = i / 576, j = (i - m*576) * 4;
    float4 x4 = *(const float4*)(g_c + (size_t)m*NQKV + j);
    float4 y4 = *(const float4*)(g_c + (size_t)(m + MM)*NQKV + j);
    int bb = m >> 10, n = m & 1023;
    float o[4];
    if (j < CC) {
        float4 b4 = *(const float4*)(qb + j);
        float xx[4] = {x4.x+b4.x, x4.y+b4.y, x4.z+b4.z, x4.w+b4.w};
        float yy[4] = {y4.x+b4.x, y4.y+b4.y, y4.z+b4.z, y4.w+b4.w};
#pragma unroll
        for (int e = 0; e < 4; e++) o[e] = 0.125f * xx[e]*(1.f + sigmoidf_(yy[e]));
        int h = j >> 6, d = j & 63;
        size_t off = (((size_t)bb*NH + h)*SEQ + n)*HD + d;
        __nv_bfloat16 hh[4], ll[4];
#pragma unroll
        for (int e = 0; e < 4; e++) bsplit(o[e], hh[e], ll[e]);
        *(__nv_bfloat162*)(g_qh+off)   = __nv_bfloat162(hh[0],hh[1]);
        *(__nv_bfloat162*)(g_qh+off+2) = __nv_bfloat162(hh[2],hh[3]);
        *(__nv_bfloat162*)(g_ql+off)   = __nv_bfloat162(ll[0],ll[1]);
        *(__nv_bfloat162*)(g_ql+off+2) = __nv_bfloat162(ll[2],ll[3]);
    } else {
        float4 b4 = *(const float4*)(kvb + j - CC);
        float xx[4] = {x4.x+b4.x, x4.y+b4.y, x4.z+b4.z, x4.w+b4.w};
        float yy[4] = {y4.x+b4.x, y4.y+b4.y, y4.z+b4.z, y4.w+b4.w};
#pragma unroll
        for (int e = 0; e < 4; e++) o[e] = sigmoidf_(yy[e])*(xx[e] + 1.f);
        if (j < 2*CC) {
            int h = (j - CC) >> 6, d = j & 63;
            size_t off = (((size_t)bb*NH + h)*SEQ + n)*HD + d;
            __nv_bfloat16 hh[4], ll[4];
#pragma unroll
            for (int e = 0; e < 4; e++) bsplit(o[e], hh[e], ll[e]);
            *(__nv_bfloat162*)(g_kh+off)   = __nv_bfloat162(hh[0],hh[1]);
            *(__nv_bfloat162*)(g_kh+off+2) = __nv_bfloat162(hh[2],hh[3]);
            *(__nv_bfloat162*)(g_kl+off)   = __nv_bfloat162(ll[0],ll[1]);
            *(__nv_bfloat162*)(g_kl+off+2) = __nv_bfloat162(ll[2],ll[3]);
        } else {
            int h = (j - 2*CC) >> 6, d = j & 63;
            size_t off = (((size_t)bb*NH + h)*SEQ + n)*HD + d;
            __half hh[4], ll[4];
#pragma unroll
            for (int e = 0; e < 4; e++) hsplit(o[e], hh[e], ll[e]);
            *(__half2*)(g_vh+off)   = __half2(hh[0],hh[1]);
            *(__half2*)(g_vh+off+2) = __half2(hh[2],hh[3]);
            *(__half2*)(g_vl+off)   = __half2(ll[0],ll[1]);
            *(__half2*)(g_vl+off+2) = __half2(ll[2],ll[3]);
        }
    }
}

// ---------------------------------------------------------------------------
// Tensor-core flash attention. Block = 128 q rows, loop 8 key tiles of 128.
// Warp w owns q rows [w*16, w*16+16). Q frags in registers (bf16 hi/lo).
// S = QK^T via bf16 3-pass; P f16 single; O += P·V via f16 2-pass (V hi/lo).
// smem: 2 stages x 64KB (Kh,Kl,Vh,Vl each 128x128B swizzled). Q staged in stage0.
// ---------------------------------------------------------------------------
__global__ __launch_bounds__(256, 1)
void attn_mma() {
    extern __shared__ __align__(16) char smraw[];
    uint32_t smb = smem_u32(smraw);
    int qt = blockIdx.x, bh = blockIdx.y;
    int t = threadIdx.x, lane = t & 31, w = t >> 5;
    const __nv_bfloat16* qhp = g_qh + (size_t)bh*SEQ*HD + (size_t)qt*128*HD;
    const __nv_bfloat16* qlp = g_ql + (size_t)bh*SEQ*HD + (size_t)qt*128*HD;
    const __nv_bfloat16* khp = g_kh + (size_t)bh*SEQ*HD;
    const __nv_bfloat16* klp = g_kl + (size_t)bh*SEQ*HD;
    const __half*        vhp = g_vh + (size_t)bh*SEQ*HD;
    const __half*        vlp = g_vl + (size_t)bh*SEQ*HD;

    // ---- stage Q into stage0 (Qh at 0, Ql at 16KB), swizzled 128B rows ----
#pragma unroll
    for (int i = 0; i < 4; i++) {
        int c = t + i*256;           // 1024 chunks
        int row = c >> 3, ch = c & 7;
        cpa16(smb + swzb(row, ch*16),           qhp + (size_t)row*HD + ch*8);
        cpa16(smb + 0x4000 + swzb(row, ch*16),  qlp + (size_t)row*HD + ch*8);
    }
    cpa_commit();

    auto load_kv = [&](int kt, int stage) {
        uint32_t base = smb + stage*0x10000;
#pragma unroll
        for (int i = 0; i < 4; i++) {
            int c = t + i*256;
            int row = c >> 3, ch = c & 7;
            uint32_t off = swzb(row, ch*16);
            const size_t go = (size_t)(kt*128 + row)*HD + ch*8;
            cpa16(base + 0x0000 + off, khp + go);
            cpa16(base + 0x4000 + off, klp + go);
            cpa16(base + 0x8000 + off, vhp + go);
            cpa16(base + 0xC000 + off, vlp + go);
        }
        cpa_commit();
    };

    load_kv(0, 1);          // kt0 -> stage1
    cpa_wait<1>();          // Q done
    __syncthreads();

    // ---- Q fragments to registers ----
    uint32_t qfh[4][4], qfl[4][4];
    int arow = w*16 + (lane & 15);
    int acb0 = (lane >> 4) << 4;
#pragma unroll
    for (int ks = 0; ks < 4; ks++) {
        uint32_t off = swzb(arow, ks*32 + acb0);
        ldsm4(qfh[ks][0], qfh[ks][1], qfh[ks][2], qfh[ks][3], smb + off);
        ldsm4(qfl[ks][0], qfl[ks][1], qfl[ks][2], qfl[ks][3], smb + 0x4000 + off);
    }
    __syncthreads();        // everyone done with Q smem
    load_kv(1, 0);          // kt1 -> stage0 (overwrites Q region)

    float O[8][4];
#pragma unroll
    for (int nd = 0; nd < 8; nd++)
#pragma unroll
        for (int e = 0; e < 4; e++) O[nd][e] = 0.f;
    float m0 = -1e30f, m1 = -1e30f, l0 = 0.f, l1 = 0.f;

    int krow_b = (lane & 7) + ((lane >> 1) & 8);
    int kcb_b  = (lane & 8) << 1;
    int vrow_b = lane & 15;
    int vcb_b  = (lane >> 4) << 4;

#pragma unroll 1
    for (int kt = 0; kt < 8; kt++) {
        if (kt == 7) cpa_wait<0>(); else cpa_wait<1>();
        __syncthreads();
        uint32_t base = smb + ((kt + 1) & 1)*0x10000;
        uint32_t bKh = base, bKl = base + 0x4000, bVh = base + 0x8000, bVl = base + 0xC000;

        // ---- S = Q K^T  (16 n-chunks of 8 keys) ----
        float sc[16][4];
#pragma unroll
        for (int jj = 0; jj < 16; jj++)
#pragma unroll
            for (int e = 0; e < 4; e++) sc[jj][e] = 0.f;
#pragma unroll
        for (int ks = 0; ks < 4; ks++) {
#pragma unroll
            for (int p = 0; p < 8; p++) {
                uint32_t kh4[4], kl4[4];
                int krow = 16*p + krow_b;
                uint32_t off = swzb(krow, ks*32 + kcb_b);
                ldsm4(kh4[0], kh4[1], kh4[2], kh4[3], bKh + off);
                ldsm4(kl4[0], kl4[1], kl4[2], kl4[3], bKl + off);
                mma16816(sc[2*p],   qfh[ks], kh4+0);
                mma16816(sc[2*p],   qfh[ks], kl4+0);
                mma16816(sc[2*p],   qfl[ks], kh4+0);
                mma16816(sc[2*p+1], qfh[ks], kh4+2);
                mma16816(sc[2*p+1], qfh[ks], kl4+2);
                mma16816(sc[2*p+1], qfl[ks], kh4+2);
            }
        }

        // ---- online softmax (rows g=lane>>2 and g+8) ----
        float rm0 = -1e30f, rm1 = -1e30f;
#pragma unroll
        for (int jj = 0; jj < 16; jj++) {
            rm0 = fmaxf(rm0, fmaxf(sc[jj][0], sc[jj][1]));
            rm1 = fmaxf(rm1, fmaxf(sc[jj][2], sc[jj][3]));
        }
        rm0 = fmaxf(rm0, __shfl_xor_sync(0xffffffffu, rm0, 1));
        rm0 = fmaxf(rm0, __shfl_xor_sync(0xffffffffu, rm0, 2));
        rm1 = fmaxf(rm1, __shfl_xor_sync(0xffffffffu, rm1, 1));
        rm1 = fmaxf(rm1, __shfl_xor_sync(0xffffffffu, rm1, 2));
        float mn0 = fmaxf(m0, rm0), mn1 = fmaxf(m1, rm1);
        float a0 = __expf(m0 - mn0), a1 = __expf(m1 - mn1);
        float rs0 = 0.f, rs1 = 0.f;
#pragma unroll
        for (int jj = 0; jj < 16; jj++) {
            sc[jj][0] = __expf(sc[jj][0] - mn0);
            sc[jj][1] = __expf(sc[jj][1] - mn0);
            sc[jj][2] = __expf(sc[jj][2] - mn1);
            sc[jj][3] = __expf(sc[jj][3] - mn1);
            rs0 += sc[jj][0] + sc[jj][1];
            rs1 += sc[jj][2] + sc[jj][3];
        }
        rs0 += __shfl_xor_sync(0xffffffffu, rs0, 1);
        rs0 += __shfl_xor_sync(0xffffffffu, rs0, 2);
        rs1 += __shfl_xor_sync(0xffffffffu, rs1, 1);
        rs1 += __shfl_xor_sync(0xffffffffu, rs1, 2);
        l0 = l0*a0 + rs0; l1 = l1*a1 + rs1;
        m0 = mn0; m1 = mn1;
#pragma unroll
        for (int nd = 0; nd < 8; nd++) {
            O[nd][0] *= a0; O[nd][1] *= a0;
            O[nd][2] *= a1; O[nd][3] *= a1;
        }

        // ---- P (f16) fragments ----
        uint32_t pf[8][4];
#pragma unroll
        for (int jj = 0; jj < 8; jj++) {
            pf[jj][0] = h2pack(sc[2*jj][0],   sc[2*jj][1]);
            pf[jj][1] = h2pack(sc[2*jj][2],   sc[2*jj][3]);
            pf[jj][2] = h2pack(sc[2*jj+1][0], sc[2*jj+1][1]);
            pf[jj][3] = h2pack(sc[2*jj+1][2], sc[2*jj+1][3]);
        }

        // ---- O += P V  (V via ldmatrix.trans; hi/lo 2-pass) ----
#pragma unroll
        for (int ks2 = 0; ks2 < 8; ks2++) {
#pragma unroll
            for (int pp = 0; pp < 4; pp++) {
                uint32_t vh4[4], vl4[4];
                int vrow = ks2*16 + vrow_b;
                uint32_t off = swzb(vrow, pp*32 + vcb_b);
                ldsm4t(vh4[0], vh4[1], vh4[2], vh4[3], bVh + off);
                ldsm4t(vl4[0], vl4[1], vl4[2], vl4[3], bVl + off);
                mmaf16(O[2*pp],   pf[ks2], vh4+0);
                mmaf16(O[2*pp],   pf[ks2], vl4+0);
                mmaf16(O[2*pp+1], pf[ks2], vh4+2);
                mmaf16(O[2*pp+1], pf[ks2], vl4+2);
            }
        }
        __syncthreads();
        if (kt + 2 < 8) load_kv(kt + 2, (kt + 1) & 1);
    }

    // ---- epilogue: normalize, bf16 hi/lo to g_ao ----
    float inv0 = 1.f / l0, inv1 = 1.f / l1;
    int g = lane >> 2, t2 = (lane & 3)*2;
    int bb = bh / NH, h = bh - bb*NH;
    int n0 = qt*128 + w*16 + g;
#pragma unroll
    for (int nd = 0; nd < 8; nd++) {
        int col = h*64 + nd*8 + t2;
        __nv_bfloat16 hh, ll;
        size_t o0 = ((size_t)bb*SEQ + n0)*CC + col;
        size_t o1 = ((size_t)bb*SEQ + n0 + 8)*CC + col;
        float f0 = O[nd][0]*inv0, f1 = O[nd][1]*inv0;
        float f2 = O[nd][2]*inv1, f3 = O[nd][3]*inv1;
        __nv_bfloat16 h0,l0b,h1,l1b,h2v,l2,h3,l3;
        bsplit(f0,h0,l0b); bsplit(f1,h1,l1b); bsplit(f2,h2v,l2); bsplit(f3,h3,l3);
        *(__nv_bfloat162*)(g_aoh + o0) = __nv_bfloat162(h0,h1);
        *(__nv_bfloat162*)(g_aol + o0) = __nv_bfloat162(l0b,l1b);
        *(__nv_bfloat162*)(g_aoh + o1) = __nv_bfloat162(h2v,h3);
        *(__nv_bfloat162*)(g_aol + o1) = __nv_bfloat162(l2,l3);
        (void)hh; (void)ll;
    }
}

// ---------------------------------------------------------------------------
extern "C" void kernel_launch(void* const* d_in, const int* in_sizes, int n_in,
                              void* d_out, int out_size) {
    const float* x      = (const float*)d_in[0];
    const float* y      = (const float*)d_in[1];
    const float* q_w    = (const float*)d_in[2];
    const float* q_b    = (const float*)d_in[3];
    const float* kv_w   = (const float*)d_in[4];
    const float* kv_b   = (const float*)d_in[5];
    const float* proj_w = (const float*)d_in[6];
    const float* proj_b = (const float*)d_in[7];
    const float* ln_g   = (const float*)d_in[8];
    const float* ln_b   = (const float*)d_in[9];
    float* out = (float*)d_out;

    void *pah, *pal, *pwh, *pwl, *pph, *ppl, *pc, *paoh, *paol;
    cudaGetSymbolAddress(&pah,  g_ah);
    cudaGetSymbolAddress(&pal,  g_al);
    cudaGetSymbolAddress(&pwh,  g_wh);
    cudaGetSymbolAddress(&pwl,  g_wl);
    cudaGetSymbolAddress(&pph,  g_ph);
    cudaGetSymbolAddress(&ppl,  g_pl);
    cudaGetSymbolAddress(&pc,   g_c);
    cudaGetSymbolAddress(&paoh, g_aoh);
    cudaGetSymbolAddress(&paol, g_aol);

    prep_x<<<1184, 256>>>(x);
    prep_w<<<1184, 256>>>(q_w, kv_w, proj_w);
    ln_kernel<<<MM, 256>>>(y, ln_g, ln_b);

    int smg = 2*STGB;
    cudaFuncSetAttribute(hgemm<false>, cudaFuncAttributeMaxDynamicSharedMemorySize, smg);
    cudaFuncSetAttribute(hgemm<true>,  cudaFuncAttributeMaxDynamicSharedMemorySize, smg);

    hgemm<false><<<dim3(18, 128), 256, smg>>>(
        (const __nv_bfloat16*)pah, (const __nv_bfloat16*)pal,
        (const __nv_bfloat16*)pwh, (const __nv_bfloat16*)pwl,
        (float*)pc, nullptr, NQKV);

    gate_kernel<<<18432, 256>>>(q_b, kv_b);

    int sma = 2*0x10000;   // 131072
    cudaFuncSetAttribute(attn_mma, cudaFuncAttributeMaxDynamicSharedMemorySize, sma);
    attn_mma<<<dim3(8, 96), 256, sma>>>();

    hgemm<true><<<dim3(6, 64), 256, smg>>>(
        (const __nv_bfloat16*)paoh, (const __nv_bfloat16*)paol,
        (const __nv_bfloat16*)pph, (const __nv_bfloat16*)ppl,
        out, proj_b, CC);
}

// round 7
// speedup vs baseline: 3.8016x; 1.3873x over previous
#include <cuda_runtime.h>
#include <cuda_bf16.h>
#include <cuda_fp16.h>
#include <cstdint>

#define SEQ  1024
#define CC   768
#define NH   12
#define HD   64
#define MM   8192
#define NQKV 2304

// ---------------- scratch (device globals) ----------------------------------
__device__ __half g_ah[2*MM*CC], g_al[2*MM*CC];   // [x; y2] f16 hi/lo
__device__ __half g_w[NQKV*CC];                   // concat(q_w, kv_w) f16
__device__ __half g_p[CC*CC];                     // proj_w f16
__device__ float  g_c[2*MM*NQKV];                 // qkv GEMM out (fp32)
__device__ __half g_qh[MM*CC], g_ql[MM*CC];       // q (x0.125) f16 hi/lo
__device__ __half g_k[MM*CC];                     // k f16
__device__ __half g_v[MM*CC];                     // v f16
__device__ __half g_aoh[MM*CC], g_aol[MM*CC];     // attn out f16 hi/lo

// ---------------- helpers ----------------------------------------------------
__device__ __forceinline__ uint32_t smem_u32(const void* p) {
    uint32_t a;
    asm("{ .reg .u64 t; cvta.to.shared.u64 t, %1; cvt.u32.u64 %0, t; }" : "=r"(a) : "l"(p));
    return a;
}
__device__ __forceinline__ void cpa16(uint32_t s, const void* g) {
    asm volatile("cp.async.cg.shared.global [%0], [%1], 16;" :: "r"(s), "l"(g));
}
__device__ __forceinline__ void cpa_commit() { asm volatile("cp.async.commit_group;"); }
template<int N> __device__ __forceinline__ void cpa_wait() {
    asm volatile("cp.async.wait_group %0;" :: "n"(N));
}
__device__ __forceinline__ void ldsm4(uint32_t& r0, uint32_t& r1, uint32_t& r2, uint32_t& r3,
                                      uint32_t addr) {
    asm volatile("ldmatrix.sync.aligned.m8n8.x4.shared.b16 {%0,%1,%2,%3}, [%4];"
                 : "=r"(r0), "=r"(r1), "=r"(r2), "=r"(r3) : "r"(addr));
}
__device__ __forceinline__ void ldsm4t(uint32_t& r0, uint32_t& r1, uint32_t& r2, uint32_t& r3,
                                       uint32_t addr) {
    asm volatile("ldmatrix.sync.aligned.m8n8.x4.trans.shared.b16 {%0,%1,%2,%3}, [%4];"
                 : "=r"(r0), "=r"(r1), "=r"(r2), "=r"(r3) : "r"(addr));
}
__device__ __forceinline__ void mmaf16(float* c, const uint32_t* a, const uint32_t* b) {
    asm volatile("mma.sync.aligned.m16n8k16.row.col.f32.f16.f16.f32 "
                 "{%0,%1,%2,%3}, {%4,%5,%6,%7}, {%8,%9}, {%0,%1,%2,%3};"
                 : "+f"(c[0]), "+f"(c[1]), "+f"(c[2]), "+f"(c[3])
                 : "r"(a[0]), "r"(a[1]), "r"(a[2]), "r"(a[3]), "r"(b[0]), "r"(b[1]));
}
__device__ __forceinline__ void hsplit(float f, __half& h, __half& l) {
    h = __float2half_rn(f);
    l = __float2half_rn(f - __half2float(h));
}
__device__ __forceinline__ uint32_t h2pack(float a, float b) {
    __half2 h = __floats2half2_rn(a, b);
    return *(uint32_t*)&h;
}
__device__ __forceinline__ float sigmoidf_(float x) { return 1.f/(1.f+__expf(-x)); }
__device__ __forceinline__ uint32_t swzb(int row, int cb) {
    return (uint32_t)(row*128 + ((((cb) >> 4) ^ (row & 7)) << 4));
}

// ---------------------------------------------------------------------------
__global__ void prep_x(const float* __restrict__ x) {
    for (int i = blockIdx.x*blockDim.x + threadIdx.x; i < MM*CC; i += gridDim.x*blockDim.x)
        hsplit(x[i], g_ah[i], g_al[i]);
}
__global__ void prep_w(const float* __restrict__ qw, const float* __restrict__ kvw,
                       const float* __restrict__ pw) {
    const int QW = CC*CC, WCAT = NQKV*CC, TOT = WCAT + CC*CC;
    for (int i = blockIdx.x*blockDim.x + threadIdx.x; i < TOT; i += gridDim.x*blockDim.x) {
        if (i < QW)        g_w[i] = __float2half_rn(qw[i]);
        else if (i < WCAT) g_w[i] = __float2half_rn(kvw[i-QW]);
        else               g_p[i-WCAT] = __float2half_rn(pw[i-WCAT]);
    }
}

__global__ void ln_kernel(const float* __restrict__ y,
                          const float* __restrict__ gam, const float* __restrict__ bet) {
    int m = blockIdx.x, bb = m >> 10, n = m & 1023;
    const float* yp = y + (size_t)bb*CC*SEQ + n;
    float v[3]; float s = 0.f, s2 = 0.f;
#pragma unroll
    for (int i = 0; i < 3; i++) {
        int c = threadIdx.x + i*256;
        float t = yp[(size_t)c*SEQ];
        v[i] = t; s += t; s2 += t*t;
    }
#pragma unroll
    for (int o = 16; o > 0; o >>= 1) {
        s  += __shfl_xor_sync(0xffffffffu, s,  o);
        s2 += __shfl_xor_sync(0xffffffffu, s2, o);
    }
    __shared__ float rb[2][8];
    if ((threadIdx.x & 31) == 0) { rb[0][threadIdx.x>>5] = s; rb[1][threadIdx.x>>5] = s2; }
    __syncthreads();
    float ts = 0.f, ts2 = 0.f;
#pragma unroll
    for (int i = 0; i < 8; i++) { ts += rb[0][i]; ts2 += rb[1][i]; }
    float mean = ts*(1.f/CC), var = ts2*(1.f/CC) - mean*mean;
    float rstd = rsqrtf(var + 1e-5f);
    size_t base = (size_t)(MM + m)*CC;
#pragma unroll
    for (int i = 0; i < 3; i++) {
        int c = threadIdx.x + i*256;
        float o = (v[i]-mean)*rstd*gam[c] + bet[c];
        hsplit(o, g_ah[base + c], g_al[base + c]);
    }
}

// ---------------------------------------------------------------------------
// f16 GEMM: C = (Ah+Al)[M,K] @ W[N,K]^T, 2 MMAs per tile (A hi/lo, W single).
// Block 128x128, K staged 32, double-buffered. 3 sub-buffers/stage = 30KB.
// ---------------------------------------------------------------------------
#define PITCH 80
#define BUFB  10240
#define STGB  30720

template<bool BIAS>
__global__ __launch_bounds__(256, 2)
void hgemm(const __half* __restrict__ Ah, const __half* __restrict__ Al,
           const __half* __restrict__ W,
           float* __restrict__ C, const float* __restrict__ bias, int ldc) {
    extern __shared__ __align__(16) char smraw[];
    uint32_t smb = smem_u32(smraw);
    int t = threadIdx.x, lane = t & 31, w = t >> 5;
    int wm = w >> 1, wn = w & 1;
    int am0 = blockIdx.y * 128, wn0 = blockIdx.x * 128;

    const __half* srcs[3] = {
        Ah + (size_t)am0*CC, Al + (size_t)am0*CC, W + (size_t)wn0*CC };

    int r0 = t >> 2, c0 = t & 3;
    int r1 = (t + 256) >> 2, c1 = t & 3;

    auto load_stage = [&](int s, int k0) {
        uint32_t base = smb + (s & 1)*STGB;
#pragma unroll
        for (int b = 0; b < 3; b++) {
            cpa16(base + b*BUFB + r0*PITCH + c0*16, srcs[b] + (size_t)r0*CC + k0 + c0*8);
            cpa16(base + b*BUFB + r1*PITCH + c1*16, srcs[b] + (size_t)r1*CC + k0 + c1*8);
        }
        cpa_commit();
    };

    float acc[2][8][4];
#pragma unroll
    for (int mi = 0; mi < 2; mi++)
#pragma unroll
        for (int ni = 0; ni < 8; ni++)
#pragma unroll
            for (int e = 0; e < 4; e++) acc[mi][ni][e] = 0.f;

    load_stage(0, 0);

    const int NSTG = CC/32;
    int a_row  = wm*32 + (lane & 15);
    int a_coff = (lane >> 4) * 16;
    int b_row  = (lane & 7) + ((lane >> 1) & 8);
    int b_coff = (lane & 8) * 2;

#pragma unroll 1
    for (int s = 0; s < NSTG; s++) {
        if (s + 1 < NSTG) load_stage(s + 1, (s + 1)*32);
        if (s + 1 < NSTG) cpa_wait<1>(); else cpa_wait<0>();
        __syncthreads();
        uint32_t bAh = smb + (s & 1)*STGB;
        uint32_t bAl = bAh + BUFB, bW = bAh + 2*BUFB;
#pragma unroll
        for (int ks = 0; ks < 2; ks++) {
            int kb = ks*32;
            uint32_t ah[2][4], al[2][4], bw[8][2];
            ldsm4(ah[0][0], ah[0][1], ah[0][2], ah[0][3], bAh + (a_row)*PITCH     + kb + a_coff);
            ldsm4(ah[1][0], ah[1][1], ah[1][2], ah[1][3], bAh + (a_row+16)*PITCH + kb + a_coff);
            ldsm4(al[0][0], al[0][1], al[0][2], al[0][3], bAl + (a_row)*PITCH     + kb + a_coff);
            ldsm4(al[1][0], al[1][1], al[1][2], al[1][3], bAl + (a_row+16)*PITCH + kb + a_coff);
#pragma unroll
            for (int p = 0; p < 4; p++) {
                int nr = wn*64 + p*16 + b_row;
                ldsm4(bw[2*p][0], bw[2*p][1], bw[2*p+1][0], bw[2*p+1][1],
                      bW + nr*PITCH + kb + b_coff);
            }
#pragma unroll
            for (int mi = 0; mi < 2; mi++)
#pragma unroll
                for (int ni = 0; ni < 8; ni++) {
                    mmaf16(acc[mi][ni], ah[mi], bw[ni]);
                    mmaf16(acc[mi][ni], al[mi], bw[ni]);
                }
        }
        __syncthreads();
    }

#pragma unroll
    for (int mi = 0; mi < 2; mi++) {
        int row = am0 + wm*32 + mi*16 + (lane >> 2);
#pragma unroll
        for (int ni = 0; ni < 8; ni++) {
            int col = wn0 + wn*64 + ni*8 + 2*(lane & 3);
            float b0 = 0.f, b1 = 0.f;
            if (BIAS) { b0 = bias[col]; b1 = bias[col+1]; }
            *(float2*)(C + (size_t)row*ldc + col)     = make_float2(acc[mi][ni][0]+b0, acc[mi][ni][1]+b1);
            *(float2*)(C + (size_t)(row+8)*ldc + col) = make_float2(acc[mi][ni][2]+b0, acc[mi][ni][3]+b1);
        }
    }
}

// ---------------------------------------------------------------------------
// gate: gating epilogue -> q f16 hi/lo (x0.125), k f16, v f16, [b,h,n,d]
// ---------------------------------------------------------------------------
__global__ void gate_kernel(const float* __restrict__ qb, const float* __restrict__ kvb) {
    int i = blockIdx.x*blockDim.x + threadIdx.x;
    int m = i / 576, j = (i - m*576) * 4;
    float4 x4 = *(const float4*)(g_c + (size_t)m*NQKV + j);
    float4 y4 = *(const float4*)(g_c + (size_t)(m + MM)*NQKV + j);
    int bb = m >> 10, n = m & 1023;
    float o[4];
    if (j < CC) {
        float4 b4 = *(const float4*)(qb + j);
        float xx[4] = {x4.x+b4.x, x4.y+b4.y, x4.z+b4.z, x4.w+b4.w};
        float yy[4] = {y4.x+b4.x, y4.y+b4.y, y4.z+b4.z, y4.w+b4.w};
#pragma unroll
        for (int e = 0; e < 4; e++) o[e] = 0.125f * xx[e]*(1.f + sigmoidf_(yy[e]));
        int h = j >> 6, d = j & 63;
        size_t off = (((size_t)bb*NH + h)*SEQ + n)*HD + d;
        __half hh[4], ll[4];
#pragma unroll
        for (int e = 0; e < 4; e++) hsplit(o[e], hh[e], ll[e]);
        *(__half2*)(g_qh+off)   = __half2(hh[0],hh[1]);
        *(__half2*)(g_qh+off+2) = __half2(hh[2],hh[3]);
        *(__half2*)(g_ql+off)   = __half2(ll[0],ll[1]);
        *(__half2*)(g_ql+off+2) = __half2(ll[2],ll[3]);
    } else {
        float4 b4 = *(const float4*)(kvb + j - CC);
        float xx[4] = {x4.x+b4.x, x4.y+b4.y, x4.z+b4.z, x4.w+b4.w};
        float yy[4] = {y4.x+b4.x, y4.y+b4.y, y4.z+b4.z, y4.w+b4.w};
#pragma unroll
        for (int e = 0; e < 4; e++) o[e] = sigmoidf_(yy[e])*(xx[e] + 1.f);
        __half* dst = (j < 2*CC) ? g_k : g_v;
        int h = ((j < 2*CC) ? (j - CC) : (j - 2*CC)) >> 6, d = j & 63;
        size_t off = (((size_t)bb*NH + h)*SEQ + n)*HD + d;
        *(__half2*)(dst+off)   = __floats2half2_rn(o[0], o[1]);
        *(__half2*)(dst+off+2) = __floats2half2_rn(o[2], o[3]);
    }
}

// ---------------------------------------------------------------------------
// TC flash attention: 128q x 128k tiles; Q f16 hi/lo in regs, K/V/P single f16.
// smem: 2 stages x 32KB (K 16KB + V 16KB); Q hi/lo staged in stage0 (32KB).
// ---------------------------------------------------------------------------
__global__ __launch_bounds__(256, 1)
void attn_mma() {
    extern __shared__ __align__(16) char smraw[];
    uint32_t smb = smem_u32(smraw);
    int qt = blockIdx.x, bh = blockIdx.y;
    int t = threadIdx.x, lane = t & 31, w = t >> 5;
    const __half* qhp = g_qh + (size_t)bh*SEQ*HD + (size_t)qt*128*HD;
    const __half* qlp = g_ql + (size_t)bh*SEQ*HD + (size_t)qt*128*HD;
    const __half* kp  = g_k  + (size_t)bh*SEQ*HD;
    const __half* vp  = g_v  + (size_t)bh*SEQ*HD;

    // stage Q (Qh at 0, Ql at 16KB)
#pragma unroll
    for (int i = 0; i < 4; i++) {
        int c = t + i*256;
        int row = c >> 3, ch = c & 7;
        cpa16(smb + swzb(row, ch*16),          qhp + (size_t)row*HD + ch*8);
        cpa16(smb + 0x4000 + swzb(row, ch*16), qlp + (size_t)row*HD + ch*8);
    }
    cpa_commit();

    auto load_kv = [&](int kt, int stage) {
        uint32_t base = smb + stage*0x8000;
#pragma unroll
        for (int i = 0; i < 4; i++) {
            int c = t + i*256;
            int row = c >> 3, ch = c & 7;
            uint32_t off = swzb(row, ch*16);
            const size_t go = (size_t)(kt*128 + row)*HD + ch*8;
            cpa16(base + 0x0000 + off, kp + go);
            cpa16(base + 0x4000 + off, vp + go);
        }
        cpa_commit();
    };

    load_kv(0, 1);
    cpa_wait<1>();
    __syncthreads();

    uint32_t qfh[4][4], qfl[4][4];
    int arow = w*16 + (lane & 15);
    int acb0 = (lane >> 4) << 4;
#pragma unroll
    for (int ks = 0; ks < 4; ks++) {
        uint32_t off = swzb(arow, ks*32 + acb0);
        ldsm4(qfh[ks][0], qfh[ks][1], qfh[ks][2], qfh[ks][3], smb + off);
        ldsm4(qfl[ks][0], qfl[ks][1], qfl[ks][2], qfl[ks][3], smb + 0x4000 + off);
    }
    __syncthreads();
    load_kv(1, 0);

    float O[8][4];
#pragma unroll
    for (int nd = 0; nd < 8; nd++)
#pragma unroll
        for (int e = 0; e < 4; e++) O[nd][e] = 0.f;
    float m0 = -1e30f, m1 = -1e30f, l0 = 0.f, l1 = 0.f;

    int krow_b = (lane & 7) + ((lane >> 1) & 8);
    int kcb_b  = (lane & 8) << 1;
    int vrow_b = lane & 15;
    int vcb_b  = (lane >> 4) << 4;

#pragma unroll 1
    for (int kt = 0; kt < 8; kt++) {
        if (kt == 7) cpa_wait<0>(); else cpa_wait<1>();
        __syncthreads();
        uint32_t base = smb + ((kt + 1) & 1)*0x8000;
        uint32_t bK = base, bV = base + 0x4000;

        float sc[16][4];
#pragma unroll
        for (int jj = 0; jj < 16; jj++)
#pragma unroll
            for (int e = 0; e < 4; e++) sc[jj][e] = 0.f;
#pragma unroll
        for (int ks = 0; ks < 4; ks++) {
#pragma unroll
            for (int p = 0; p < 8; p++) {
                uint32_t k4[4];
                int krow = 16*p + krow_b;
                ldsm4(k4[0], k4[1], k4[2], k4[3], bK + swzb(krow, ks*32 + kcb_b));
                mmaf16(sc[2*p],   qfh[ks], k4+0);
                mmaf16(sc[2*p],   qfl[ks], k4+0);
                mmaf16(sc[2*p+1], qfh[ks], k4+2);
                mmaf16(sc[2*p+1], qfl[ks], k4+2);
            }
        }

        float rm0 = -1e30f, rm1 = -1e30f;
#pragma unroll
        for (int jj = 0; jj < 16; jj++) {
            rm0 = fmaxf(rm0, fmaxf(sc[jj][0], sc[jj][1]));
            rm1 = fmaxf(rm1, fmaxf(sc[jj][2], sc[jj][3]));
        }
        rm0 = fmaxf(rm0, __shfl_xor_sync(0xffffffffu, rm0, 1));
        rm0 = fmaxf(rm0, __shfl_xor_sync(0xffffffffu, rm0, 2));
        rm1 = fmaxf(rm1, __shfl_xor_sync(0xffffffffu, rm1, 1));
        rm1 = fmaxf(rm1, __shfl_xor_sync(0xffffffffu, rm1, 2));
        float mn0 = fmaxf(m0, rm0), mn1 = fmaxf(m1, rm1);
        float a0 = __expf(m0 - mn0), a1 = __expf(m1 - mn1);
        float rs0 = 0.f, rs1 = 0.f;
#pragma unroll
        for (int jj = 0; jj < 16; jj++) {
            sc[jj][0] = __expf(sc[jj][0] - mn0);
            sc[jj][1] = __expf(sc[jj][1] - mn0);
            sc[jj][2] = __expf(sc[jj][2] - mn1);
            sc[jj][3] = __expf(sc[jj][3] - mn1);
            rs0 += sc[jj][0] + sc[jj][1];
            rs1 += sc[jj][2] + sc[jj][3];
        }
        rs0 += __shfl_xor_sync(0xffffffffu, rs0, 1);
        rs0 += __shfl_xor_sync(0xffffffffu, rs0, 2);
        rs1 += __shfl_xor_sync(0xffffffffu, rs1, 1);
        rs1 += __shfl_xor_sync(0xffffffffu, rs1, 2);
        l0 = l0*a0 + rs0; l1 = l1*a1 + rs1;
        m0 = mn0; m1 = mn1;
#pragma unroll
        for (int nd = 0; nd < 8; nd++) {
            O[nd][0] *= a0; O[nd][1] *= a0;
            O[nd][2] *= a1; O[nd][3] *= a1;
        }

        uint32_t pf[8][4];
#pragma unroll
        for (int jj = 0; jj < 8; jj++) {
            pf[jj][0] = h2pack(sc[2*jj][0],   sc[2*jj][1]);
            pf[jj][1] = h2pack(sc[2*jj][2],   sc[2*jj][3]);
            pf[jj][2] = h2pack(sc[2*jj+1][0], sc[2*jj+1][1]);
            pf[jj][3] = h2pack(sc[2*jj+1][2], sc[2*jj+1][3]);
        }

#pragma unroll
        for (int ks2 = 0; ks2 < 8; ks2++) {
#pragma unroll
            for (int pp = 0; pp < 4; pp++) {
                uint32_t v4[4];
                int vrow = ks2*16 + vrow_b;
                ldsm4t(v4[0], v4[1], v4[2], v4[3], bV + swzb(vrow, pp*32 + vcb_b));
                mmaf16(O[2*pp],   pf[ks2], v4+0);
                mmaf16(O[2*pp+1], pf[ks2], v4+2);
            }
        }
        __syncthreads();
        if (kt + 2 < 8) load_kv(kt + 2, (kt + 1) & 1);
    }

    float inv0 = 1.f / l0, inv1 = 1.f / l1;
    int g = lane >> 2, t2 = (lane & 3)*2;
    int bb = bh / NH, h = bh - bb*NH;
    int n0 = qt*128 + w*16 + g;
#pragma unroll
    for (int nd = 0; nd < 8; nd++) {
        int col = h*64 + nd*8 + t2;
        size_t o0 = ((size_t)bb*SEQ + n0)*CC + col;
        size_t o1 = ((size_t)bb*SEQ + n0 + 8)*CC + col;
        __half h0,l0b,h1,l1b,h2v,l2,h3,l3;
        hsplit(O[nd][0]*inv0, h0, l0b); hsplit(O[nd][1]*inv0, h1, l1b);
        hsplit(O[nd][2]*inv1, h2v, l2); hsplit(O[nd][3]*inv1, h3, l3);
        *(__half2*)(g_aoh + o0) = __half2(h0,h1);
        *(__half2*)(g_aol + o0) = __half2(l0b,l1b);
        *(__half2*)(g_aoh + o1) = __half2(h2v,h3);
        *(__half2*)(g_aol + o1) = __half2(l2,l3);
    }
}

// ---------------------------------------------------------------------------
extern "C" void kernel_launch(void* const* d_in, const int* in_sizes, int n_in,
                              void* d_out, int out_size) {
    const float* x      = (const float*)d_in[0];
    const float* y      = (const float*)d_in[1];
    const float* q_w    = (const float*)d_in[2];
    const float* q_b    = (const float*)d_in[3];
    const float* kv_w   = (const float*)d_in[4];
    const float* kv_b   = (const float*)d_in[5];
    const float* proj_w = (const float*)d_in[6];
    const float* proj_b = (const float*)d_in[7];
    const float* ln_g   = (const float*)d_in[8];
    const float* ln_b   = (const float*)d_in[9];
    float* out = (float*)d_out;

    void *pah, *pal, *pw, *pp, *pc, *paoh, *paol;
    cudaGetSymbolAddress(&pah,  g_ah);
    cudaGetSymbolAddress(&pal,  g_al);
    cudaGetSymbolAddress(&pw,   g_w);
    cudaGetSymbolAddress(&pp,   g_p);
    cudaGetSymbolAddress(&pc,   g_c);
    cudaGetSymbolAddress(&paoh, g_aoh);
    cudaGetSymbolAddress(&paol, g_aol);

    prep_x<<<1184, 256>>>(x);
    prep_w<<<1184, 256>>>(q_w, kv_w, proj_w);
    ln_kernel<<<MM, 256>>>(y, ln_g, ln_b);

    int smg = 2*STGB;   // 61440
    cudaFuncSetAttribute(hgemm<false>, cudaFuncAttributeMaxDynamicSharedMemorySize, smg);
    cudaFuncSetAttribute(hgemm<true>,  cudaFuncAttributeMaxDynamicSharedMemorySize, smg);

    hgemm<false><<<dim3(18, 128), 256, smg>>>(
        (const __half*)pah, (const __half*)pal, (const __half*)pw,
        (float*)pc, nullptr, NQKV);

    gate_kernel<<<18432, 256>>>(q_b, kv_b);

    int sma = 2*0x8000;   // 65536
    cudaFuncSetAttribute(attn_mma, cudaFuncAttributeMaxDynamicSharedMemorySize, sma);
    attn_mma<<<dim3(8, 96), 256, sma>>>();

    hgemm<true><<<dim3(6, 64), 256, smg>>>(
        (const __half*)paoh, (const __half*)paol, (const __half*)pp,
        out, proj_b, CC);
}

// round 8
// speedup vs baseline: 4.1547x; 1.0929x over previous
#include <cuda_runtime.h>
#include <cuda_fp16.h>
#include <cstdint>

#define SEQ  1024
#define CC   768
#define NH   12
#define HD   64
#define MM   8192
#define NQKV 2304

// ---------------- scratch (device globals) ----------------------------------
__device__ __half g_ah[MM*CC], g_al[MM*CC];       // x f16 hi/lo
__device__ __half g_y[MM*CC];                     // y2 (post-LN) f16
__device__ __half g_w[NQKV*CC];                   // concat(q_w, kv_w) f16
__device__ __half g_p[CC*CC];                     // proj_w f16
__device__ float  g_c[2*MM*NQKV];                 // qkv GEMM out (fp32): [Cx; Cy]
__device__ __half g_qh[MM*CC], g_ql[MM*CC];       // q (x0.125) f16 hi/lo
__device__ __half g_k[MM*CC];                     // k f16
__device__ __half g_v[MM*CC];                     // v f16
__device__ __half g_aoh[MM*CC], g_aol[MM*CC];     // attn out f16 hi/lo

// ---------------- helpers ----------------------------------------------------
__device__ __forceinline__ uint32_t smem_u32(const void* p) {
    uint32_t a;
    asm("{ .reg .u64 t; cvta.to.shared.u64 t, %1; cvt.u32.u64 %0, t; }" : "=r"(a) : "l"(p));
    return a;
}
__device__ __forceinline__ void cpa16(uint32_t s, const void* g) {
    asm volatile("cp.async.cg.shared.global [%0], [%1], 16;" :: "r"(s), "l"(g));
}
__device__ __forceinline__ void cpa_commit() { asm volatile("cp.async.commit_group;"); }
template<int N> __device__ __forceinline__ void cpa_wait() {
    asm volatile("cp.async.wait_group %0;" :: "n"(N));
}
__device__ __forceinline__ void ldsm4(uint32_t& r0, uint32_t& r1, uint32_t& r2, uint32_t& r3,
                                      uint32_t addr) {
    asm volatile("ldmatrix.sync.aligned.m8n8.x4.shared.b16 {%0,%1,%2,%3}, [%4];"
                 : "=r"(r0), "=r"(r1), "=r"(r2), "=r"(r3) : "r"(addr));
}
__device__ __forceinline__ void ldsm4t(uint32_t& r0, uint32_t& r1, uint32_t& r2, uint32_t& r3,
                                       uint32_t addr) {
    asm volatile("ldmatrix.sync.aligned.m8n8.x4.trans.shared.b16 {%0,%1,%2,%3}, [%4];"
                 : "=r"(r0), "=r"(r1), "=r"(r2), "=r"(r3) : "r"(addr));
}
__device__ __forceinline__ void mmaf16(float* c, const uint32_t* a, const uint32_t* b) {
    asm volatile("mma.sync.aligned.m16n8k16.row.col.f32.f16.f16.f32 "
                 "{%0,%1,%2,%3}, {%4,%5,%6,%7}, {%8,%9}, {%0,%1,%2,%3};"
                 : "+f"(c[0]), "+f"(c[1]), "+f"(c[2]), "+f"(c[3])
                 : "r"(a[0]), "r"(a[1]), "r"(a[2]), "r"(a[3]), "r"(b[0]), "r"(b[1]));
}
__device__ __forceinline__ void hsplit(float f, __half& h, __half& l) {
    h = __float2half_rn(f);
    l = __float2half_rn(f - __half2float(h));
}
__device__ __forceinline__ uint32_t h2pack(float a, float b) {
    __half2 h = __floats2half2_rn(a, b);
    return *(uint32_t*)&h;
}
__device__ __forceinline__ float sigmoidf_(float x) { return 1.f/(1.f+__expf(-x)); }
__device__ __forceinline__ uint32_t swzb(int row, int cb) {
    return (uint32_t)(row*128 + ((((cb) >> 4) ^ (row & 7)) << 4));
}

// ---------------------------------------------------------------------------
__global__ void prep_x(const float* __restrict__ x) {
    for (int i = blockIdx.x*blockDim.x + threadIdx.x; i < MM*CC; i += gridDim.x*blockDim.x)
        hsplit(x[i], g_ah[i], g_al[i]);
}
__global__ void prep_w(const float* __restrict__ qw, const float* __restrict__ kvw,
                       const float* __restrict__ pw) {
    const int QW = CC*CC, WCAT = NQKV*CC, TOT = WCAT + CC*CC;
    for (int i = blockIdx.x*blockDim.x + threadIdx.x; i < TOT; i += gridDim.x*blockDim.x) {
        if (i < QW)        g_w[i] = __float2half_rn(qw[i]);
        else if (i < WCAT) g_w[i] = __float2half_rn(kvw[i-QW]);
        else               g_p[i-WCAT] = __float2half_rn(pw[i-WCAT]);
    }
}

__global__ void ln_kernel(const float* __restrict__ y,
                          const float* __restrict__ gam, const float* __restrict__ bet) {
    int m = blockIdx.x, bb = m >> 10, n = m & 1023;
    const float* yp = y + (size_t)bb*CC*SEQ + n;
    float v[3]; float s = 0.f, s2 = 0.f;
#pragma unroll
    for (int i = 0; i < 3; i++) {
        int c = threadIdx.x + i*256;
        float t = yp[(size_t)c*SEQ];
        v[i] = t; s += t; s2 += t*t;
    }
#pragma unroll
    for (int o = 16; o > 0; o >>= 1) {
        s  += __shfl_xor_sync(0xffffffffu, s,  o);
        s2 += __shfl_xor_sync(0xffffffffu, s2, o);
    }
    __shared__ float rb[2][8];
    if ((threadIdx.x & 31) == 0) { rb[0][threadIdx.x>>5] = s; rb[1][threadIdx.x>>5] = s2; }
    __syncthreads();
    float ts = 0.f, ts2 = 0.f;
#pragma unroll
    for (int i = 0; i < 8; i++) { ts += rb[0][i]; ts2 += rb[1][i]; }
    float mean = ts*(1.f/CC), var = ts2*(1.f/CC) - mean*mean;
    float rstd = rsqrtf(var + 1e-5f);
#pragma unroll
    for (int i = 0; i < 3; i++) {
        int c = threadIdx.x + i*256;
        float o = (v[i]-mean)*rstd*gam[c] + bet[c];
        g_y[(size_t)m*CC + c] = __float2half_rn(o);
    }
}

// ---------------------------------------------------------------------------
// f16 GEMM. TWOPASS: A given as hi/lo pair (2 MMAs/tile); else single A (1 MMA).
// Block 128x128, K staged 32, double-buffered.
// ---------------------------------------------------------------------------
#define PITCH 80
#define BUFB  10240

template<bool BIAS, bool TWOPASS>
__global__ __launch_bounds__(256, 2)
void hgemm(const __half* __restrict__ Ah, const __half* __restrict__ Al,
           const __half* __restrict__ W,
           float* __restrict__ C, const float* __restrict__ bias, int ldc) {
    constexpr int NBUF = TWOPASS ? 3 : 2;
    constexpr int STGB = NBUF * BUFB;
    extern __shared__ __align__(16) char smraw[];
    uint32_t smb = smem_u32(smraw);
    int t = threadIdx.x, lane = t & 31, w = t >> 5;
    int wm = w >> 1, wn = w & 1;
    int am0 = blockIdx.y * 128, wn0 = blockIdx.x * 128;

    const __half* srcs[NBUF];
    srcs[0] = Ah + (size_t)am0*CC;
    if (TWOPASS) { srcs[1] = Al + (size_t)am0*CC; srcs[NBUF-1] = W + (size_t)wn0*CC; }
    else         { srcs[1] = W + (size_t)wn0*CC; }

    int r0 = t >> 2, c0 = t & 3;
    int r1 = (t + 256) >> 2, c1 = t & 3;

    auto load_stage = [&](int s, int k0) {
        uint32_t base = smb + (s & 1)*STGB;
#pragma unroll
        for (int b = 0; b < NBUF; b++) {
            cpa16(base + b*BUFB + r0*PITCH + c0*16, srcs[b] + (size_t)r0*CC + k0 + c0*8);
            cpa16(base + b*BUFB + r1*PITCH + c1*16, srcs[b] + (size_t)r1*CC + k0 + c1*8);
        }
        cpa_commit();
    };

    float acc[2][8][4];
#pragma unroll
    for (int mi = 0; mi < 2; mi++)
#pragma unroll
        for (int ni = 0; ni < 8; ni++)
#pragma unroll
            for (int e = 0; e < 4; e++) acc[mi][ni][e] = 0.f;

    load_stage(0, 0);

    const int NSTG = CC/32;
    int a_row  = wm*32 + (lane & 15);
    int a_coff = (lane >> 4) * 16;
    int b_row  = (lane & 7) + ((lane >> 1) & 8);
    int b_coff = (lane & 8) * 2;

#pragma unroll 1
    for (int s = 0; s < NSTG; s++) {
        if (s + 1 < NSTG) load_stage(s + 1, (s + 1)*32);
        if (s + 1 < NSTG) cpa_wait<1>(); else cpa_wait<0>();
        __syncthreads();
        uint32_t bAh = smb + (s & 1)*STGB;
        uint32_t bAl = bAh + BUFB;
        uint32_t bW  = bAh + (NBUF-1)*BUFB;
#pragma unroll
        for (int ks = 0; ks < 2; ks++) {
            int kb = ks*32;
            uint32_t ah[2][4], al[2][4], bw[8][2];
            ldsm4(ah[0][0], ah[0][1], ah[0][2], ah[0][3], bAh + (a_row)*PITCH     + kb + a_coff);
            ldsm4(ah[1][0], ah[1][1], ah[1][2], ah[1][3], bAh + (a_row+16)*PITCH + kb + a_coff);
            if (TWOPASS) {
                ldsm4(al[0][0], al[0][1], al[0][2], al[0][3], bAl + (a_row)*PITCH     + kb + a_coff);
                ldsm4(al[1][0], al[1][1], al[1][2], al[1][3], bAl + (a_row+16)*PITCH + kb + a_coff);
            }
#pragma unroll
            for (int p = 0; p < 4; p++) {
                int nr = wn*64 + p*16 + b_row;
                ldsm4(bw[2*p][0], bw[2*p][1], bw[2*p+1][0], bw[2*p+1][1],
                      bW + nr*PITCH + kb + b_coff);
            }
#pragma unroll
            for (int mi = 0; mi < 2; mi++)
#pragma unroll
                for (int ni = 0; ni < 8; ni++) {
                    mmaf16(acc[mi][ni], ah[mi], bw[ni]);
                    if (TWOPASS) mmaf16(acc[mi][ni], al[mi], bw[ni]);
                }
        }
        __syncthreads();
    }

#pragma unroll
    for (int mi = 0; mi < 2; mi++) {
        int row = am0 + wm*32 + mi*16 + (lane >> 2);
#pragma unroll
        for (int ni = 0; ni < 8; ni++) {
            int col = wn0 + wn*64 + ni*8 + 2*(lane & 3);
            float b0 = 0.f, b1 = 0.f;
            if (BIAS) { b0 = bias[col]; b1 = bias[col+1]; }
            *(float2*)(C + (size_t)row*ldc + col)     = make_float2(acc[mi][ni][0]+b0, acc[mi][ni][1]+b1);
            *(float2*)(C + (size_t)(row+8)*ldc + col) = make_float2(acc[mi][ni][2]+b0, acc[mi][ni][3]+b1);
        }
    }
}

// ---------------------------------------------------------------------------
// gate: gating epilogue -> q f16 hi/lo (x0.125), k f16, v f16, [b,h,n,d]
// ---------------------------------------------------------------------------
__global__ void gate_kernel(const float* __restrict__ qb, const float* __restrict__ kvb) {
    int i = blockIdx.x*blockDim.x + threadIdx.x;
    int m = i / 576, j = (i - m*576) * 4;
    float4 x4 = *(const float4*)(g_c + (size_t)m*NQKV + j);
    float4 y4 = *(const float4*)(g_c + (size_t)(m + MM)*NQKV + j);
    int bb = m >> 10, n = m & 1023;
    float o[4];
    if (j < CC) {
        float4 b4 = *(const float4*)(qb + j);
        float xx[4] = {x4.x+b4.x, x4.y+b4.y, x4.z+b4.z, x4.w+b4.w};
        float yy[4] = {y4.x+b4.x, y4.y+b4.y, y4.z+b4.z, y4.w+b4.w};
#pragma unroll
        for (int e = 0; e < 4; e++) o[e] = 0.125f * xx[e]*(1.f + sigmoidf_(yy[e]));
        int h = j >> 6, d = j & 63;
        size_t off = (((size_t)bb*NH + h)*SEQ + n)*HD + d;
        __half hh[4], ll[4];
#pragma unroll
        for (int e = 0; e < 4; e++) hsplit(o[e], hh[e], ll[e]);
        *(__half2*)(g_qh+off)   = __half2(hh[0],hh[1]);
        *(__half2*)(g_qh+off+2) = __half2(hh[2],hh[3]);
        *(__half2*)(g_ql+off)   = __half2(ll[0],ll[1]);
        *(__half2*)(g_ql+off+2) = __half2(ll[2],ll[3]);
    } else {
        float4 b4 = *(const float4*)(kvb + j - CC);
        float xx[4] = {x4.x+b4.x, x4.y+b4.y, x4.z+b4.z, x4.w+b4.w};
        float yy[4] = {y4.x+b4.x, y4.y+b4.y, y4.z+b4.z, y4.w+b4.w};
#pragma unroll
        for (int e = 0; e < 4; e++) o[e] = sigmoidf_(yy[e])*(xx[e] + 1.f);
        __half* dst = (j < 2*CC) ? g_k : g_v;
        int h = ((j < 2*CC) ? (j - CC) : (j - 2*CC)) >> 6, d = j & 63;
        size_t off = (((size_t)bb*NH + h)*SEQ + n)*HD + d;
        *(__half2*)(dst+off)   = __floats2half2_rn(o[0], o[1]);
        *(__half2*)(dst+off+2) = __floats2half2_rn(o[2], o[3]);
    }
}

// ---------------------------------------------------------------------------
// TC flash attention (unchanged from R7).
// ---------------------------------------------------------------------------
__global__ __launch_bounds__(256, 1)
void attn_mma() {
    extern __shared__ __align__(16) char smraw[];
    uint32_t smb = smem_u32(smraw);
    int qt = blockIdx.x, bh = blockIdx.y;
    int t = threadIdx.x, lane = t & 31, w = t >> 5;
    const __half* qhp = g_qh + (size_t)bh*SEQ*HD + (size_t)qt*128*HD;
    const __half* qlp = g_ql + (size_t)bh*SEQ*HD + (size_t)qt*128*HD;
    const __half* kp  = g_k  + (size_t)bh*SEQ*HD;
    const __half* vp  = g_v  + (size_t)bh*SEQ*HD;

#pragma unroll
    for (int i = 0; i < 4; i++) {
        int c = t + i*256;
        int row = c >> 3, ch = c & 7;
        cpa16(smb + swzb(row, ch*16),          qhp + (size_t)row*HD + ch*8);
        cpa16(smb + 0x4000 + swzb(row, ch*16), qlp + (size_t)row*HD + ch*8);
    }
    cpa_commit();

    auto load_kv = [&](int kt, int stage) {
        uint32_t base = smb + stage*0x8000;
#pragma unroll
        for (int i = 0; i < 4; i++) {
            int c = t + i*256;
            int row = c >> 3, ch = c & 7;
            uint32_t off = swzb(row, ch*16);
            const size_t go = (size_t)(kt*128 + row)*HD + ch*8;
            cpa16(base + 0x0000 + off, kp + go);
            cpa16(base + 0x4000 + off, vp + go);
        }
        cpa_commit();
    };

    load_kv(0, 1);
    cpa_wait<1>();
    __syncthreads();

    uint32_t qfh[4][4], qfl[4][4];
    int arow = w*16 + (lane & 15);
    int acb0 = (lane >> 4) << 4;
#pragma unroll
    for (int ks = 0; ks < 4; ks++) {
        uint32_t off = swzb(arow, ks*32 + acb0);
        ldsm4(qfh[ks][0], qfh[ks][1], qfh[ks][2], qfh[ks][3], smb + off);
        ldsm4(qfl[ks][0], qfl[ks][1], qfl[ks][2], qfl[ks][3], smb + 0x4000 + off);
    }
    __syncthreads();
    load_kv(1, 0);

    float O[8][4];
#pragma unroll
    for (int nd = 0; nd < 8; nd++)
#pragma unroll
        for (int e = 0; e < 4; e++) O[nd][e] = 0.f;
    float m0 = -1e30f, m1 = -1e30f, l0 = 0.f, l1 = 0.f;

    int krow_b = (lane & 7) + ((lane >> 1) & 8);
    int kcb_b  = (lane & 8) << 1;
    int vrow_b = lane & 15;
    int vcb_b  = (lane >> 4) << 4;

#pragma unroll 1
    for (int kt = 0; kt < 8; kt++) {
        if (kt == 7) cpa_wait<0>(); else cpa_wait<1>();
        __syncthreads();
        uint32_t base = smb + ((kt + 1) & 1)*0x8000;
        uint32_t bK = base, bV = base + 0x4000;

        float sc[16][4];
#pragma unroll
        for (int jj = 0; jj < 16; jj++)
#pragma unroll
            for (int e = 0; e < 4; e++) sc[jj][e] = 0.f;
#pragma unroll
        for (int ks = 0; ks < 4; ks++) {
#pragma unroll
            for (int p = 0; p < 8; p++) {
                uint32_t k4[4];
                int krow = 16*p + krow_b;
                ldsm4(k4[0], k4[1], k4[2], k4[3], bK + swzb(krow, ks*32 + kcb_b));
                mmaf16(sc[2*p],   qfh[ks], k4+0);
                mmaf16(sc[2*p],   qfl[ks], k4+0);
                mmaf16(sc[2*p+1], qfh[ks], k4+2);
                mmaf16(sc[2*p+1], qfl[ks], k4+2);
            }
        }

        float rm0 = -1e30f, rm1 = -1e30f;
#pragma unroll
        for (int jj = 0; jj < 16; jj++) {
            rm0 = fmaxf(rm0, fmaxf(sc[jj][0], sc[jj][1]));
            rm1 = fmaxf(rm1, fmaxf(sc[jj][2], sc[jj][3]));
        }
        rm0 = fmaxf(rm0, __shfl_xor_sync(0xffffffffu, rm0, 1));
        rm0 = fmaxf(rm0, __shfl_xor_sync(0xffffffffu, rm0, 2));
        rm1 = fmaxf(rm1, __shfl_xor_sync(0xffffffffu, rm1, 1));
        rm1 = fmaxf(rm1, __shfl_xor_sync(0xffffffffu, rm1, 2));
        float mn0 = fmaxf(m0, rm0), mn1 = fmaxf(m1, rm1);
        float a0 = __expf(m0 - mn0), a1 = __expf(m1 - mn1);
        float rs0 = 0.f, rs1 = 0.f;
#pragma unroll
        for (int jj = 0; jj < 16; jj++) {
            sc[jj][0] = __expf(sc[jj][0] - mn0);
            sc[jj][1] = __expf(sc[jj][1] - mn0);
            sc[jj][2] = __expf(sc[jj][2] - mn1);
            sc[jj][3] = __expf(sc[jj][3] - mn1);
            rs0 += sc[jj][0] + sc[jj][1];
            rs1 += sc[jj][2] + sc[jj][3];
        }
        rs0 += __shfl_xor_sync(0xffffffffu, rs0, 1);
        rs0 += __shfl_xor_sync(0xffffffffu, rs0, 2);
        rs1 += __shfl_xor_sync(0xffffffffu, rs1, 1);
        rs1 += __shfl_xor_sync(0xffffffffu, rs1, 2);
        l0 = l0*a0 + rs0; l1 = l1*a1 + rs1;
        m0 = mn0; m1 = mn1;
#pragma unroll
        for (int nd = 0; nd < 8; nd++) {
            O[nd][0] *= a0; O[nd][1] *= a0;
            O[nd][2] *= a1; O[nd][3] *= a1;
        }

        uint32_t pf[8][4];
#pragma unroll
        for (int jj = 0; jj < 8; jj++) {
            pf[jj][0] = h2pack(sc[2*jj][0],   sc[2*jj][1]);
            pf[jj][1] = h2pack(sc[2*jj][2],   sc[2*jj][3]);
            pf[jj][2] = h2pack(sc[2*jj+1][0], sc[2*jj+1][1]);
            pf[jj][3] = h2pack(sc[2*jj+1][2], sc[2*jj+1][3]);
        }

#pragma unroll
        for (int ks2 = 0; ks2 < 8; ks2++) {
#pragma unroll
            for (int pp = 0; pp < 4; pp++) {
                uint32_t v4[4];
                int vrow = ks2*16 + vrow_b;
                ldsm4t(v4[0], v4[1], v4[2], v4[3], bV + swzb(vrow, pp*32 + vcb_b));
                mmaf16(O[2*pp],   pf[ks2], v4+0);
                mmaf16(O[2*pp+1], pf[ks2], v4+2);
            }
        }
        __syncthreads();
        if (kt + 2 < 8) load_kv(kt + 2, (kt + 1) & 1);
    }

    float inv0 = 1.f / l0, inv1 = 1.f / l1;
    int g = lane >> 2, t2 = (lane & 3)*2;
    int bb = bh / NH, h = bh - bb*NH;
    int n0 = qt*128 + w*16 + g;
#pragma unroll
    for (int nd = 0; nd < 8; nd++) {
        int col = h*64 + nd*8 + t2;
        size_t o0 = ((size_t)bb*SEQ + n0)*CC + col;
        size_t o1 = ((size_t)bb*SEQ + n0 + 8)*CC + col;
        __half h0,l0b,h1,l1b,h2v,l2,h3,l3;
        hsplit(O[nd][0]*inv0, h0, l0b); hsplit(O[nd][1]*inv0, h1, l1b);
        hsplit(O[nd][2]*inv1, h2v, l2); hsplit(O[nd][3]*inv1, h3, l3);
        *(__half2*)(g_aoh + o0) = __half2(h0,h1);
        *(__half2*)(g_aol + o0) = __half2(l0b,l1b);
        *(__half2*)(g_aoh + o1) = __half2(h2v,h3);
        *(__half2*)(g_aol + o1) = __half2(l2,l3);
    }
}

// ---------------------------------------------------------------------------
extern "C" void kernel_launch(void* const* d_in, const int* in_sizes, int n_in,
                              void* d_out, int out_size) {
    const float* x      = (const float*)d_in[0];
    const float* y      = (const float*)d_in[1];
    const float* q_w    = (const float*)d_in[2];
    const float* q_b    = (const float*)d_in[3];
    const float* kv_w   = (const float*)d_in[4];
    const float* kv_b   = (const float*)d_in[5];
    const float* proj_w = (const float*)d_in[6];
    const float* proj_b = (const float*)d_in[7];
    const float* ln_g   = (const float*)d_in[8];
    const float* ln_b   = (const float*)d_in[9];
    float* out = (float*)d_out;

    void *pah, *pal, *py, *pw, *pp, *pc, *paoh, *paol;
    cudaGetSymbolAddress(&pah,  g_ah);
    cudaGetSymbolAddress(&pal,  g_al);
    cudaGetSymbolAddress(&py,   g_y);
    cudaGetSymbolAddress(&pw,   g_w);
    cudaGetSymbolAddress(&pp,   g_p);
    cudaGetSymbolAddress(&pc,   g_c);
    cudaGetSymbolAddress(&paoh, g_aoh);
    cudaGetSymbolAddress(&paol, g_aol);

    prep_x<<<1184, 256>>>(x);
    prep_w<<<1184, 256>>>(q_w, kv_w, proj_w);
    ln_kernel<<<MM, 256>>>(y, ln_g, ln_b);

    int smg3 = 2*3*BUFB;   // 61440 (TWOPASS)
    int smg2 = 2*2*BUFB;   // 40960 (single)
    cudaFuncSetAttribute((const void*)hgemm<false,true>,  cudaFuncAttributeMaxDynamicSharedMemorySize, smg3);
    cudaFuncSetAttribute((const void*)hgemm<false,false>, cudaFuncAttributeMaxDynamicSharedMemorySize, smg2);
    cudaFuncSetAttribute((const void*)hgemm<true,true>,   cudaFuncAttributeMaxDynamicSharedMemorySize, smg3);

    // Cx = x @ Wcat^T   (2-pass, error-critical)
    hgemm<false,true><<<dim3(18, 64), 256, smg3>>>(
        (const __half*)pah, (const __half*)pal, (const __half*)pw,
        (float*)pc, nullptr, NQKV);
    // Cy = y2 @ Wcat^T  (1-pass; only feeds sigmoid)
    hgemm<false,false><<<dim3(18, 64), 256, smg2>>>(
        (const __half*)py, nullptr, (const __half*)pw,
        (float*)pc + (size_t)MM*NQKV, nullptr, NQKV);

    gate_kernel<<<18432, 256>>>(q_b, kv_b);

    int sma = 2*0x8000;
    cudaFuncSetAttribute(attn_mma, cudaFuncAttributeMaxDynamicSharedMemorySize, sma);
    attn_mma<<<dim3(8, 96), 256, sma>>>();

    hgemm<true,true><<<dim3(6, 64), 256, smg3>>>(
        (const __half*)paoh, (const __half*)paol, (const __half*)pp,
        out, proj_b, CC);
}

// round 9
// speedup vs baseline: 4.1672x; 1.0030x over previous
#include <cuda_runtime.h>
#include <cuda_fp16.h>
#include <cstdint>

#define SEQ  1024
#define CC   768
#define NH   12
#define HD   64
#define MM   8192
#define NQKV 2304

// ---------------- scratch (device globals) ----------------------------------
__device__ __half g_ah[MM*CC], g_al[MM*CC];       // x f16 hi/lo
__device__ __half g_y[MM*CC];                     // y2 (post-LN) f16
__device__ __half g_w[NQKV*CC];                   // concat(q_w, kv_w) f16
__device__ __half g_p[CC*CC];                     // proj_w f16
__device__ __half g_qh[MM*CC], g_ql[MM*CC];       // q (x0.125) f16 hi/lo
__device__ __half g_k[MM*CC];                     // k f16
__device__ __half g_v[MM*CC];                     // v f16
__device__ __half g_aoh[MM*CC], g_aol[MM*CC];     // attn out f16 hi/lo

// ---------------- helpers ----------------------------------------------------
__device__ __forceinline__ uint32_t smem_u32(const void* p) {
    uint32_t a;
    asm("{ .reg .u64 t; cvta.to.shared.u64 t, %1; cvt.u32.u64 %0, t; }" : "=r"(a) : "l"(p));
    return a;
}
__device__ __forceinline__ void cpa16(uint32_t s, const void* g) {
    asm volatile("cp.async.cg.shared.global [%0], [%1], 16;" :: "r"(s), "l"(g));
}
__device__ __forceinline__ void cpa_commit() { asm volatile("cp.async.commit_group;"); }
template<int N> __device__ __forceinline__ void cpa_wait() {
    asm volatile("cp.async.wait_group %0;" :: "n"(N));
}
__device__ __forceinline__ void ldsm4(uint32_t& r0, uint32_t& r1, uint32_t& r2, uint32_t& r3,
                                      uint32_t addr) {
    asm volatile("ldmatrix.sync.aligned.m8n8.x4.shared.b16 {%0,%1,%2,%3}, [%4];"
                 : "=r"(r0), "=r"(r1), "=r"(r2), "=r"(r3) : "r"(addr));
}
__device__ __forceinline__ void ldsm4t(uint32_t& r0, uint32_t& r1, uint32_t& r2, uint32_t& r3,
                                       uint32_t addr) {
    asm volatile("ldmatrix.sync.aligned.m8n8.x4.trans.shared.b16 {%0,%1,%2,%3}, [%4];"
                 : "=r"(r0), "=r"(r1), "=r"(r2), "=r"(r3) : "r"(addr));
}
__device__ __forceinline__ void mmaf16(float* c, const uint32_t* a, const uint32_t* b) {
    asm volatile("mma.sync.aligned.m16n8k16.row.col.f32.f16.f16.f32 "
                 "{%0,%1,%2,%3}, {%4,%5,%6,%7}, {%8,%9}, {%0,%1,%2,%3};"
                 : "+f"(c[0]), "+f"(c[1]), "+f"(c[2]), "+f"(c[3])
                 : "r"(a[0]), "r"(a[1]), "r"(a[2]), "r"(a[3]), "r"(b[0]), "r"(b[1]));
}
__device__ __forceinline__ void hsplit(float f, __half& h, __half& l) {
    h = __float2half_rn(f);
    l = __float2half_rn(f - __half2float(h));
}
__device__ __forceinline__ uint32_t h2pack(float a, float b) {
    __half2 h = __floats2half2_rn(a, b);
    return *(uint32_t*)&h;
}
__device__ __forceinline__ float sigmoidf_(float x) { return 1.f/(1.f+__expf(-x)); }
__device__ __forceinline__ uint32_t swzb(int row, int cb) {
    return (uint32_t)(row*128 + ((((cb) >> 4) ^ (row & 7)) << 4));
}

// ---------------------------------------------------------------------------
__global__ void prep_x(const float* __restrict__ x) {
    for (int i = blockIdx.x*blockDim.x + threadIdx.x; i < MM*CC; i += gridDim.x*blockDim.x)
        hsplit(x[i], g_ah[i], g_al[i]);
}
__global__ void prep_w(const float* __restrict__ qw, const float* __restrict__ kvw,
                       const float* __restrict__ pw) {
    const int QW = CC*CC, WCAT = NQKV*CC, TOT = WCAT + CC*CC;
    for (int i = blockIdx.x*blockDim.x + threadIdx.x; i < TOT; i += gridDim.x*blockDim.x) {
        if (i < QW)        g_w[i] = __float2half_rn(qw[i]);
        else if (i < WCAT) g_w[i] = __float2half_rn(kvw[i-QW]);
        else               g_p[i-WCAT] = __float2half_rn(pw[i-WCAT]);
    }
}

__global__ void ln_kernel(const float* __restrict__ y,
                          const float* __restrict__ gam, const float* __restrict__ bet) {
    int m = blockIdx.x, bb = m >> 10, n = m & 1023;
    const float* yp = y + (size_t)bb*CC*SEQ + n;
    float v[3]; float s = 0.f, s2 = 0.f;
#pragma unroll
    for (int i = 0; i < 3; i++) {
        int c = threadIdx.x + i*256;
        float t = yp[(size_t)c*SEQ];
        v[i] = t; s += t; s2 += t*t;
    }
#pragma unroll
    for (int o = 16; o > 0; o >>= 1) {
        s  += __shfl_xor_sync(0xffffffffu, s,  o);
        s2 += __shfl_xor_sync(0xffffffffu, s2, o);
    }
    __shared__ float rb[2][8];
    if ((threadIdx.x & 31) == 0) { rb[0][threadIdx.x>>5] = s; rb[1][threadIdx.x>>5] = s2; }
    __syncthreads();
    float ts = 0.f, ts2 = 0.f;
#pragma unroll
    for (int i = 0; i < 8; i++) { ts += rb[0][i]; ts2 += rb[1][i]; }
    float mean = ts*(1.f/CC), var = ts2*(1.f/CC) - mean*mean;
    float rstd = rsqrtf(var + 1e-5f);
#pragma unroll
    for (int i = 0; i < 3; i++) {
        int c = threadIdx.x + i*256;
        float o = (v[i]-mean)*rstd*gam[c] + bet[c];
        g_y[(size_t)m*CC + c] = __float2half_rn(o);
    }
}

// ---------------------------------------------------------------------------
// FUSED qkv GEMM + gating. Block = 128 m-rows x 64 n-cols (one head exactly).
// Computes Cx = x@W^T (hi/lo, 2 MMAs) and Cy = y2@W^T (1 MMA) simultaneously,
// applies bias+sigmoid gating in epilogue, writes q/k/v directly. No g_c.
// smem/stage: 3 A bufs (10240) + 1 W buf (5120) = 35840; 2 stages.
// 8 warps in 4(M) x 2(N); warp tile 32x32.
// ---------------------------------------------------------------------------
#define PITCH 80
#define BUFA  10240
#define BUFW  5120
#define QSTG  (3*BUFA + BUFW)    // 35840

__global__ __launch_bounds__(256, 2)
void qkv_fused(const float* __restrict__ qb, const float* __restrict__ kvb) {
    extern __shared__ __align__(16) char smraw[];
    uint32_t smb = smem_u32(smraw);
    int t = threadIdx.x, lane = t & 31, w = t >> 5;
    int wm = w >> 1, wn = w & 1;
    int bx = blockIdx.x;               // 0..35 (n tile = head)
    int m0 = blockIdx.y * 128;
    int j0 = bx * 64;

    const __half* sxh = g_ah + (size_t)m0*CC;
    const __half* sxl = g_al + (size_t)m0*CC;
    const __half* sy  = g_y  + (size_t)m0*CC;
    const __half* sw  = g_w  + (size_t)j0*CC;

    int ra = t >> 2, ca = t & 3;                 // A chunk 0 (rows 0..63)
    int rb2 = (t + 256) >> 2;                    // A chunk 1 (rows 64..127)

    auto load_stage = [&](int s, int k0) {
        uint32_t base = smb + (s & 1)*QSTG;
        cpa16(base + 0*BUFA + ra*PITCH + ca*16,  sxh + (size_t)ra*CC  + k0 + ca*8);
        cpa16(base + 0*BUFA + rb2*PITCH + ca*16, sxh + (size_t)rb2*CC + k0 + ca*8);
        cpa16(base + 1*BUFA + ra*PITCH + ca*16,  sxl + (size_t)ra*CC  + k0 + ca*8);
        cpa16(base + 1*BUFA + rb2*PITCH + ca*16, sxl + (size_t)rb2*CC + k0 + ca*8);
        cpa16(base + 2*BUFA + ra*PITCH + ca*16,  sy  + (size_t)ra*CC  + k0 + ca*8);
        cpa16(base + 2*BUFA + rb2*PITCH + ca*16, sy  + (size_t)rb2*CC + k0 + ca*8);
        cpa16(base + 3*BUFA + ra*PITCH + ca*16,  sw  + (size_t)ra*CC  + k0 + ca*8); // 64 W rows
        cpa_commit();
    };

    float accx[2][4][4], accy[2][4][4];
#pragma unroll
    for (int mi = 0; mi < 2; mi++)
#pragma unroll
        for (int ni = 0; ni < 4; ni++)
#pragma unroll
            for (int e = 0; e < 4; e++) { accx[mi][ni][e] = 0.f; accy[mi][ni][e] = 0.f; }

    load_stage(0, 0);

    const int NSTG = CC/32;   // 24
    int a_row  = wm*32 + (lane & 15);
    int a_coff = (lane >> 4) * 16;
    int b_row  = (lane & 7) + ((lane >> 1) & 8);
    int b_coff = (lane & 8) * 2;

#pragma unroll 1
    for (int s = 0; s < NSTG; s++) {
        if (s + 1 < NSTG) load_stage(s + 1, (s + 1)*32);
        if (s + 1 < NSTG) cpa_wait<1>(); else cpa_wait<0>();
        __syncthreads();
        uint32_t bXh = smb + (s & 1)*QSTG;
        uint32_t bXl = bXh + BUFA, bY = bXh + 2*BUFA, bW = bXh + 3*BUFA;
#pragma unroll
        for (int ks = 0; ks < 2; ks++) {
            int kb = ks*32;
            uint32_t xh[2][4], xl[2][4], yy[2][4], bw[4][2];
            ldsm4(xh[0][0], xh[0][1], xh[0][2], xh[0][3], bXh + (a_row)*PITCH     + kb + a_coff);
            ldsm4(xh[1][0], xh[1][1], xh[1][2], xh[1][3], bXh + (a_row+16)*PITCH + kb + a_coff);
            ldsm4(xl[0][0], xl[0][1], xl[0][2], xl[0][3], bXl + (a_row)*PITCH     + kb + a_coff);
            ldsm4(xl[1][0], xl[1][1], xl[1][2], xl[1][3], bXl + (a_row+16)*PITCH + kb + a_coff);
            ldsm4(yy[0][0], yy[0][1], yy[0][2], yy[0][3], bY  + (a_row)*PITCH     + kb + a_coff);
            ldsm4(yy[1][0], yy[1][1], yy[1][2], yy[1][3], bY  + (a_row+16)*PITCH + kb + a_coff);
#pragma unroll
            for (int p = 0; p < 2; p++) {
                int nr = wn*32 + p*16 + b_row;
                ldsm4(bw[2*p][0], bw[2*p][1], bw[2*p+1][0], bw[2*p+1][1],
                      bW + nr*PITCH + kb + b_coff);
            }
#pragma unroll
            for (int mi = 0; mi < 2; mi++)
#pragma unroll
                for (int ni = 0; ni < 4; ni++) {
                    mmaf16(accx[mi][ni], xh[mi], bw[ni]);
                    mmaf16(accx[mi][ni], xl[mi], bw[ni]);
                    mmaf16(accy[mi][ni], yy[mi], bw[ni]);
                }
        }
        __syncthreads();
    }

    // ---- epilogue: gate + direct scatter to q/k/v ----
    int sec = bx / 12;                // 0=q, 1=k, 2=v
    int h   = bx - sec*12;
#pragma unroll
    for (int mi = 0; mi < 2; mi++) {
#pragma unroll
        for (int e2 = 0; e2 < 2; e2++) {      // row pair (e01 vs e23)
            int r = m0 + wm*32 + mi*16 + (lane >> 2) + e2*8;
            int bb = r >> 10, n = r & 1023;
            size_t obase = (((size_t)bb*NH + h)*SEQ + n)*HD;
#pragma unroll
            for (int ni = 0; ni < 4; ni++) {
                int d = wn*32 + ni*8 + 2*(lane & 3);
                float ax0 = accx[mi][ni][2*e2], ax1 = accx[mi][ni][2*e2+1];
                float ay0 = accy[mi][ni][2*e2], ay1 = accy[mi][ni][2*e2+1];
                if (sec == 0) {
                    float b0 = qb[j0 + d], b1 = qb[j0 + d + 1];
                    float o0 = 0.125f*(ax0+b0)*(1.f + sigmoidf_(ay0+b0));
                    float o1 = 0.125f*(ax1+b1)*(1.f + sigmoidf_(ay1+b1));
                    __half h0,l0,h1,l1;
                    hsplit(o0,h0,l0); hsplit(o1,h1,l1);
                    *(__half2*)(g_qh + obase + d) = __half2(h0,h1);
                    *(__half2*)(g_ql + obase + d) = __half2(l0,l1);
                } else {
                    float b0 = kvb[j0 - CC + d], b1 = kvb[j0 - CC + d + 1];
                    float o0 = sigmoidf_(ay0+b0)*(ax0+b0+1.f);
                    float o1 = sigmoidf_(ay1+b1)*(ax1+b1+1.f);
                    __half* dst = (sec == 1) ? g_k : g_v;
                    *(__half2*)(dst + obase + d) = __floats2half2_rn(o0, o1);
                }
            }
        }
    }
}

// ---------------------------------------------------------------------------
// f16 GEMM for proj (A hi/lo 2-pass). Block 128x128, K staged 32.
// ---------------------------------------------------------------------------
#define BUFB  10240
#define STGB  (3*BUFB)

__global__ __launch_bounds__(256, 2)
void hgemm_proj(const __half* __restrict__ Ah, const __half* __restrict__ Al,
                const __half* __restrict__ W,
                float* __restrict__ C, const float* __restrict__ bias) {
    extern __shared__ __align__(16) char smraw[];
    uint32_t smb = smem_u32(smraw);
    int t = threadIdx.x, lane = t & 31, w = t >> 5;
    int wm = w >> 1, wn = w & 1;
    int am0 = blockIdx.y * 128, wn0 = blockIdx.x * 128;

    const __half* srcs[3] = { Ah + (size_t)am0*CC, Al + (size_t)am0*CC, W + (size_t)wn0*CC };
    int r0 = t >> 2, c0 = t & 3;
    int r1 = (t + 256) >> 2;

    auto load_stage = [&](int s, int k0) {
        uint32_t base = smb + (s & 1)*STGB;
#pragma unroll
        for (int b = 0; b < 3; b++) {
            cpa16(base + b*BUFB + r0*PITCH + c0*16, srcs[b] + (size_t)r0*CC + k0 + c0*8);
            cpa16(base + b*BUFB + r1*PITCH + c0*16, srcs[b] + (size_t)r1*CC + k0 + c0*8);
        }
        cpa_commit();
    };

    float acc[2][8][4];
#pragma unroll
    for (int mi = 0; mi < 2; mi++)
#pragma unroll
        for (int ni = 0; ni < 8; ni++)
#pragma unroll
            for (int e = 0; e < 4; e++) acc[mi][ni][e] = 0.f;

    load_stage(0, 0);

    const int NSTG = CC/32;
    int a_row  = wm*32 + (lane & 15);
    int a_coff = (lane >> 4) * 16;
    int b_row  = (lane & 7) + ((lane >> 1) & 8);
    int b_coff = (lane & 8) * 2;

#pragma unroll 1
    for (int s = 0; s < NSTG; s++) {
        if (s + 1 < NSTG) load_stage(s + 1, (s + 1)*32);
        if (s + 1 < NSTG) cpa_wait<1>(); else cpa_wait<0>();
        __syncthreads();
        uint32_t bAh = smb + (s & 1)*STGB;
        uint32_t bAl = bAh + BUFB, bW = bAh + 2*BUFB;
#pragma unroll
        for (int ks = 0; ks < 2; ks++) {
            int kb = ks*32;
            uint32_t ah[2][4], al[2][4], bw[8][2];
            ldsm4(ah[0][0], ah[0][1], ah[0][2], ah[0][3], bAh + (a_row)*PITCH     + kb + a_coff);
            ldsm4(ah[1][0], ah[1][1], ah[1][2], ah[1][3], bAh + (a_row+16)*PITCH + kb + a_coff);
            ldsm4(al[0][0], al[0][1], al[0][2], al[0][3], bAl + (a_row)*PITCH     + kb + a_coff);
            ldsm4(al[1][0], al[1][1], al[1][2], al[1][3], bAl + (a_row+16)*PITCH + kb + a_coff);
#pragma unroll
            for (int p = 0; p < 4; p++) {
                int nr = wn*64 + p*16 + b_row;
                ldsm4(bw[2*p][0], bw[2*p][1], bw[2*p+1][0], bw[2*p+1][1],
                      bW + nr*PITCH + kb + b_coff);
            }
#pragma unroll
            for (int mi = 0; mi < 2; mi++)
#pragma unroll
                for (int ni = 0; ni < 8; ni++) {
                    mmaf16(acc[mi][ni], ah[mi], bw[ni]);
                    mmaf16(acc[mi][ni], al[mi], bw[ni]);
                }
        }
        __syncthreads();
    }

#pragma unroll
    for (int mi = 0; mi < 2; mi++) {
        int row = am0 + wm*32 + mi*16 + (lane >> 2);
#pragma unroll
        for (int ni = 0; ni < 8; ni++) {
            int col = wn0 + wn*64 + ni*8 + 2*(lane & 3);
            float b0 = bias[col], b1 = bias[col+1];
            *(float2*)(C + (size_t)row*CC + col)     = make_float2(acc[mi][ni][0]+b0, acc[mi][ni][1]+b1);
            *(float2*)(C + (size_t)(row+8)*CC + col) = make_float2(acc[mi][ni][2]+b0, acc[mi][ni][3]+b1);
        }
    }
}

// ---------------------------------------------------------------------------
// TC flash attention (unchanged from R7/R8).
// ---------------------------------------------------------------------------
__global__ __launch_bounds__(256, 1)
void attn_mma() {
    extern __shared__ __align__(16) char smraw[];
    uint32_t smb = smem_u32(smraw);
    int qt = blockIdx.x, bh = blockIdx.y;
    int t = threadIdx.x, lane = t & 31, w = t >> 5;
    const __half* qhp = g_qh + (size_t)bh*SEQ*HD + (size_t)qt*128*HD;
    const __half* qlp = g_ql + (size_t)bh*SEQ*HD + (size_t)qt*128*HD;
    const __half* kp  = g_k  + (size_t)bh*SEQ*HD;
    const __half* vp  = g_v  + (size_t)bh*SEQ*HD;

#pragma unroll
    for (int i = 0; i < 4; i++) {
        int c = t + i*256;
        int row = c >> 3, ch = c & 7;
        cpa16(smb + swzb(row, ch*16),          qhp + (size_t)row*HD + ch*8);
        cpa16(smb + 0x4000 + swzb(row, ch*16), qlp + (size_t)row*HD + ch*8);
    }
    cpa_commit();

    auto load_kv = [&](int kt, int stage) {
        uint32_t base = smb + stage*0x8000;
#pragma unroll
        for (int i = 0; i < 4; i++) {
            int c = t + i*256;
            int row = c >> 3, ch = c & 7;
            uint32_t off = swzb(row, ch*16);
            const size_t go = (size_t)(kt*128 + row)*HD + ch*8;
            cpa16(base + 0x0000 + off, kp + go);
            cpa16(base + 0x4000 + off, vp + go);
        }
        cpa_commit();
    };

    load_kv(0, 1);
    cpa_wait<1>();
    __syncthreads();

    uint32_t qfh[4][4], qfl[4][4];
    int arow = w*16 + (lane & 15);
    int acb0 = (lane >> 4) << 4;
#pragma unroll
    for (int ks = 0; ks < 4; ks++) {
        uint32_t off = swzb(arow, ks*32 + acb0);
        ldsm4(qfh[ks][0], qfh[ks][1], qfh[ks][2], qfh[ks][3], smb + off);
        ldsm4(qfl[ks][0], qfl[ks][1], qfl[ks][2], qfl[ks][3], smb + 0x4000 + off);
    }
    __syncthreads();
    load_kv(1, 0);

    float O[8][4];
#pragma unroll
    for (int nd = 0; nd < 8; nd++)
#pragma unroll
        for (int e = 0; e < 4; e++) O[nd][e] = 0.f;
    float m0 = -1e30f, m1 = -1e30f, l0 = 0.f, l1 = 0.f;

    int krow_b = (lane & 7) + ((lane >> 1) & 8);
    int kcb_b  = (lane & 8) << 1;
    int vrow_b = lane & 15;
    int vcb_b  = (lane >> 4) << 4;

#pragma unroll 1
    for (int kt = 0; kt < 8; kt++) {
        if (kt == 7) cpa_wait<0>(); else cpa_wait<1>();
        __syncthreads();
        uint32_t base = smb + ((kt + 1) & 1)*0x8000;
        uint32_t bK = base, bV = base + 0x4000;

        float sc[16][4];
#pragma unroll
        for (int jj = 0; jj < 16; jj++)
#pragma unroll
            for (int e = 0; e < 4; e++) sc[jj][e] = 0.f;
#pragma unroll
        for (int ks = 0; ks < 4; ks++) {
#pragma unroll
            for (int p = 0; p < 8; p++) {
                uint32_t k4[4];
                int krow = 16*p + krow_b;
                ldsm4(k4[0], k4[1], k4[2], k4[3], bK + swzb(krow, ks*32 + kcb_b));
                mmaf16(sc[2*p],   qfh[ks], k4+0);
                mmaf16(sc[2*p],   qfl[ks], k4+0);
                mmaf16(sc[2*p+1], qfh[ks], k4+2);
                mmaf16(sc[2*p+1], qfl[ks], k4+2);
            }
        }

        float rm0 = -1e30f, rm1 = -1e30f;
#pragma unroll
        for (int jj = 0; jj < 16; jj++) {
            rm0 = fmaxf(rm0, fmaxf(sc[jj][0], sc[jj][1]));
            rm1 = fmaxf(rm1, fmaxf(sc[jj][2], sc[jj][3]));
        }
        rm0 = fmaxf(rm0, __shfl_xor_sync(0xffffffffu, rm0, 1));
        rm0 = fmaxf(rm0, __shfl_xor_sync(0xffffffffu, rm0, 2));
        rm1 = fmaxf(rm1, __shfl_xor_sync(0xffffffffu, rm1, 1));
        rm1 = fmaxf(rm1, __shfl_xor_sync(0xffffffffu, rm1, 2));
        float mn0 = fmaxf(m0, rm0), mn1 = fmaxf(m1, rm1);
        float a0 = __expf(m0 - mn0), a1 = __expf(m1 - mn1);
        float rs0 = 0.f, rs1 = 0.f;
#pragma unroll
        for (int jj = 0; jj < 16; jj++) {
            sc[jj][0] = __expf(sc[jj][0] - mn0);
            sc[jj][1] = __expf(sc[jj][1] - mn0);
            sc[jj][2] = __expf(sc[jj][2] - mn1);
            sc[jj][3] = __expf(sc[jj][3] - mn1);
            rs0 += sc[jj][0] + sc[jj][1];
            rs1 += sc[jj][2] + sc[jj][3];
        }
        rs0 += __shfl_xor_sync(0xffffffffu, rs0, 1);
        rs0 += __shfl_xor_sync(0xffffffffu, rs0, 2);
        rs1 += __shfl_xor_sync(0xffffffffu, rs1, 1);
        rs1 += __shfl_xor_sync(0xffffffffu, rs1, 2);
        l0 = l0*a0 + rs0; l1 = l1*a1 + rs1;
        m0 = mn0; m1 = mn1;
#pragma unroll
        for (int nd = 0; nd < 8; nd++) {
            O[nd][0] *= a0; O[nd][1] *= a0;
            O[nd][2] *= a1; O[nd][3] *= a1;
        }

        uint32_t pf[8][4];
#pragma unroll
        for (int jj = 0; jj < 8; jj++) {
            pf[jj][0] = h2pack(sc[2*jj][0],   sc[2*jj][1]);
            pf[jj][1] = h2pack(sc[2*jj][2],   sc[2*jj][3]);
            pf[jj][2] = h2pack(sc[2*jj+1][0], sc[2*jj+1][1]);
            pf[jj][3] = h2pack(sc[2*jj+1][2], sc[2*jj+1][3]);
        }

#pragma unroll
        for (int ks2 = 0; ks2 < 8; ks2++) {
#pragma unroll
            for (int pp = 0; pp < 4; pp++) {
                uint32_t v4[4];
                int vrow = ks2*16 + vrow_b;
                ldsm4t(v4[0], v4[1], v4[2], v4[3], bV + swzb(vrow, pp*32 + vcb_b));
                mmaf16(O[2*pp],   pf[ks2], v4+0);
                mmaf16(O[2*pp+1], pf[ks2], v4+2);
            }
        }
        __syncthreads();
        if (kt + 2 < 8) load_kv(kt + 2, (kt + 1) & 1);
    }

    float inv0 = 1.f / l0, inv1 = 1.f / l1;
    int g = lane >> 2, t2 = (lane & 3)*2;
    int bb = bh / NH, h = bh - bb*NH;
    int n0 = qt*128 + w*16 + g;
#pragma unroll
    for (int nd = 0; nd < 8; nd++) {
        int col = h*64 + nd*8 + t2;
        size_t o0 = ((size_t)bb*SEQ + n0)*CC + col;
        size_t o1 = ((size_t)bb*SEQ + n0 + 8)*CC + col;
        __half h0,l0b,h1,l1b,h2v,l2,h3,l3;
        hsplit(O[nd][0]*inv0, h0, l0b); hsplit(O[nd][1]*inv0, h1, l1b);
        hsplit(O[nd][2]*inv1, h2v, l2); hsplit(O[nd][3]*inv1, h3, l3);
        *(__half2*)(g_aoh + o0) = __half2(h0,h1);
        *(__half2*)(g_aol + o0) = __half2(l0b,l1b);
        *(__half2*)(g_aoh + o1) = __half2(h2v,h3);
        *(__half2*)(g_aol + o1) = __half2(l2,l3);
    }
}

// ---------------------------------------------------------------------------
extern "C" void kernel_launch(void* const* d_in, const int* in_sizes, int n_in,
                              void* d_out, int out_size) {
    const float* x      = (const float*)d_in[0];
    const float* y      = (const float*)d_in[1];
    const float* q_w    = (const float*)d_in[2];
    const float* q_b    = (const float*)d_in[3];
    const float* kv_w   = (const float*)d_in[4];
    const float* kv_b   = (const float*)d_in[5];
    const float* proj_w = (const float*)d_in[6];
    const float* proj_b = (const float*)d_in[7];
    const float* ln_g   = (const float*)d_in[8];
    const float* ln_b   = (const float*)d_in[9];
    float* out = (float*)d_out;

    void *paoh, *paol, *pp;
    cudaGetSymbolAddress(&paoh, g_aoh);
    cudaGetSymbolAddress(&paol, g_aol);
    cudaGetSymbolAddress(&pp,   g_p);

    prep_x<<<1184, 256>>>(x);
    prep_w<<<1184, 256>>>(q_w, kv_w, proj_w);
    ln_kernel<<<MM, 256>>>(y, ln_g, ln_b);

    int smq = 2*QSTG;   // 71680
    cudaFuncSetAttribute(qkv_fused, cudaFuncAttributeMaxDynamicSharedMemorySize, smq);
    qkv_fused<<<dim3(36, 64), 256, smq>>>(q_b, kv_b);

    int sma = 2*0x8000;
    cudaFuncSetAttribute(attn_mma, cudaFuncAttributeMaxDynamicSharedMemorySize, sma);
    attn_mma<<<dim3(8, 96), 256, sma>>>();

    int smp = 2*STGB;
    cudaFuncSetAttribute(hgemm_proj, cudaFuncAttributeMaxDynamicSharedMemorySize, smp);
    hgemm_proj<<<dim3(6, 64), 256, smp>>>(
        (const __half*)paoh, (const __half*)paol, (const __half*)pp,
        out, proj_b);
}

// round 10
// speedup vs baseline: 5.0407x; 1.2096x over previous
#include <cuda_runtime.h>
#include <cuda_fp16.h>
#include <cstdint>

#define SEQ  1024
#define CC   768
#define NH   12
#define HD   64
#define MM   8192
#define NQKV 2304

// ---------------- scratch (device globals) ----------------------------------
__device__ __half g_x[MM*CC];                     // x f16
__device__ __half g_y[MM*CC];                     // y2 (post-LN) f16
__device__ __half g_w[NQKV*CC];                   // concat(q_w, kv_w) f16
__device__ __half g_p[CC*CC];                     // proj_w f16
__device__ __half g_q[MM*CC];                     // q (x0.125) f16
__device__ __half g_k[MM*CC];                     // k f16
__device__ __half g_v[MM*CC];                     // v f16
__device__ __half g_aoh[MM*CC], g_aol[MM*CC];     // attn out f16 hi/lo

// ---------------- helpers ----------------------------------------------------
__device__ __forceinline__ uint32_t smem_u32(const void* p) {
    uint32_t a;
    asm("{ .reg .u64 t; cvta.to.shared.u64 t, %1; cvt.u32.u64 %0, t; }" : "=r"(a) : "l"(p));
    return a;
}
__device__ __forceinline__ void cpa16(uint32_t s, const void* g) {
    asm volatile("cp.async.cg.shared.global [%0], [%1], 16;" :: "r"(s), "l"(g));
}
__device__ __forceinline__ void cpa_commit() { asm volatile("cp.async.commit_group;"); }
template<int N> __device__ __forceinline__ void cpa_wait() {
    asm volatile("cp.async.wait_group %0;" :: "n"(N));
}
__device__ __forceinline__ void ldsm4(uint32_t& r0, uint32_t& r1, uint32_t& r2, uint32_t& r3,
                                      uint32_t addr) {
    asm volatile("ldmatrix.sync.aligned.m8n8.x4.shared.b16 {%0,%1,%2,%3}, [%4];"
                 : "=r"(r0), "=r"(r1), "=r"(r2), "=r"(r3) : "r"(addr));
}
__device__ __forceinline__ void ldsm4t(uint32_t& r0, uint32_t& r1, uint32_t& r2, uint32_t& r3,
                                       uint32_t addr) {
    asm volatile("ldmatrix.sync.aligned.m8n8.x4.trans.shared.b16 {%0,%1,%2,%3}, [%4];"
                 : "=r"(r0), "=r"(r1), "=r"(r2), "=r"(r3) : "r"(addr));
}
__device__ __forceinline__ void mmaf16(float* c, const uint32_t* a, const uint32_t* b) {
    asm volatile("mma.sync.aligned.m16n8k16.row.col.f32.f16.f16.f32 "
                 "{%0,%1,%2,%3}, {%4,%5,%6,%7}, {%8,%9}, {%0,%1,%2,%3};"
                 : "+f"(c[0]), "+f"(c[1]), "+f"(c[2]), "+f"(c[3])
                 : "r"(a[0]), "r"(a[1]), "r"(a[2]), "r"(a[3]), "r"(b[0]), "r"(b[1]));
}
__device__ __forceinline__ void hsplit(float f, __half& h, __half& l) {
    h = __float2half_rn(f);
    l = __float2half_rn(f - __half2float(h));
}
__device__ __forceinline__ uint32_t h2pack(float a, float b) {
    __half2 h = __floats2half2_rn(a, b);
    return *(uint32_t*)&h;
}
__device__ __forceinline__ float sigmoidf_(float x) { return 1.f/(1.f+__expf(-x)); }
__device__ __forceinline__ uint32_t swzb(int row, int cb) {
    return (uint32_t)(row*128 + ((((cb) >> 4) ^ (row & 7)) << 4));
}

// ---------------------------------------------------------------------------
__global__ void prep_x(const float* __restrict__ x) {
    for (int i = blockIdx.x*blockDim.x + threadIdx.x; i < MM*CC; i += gridDim.x*blockDim.x)
        g_x[i] = __float2half_rn(x[i]);
}
__global__ void prep_w(const float* __restrict__ qw, const float* __restrict__ kvw,
                       const float* __restrict__ pw) {
    const int QW = CC*CC, WCAT = NQKV*CC, TOT = WCAT + CC*CC;
    for (int i = blockIdx.x*blockDim.x + threadIdx.x; i < TOT; i += gridDim.x*blockDim.x) {
        if (i < QW)        g_w[i] = __float2half_rn(qw[i]);
        else if (i < WCAT) g_w[i] = __float2half_rn(kvw[i-QW]);
        else               g_p[i-WCAT] = __float2half_rn(pw[i-WCAT]);
    }
}

__global__ void ln_kernel(const float* __restrict__ y,
                          const float* __restrict__ gam, const float* __restrict__ bet) {
    int m = blockIdx.x, bb = m >> 10, n = m & 1023;
    const float* yp = y + (size_t)bb*CC*SEQ + n;
    float v[3]; float s = 0.f, s2 = 0.f;
#pragma unroll
    for (int i = 0; i < 3; i++) {
        int c = threadIdx.x + i*256;
        float t = yp[(size_t)c*SEQ];
        v[i] = t; s += t; s2 += t*t;
    }
#pragma unroll
    for (int o = 16; o > 0; o >>= 1) {
        s  += __shfl_xor_sync(0xffffffffu, s,  o);
        s2 += __shfl_xor_sync(0xffffffffu, s2, o);
    }
    __shared__ float rb[2][8];
    if ((threadIdx.x & 31) == 0) { rb[0][threadIdx.x>>5] = s; rb[1][threadIdx.x>>5] = s2; }
    __syncthreads();
    float ts = 0.f, ts2 = 0.f;
#pragma unroll
    for (int i = 0; i < 8; i++) { ts += rb[0][i]; ts2 += rb[1][i]; }
    float mean = ts*(1.f/CC), var = ts2*(1.f/CC) - mean*mean;
    float rstd = rsqrtf(var + 1e-5f);
#pragma unroll
    for (int i = 0; i < 3; i++) {
        int c = threadIdx.x + i*256;
        float o = (v[i]-mean)*rstd*gam[c] + bet[c];
        g_y[(size_t)m*CC + c] = __float2half_rn(o);
    }
}

// ---------------------------------------------------------------------------
// FUSED qkv GEMM + gating. Block 128m x 64n (one head). 2 MMA passes per tile
// (x single, y single). smem/stage: x(10240)+y(10240)+w(5120) = 25600.
// ---------------------------------------------------------------------------
#define PITCH 80
#define BUFA  10240
#define BUFW  5120
#define QSTG  (2*BUFA + BUFW)    // 25600

__global__ __launch_bounds__(256, 2)
void qkv_fused(const float* __restrict__ qb, const float* __restrict__ kvb) {
    extern __shared__ __align__(16) char smraw[];
    uint32_t smb = smem_u32(smraw);
    int t = threadIdx.x, lane = t & 31, w = t >> 5;
    int wm = w >> 1, wn = w & 1;
    int bx = blockIdx.x;               // 0..35 (head section)
    int m0 = blockIdx.y * 128;
    int j0 = bx * 64;

    const __half* sx = g_x + (size_t)m0*CC;
    const __half* sy = g_y + (size_t)m0*CC;
    const __half* sw = g_w + (size_t)j0*CC;

    int ra = t >> 2, ca = t & 3;
    int rb2 = (t + 256) >> 2;

    auto load_stage = [&](int s, int k0) {
        uint32_t base = smb + (s & 1)*QSTG;
        cpa16(base + 0*BUFA + ra*PITCH + ca*16,  sx + (size_t)ra*CC  + k0 + ca*8);
        cpa16(base + 0*BUFA + rb2*PITCH + ca*16, sx + (size_t)rb2*CC + k0 + ca*8);
        cpa16(base + 1*BUFA + ra*PITCH + ca*16,  sy + (size_t)ra*CC  + k0 + ca*8);
        cpa16(base + 1*BUFA + rb2*PITCH + ca*16, sy + (size_t)rb2*CC + k0 + ca*8);
        cpa16(base + 2*BUFA + ra*PITCH + ca*16,  sw + (size_t)ra*CC  + k0 + ca*8);
        cpa_commit();
    };

    float accx[2][4][4], accy[2][4][4];
#pragma unroll
    for (int mi = 0; mi < 2; mi++)
#pragma unroll
        for (int ni = 0; ni < 4; ni++)
#pragma unroll
            for (int e = 0; e < 4; e++) { accx[mi][ni][e] = 0.f; accy[mi][ni][e] = 0.f; }

    load_stage(0, 0);

    const int NSTG = CC/32;
    int a_row  = wm*32 + (lane & 15);
    int a_coff = (lane >> 4) * 16;
    int b_row  = (lane & 7) + ((lane >> 1) & 8);
    int b_coff = (lane & 8) * 2;

#pragma unroll 1
    for (int s = 0; s < NSTG; s++) {
        if (s + 1 < NSTG) load_stage(s + 1, (s + 1)*32);
        if (s + 1 < NSTG) cpa_wait<1>(); else cpa_wait<0>();
        __syncthreads();
        uint32_t bX = smb + (s & 1)*QSTG;
        uint32_t bY = bX + BUFA, bW = bX + 2*BUFA;
#pragma unroll
        for (int ks = 0; ks < 2; ks++) {
            int kb = ks*32;
            uint32_t xx[2][4], yy[2][4], bw[4][2];
            ldsm4(xx[0][0], xx[0][1], xx[0][2], xx[0][3], bX + (a_row)*PITCH     + kb + a_coff);
            ldsm4(xx[1][0], xx[1][1], xx[1][2], xx[1][3], bX + (a_row+16)*PITCH + kb + a_coff);
            ldsm4(yy[0][0], yy[0][1], yy[0][2], yy[0][3], bY + (a_row)*PITCH     + kb + a_coff);
            ldsm4(yy[1][0], yy[1][1], yy[1][2], yy[1][3], bY + (a_row+16)*PITCH + kb + a_coff);
#pragma unroll
            for (int p = 0; p < 2; p++) {
                int nr = wn*32 + p*16 + b_row;
                ldsm4(bw[2*p][0], bw[2*p][1], bw[2*p+1][0], bw[2*p+1][1],
                      bW + nr*PITCH + kb + b_coff);
            }
#pragma unroll
            for (int mi = 0; mi < 2; mi++)
#pragma unroll
                for (int ni = 0; ni < 4; ni++) {
                    mmaf16(accx[mi][ni], xx[mi], bw[ni]);
                    mmaf16(accy[mi][ni], yy[mi], bw[ni]);
                }
        }
        __syncthreads();
    }

    // epilogue: gate + direct scatter
    int sec = bx / 12;                // 0=q, 1=k, 2=v
    int h   = bx - sec*12;
#pragma unroll
    for (int mi = 0; mi < 2; mi++) {
#pragma unroll
        for (int e2 = 0; e2 < 2; e2++) {
            int r = m0 + wm*32 + mi*16 + (lane >> 2) + e2*8;
            int bb = r >> 10, n = r & 1023;
            size_t obase = (((size_t)bb*NH + h)*SEQ + n)*HD;
#pragma unroll
            for (int ni = 0; ni < 4; ni++) {
                int d = wn*32 + ni*8 + 2*(lane & 3);
                float ax0 = accx[mi][ni][2*e2], ax1 = accx[mi][ni][2*e2+1];
                float ay0 = accy[mi][ni][2*e2], ay1 = accy[mi][ni][2*e2+1];
                if (sec == 0) {
                    float b0 = qb[j0 + d], b1 = qb[j0 + d + 1];
                    float o0 = 0.125f*(ax0+b0)*(1.f + sigmoidf_(ay0+b0));
                    float o1 = 0.125f*(ax1+b1)*(1.f + sigmoidf_(ay1+b1));
                    *(__half2*)(g_q + obase + d) = __floats2half2_rn(o0, o1);
                } else {
                    float b0 = kvb[j0 - CC + d], b1 = kvb[j0 - CC + d + 1];
                    float o0 = sigmoidf_(ay0+b0)*(ax0+b0+1.f);
                    float o1 = sigmoidf_(ay1+b1)*(ax1+b1+1.f);
                    __half* dst = (sec == 1) ? g_k : g_v;
                    *(__half2*)(dst + obase + d) = __floats2half2_rn(o0, o1);
                }
            }
        }
    }
}

// ---------------------------------------------------------------------------
// proj GEMM (A hi/lo 2-pass, unchanged). Block 128x128.
// ---------------------------------------------------------------------------
#define BUFB  10240
#define STGB  (3*BUFB)

__global__ __launch_bounds__(256, 2)
void hgemm_proj(const __half* __restrict__ Ah, const __half* __restrict__ Al,
                const __half* __restrict__ W,
                float* __restrict__ C, const float* __restrict__ bias) {
    extern __shared__ __align__(16) char smraw[];
    uint32_t smb = smem_u32(smraw);
    int t = threadIdx.x, lane = t & 31, w = t >> 5;
    int wm = w >> 1, wn = w & 1;
    int am0 = blockIdx.y * 128, wn0 = blockIdx.x * 128;

    const __half* srcs[3] = { Ah + (size_t)am0*CC, Al + (size_t)am0*CC, W + (size_t)wn0*CC };
    int r0 = t >> 2, c0 = t & 3;
    int r1 = (t + 256) >> 2;

    auto load_stage = [&](int s, int k0) {
        uint32_t base = smb + (s & 1)*STGB;
#pragma unroll
        for (int b = 0; b < 3; b++) {
            cpa16(base + b*BUFB + r0*PITCH + c0*16, srcs[b] + (size_t)r0*CC + k0 + c0*8);
            cpa16(base + b*BUFB + r1*PITCH + c0*16, srcs[b] + (size_t)r1*CC + k0 + c0*8);
        }
        cpa_commit();
    };

    float acc[2][8][4];
#pragma unroll
    for (int mi = 0; mi < 2; mi++)
#pragma unroll
        for (int ni = 0; ni < 8; ni++)
#pragma unroll
            for (int e = 0; e < 4; e++) acc[mi][ni][e] = 0.f;

    load_stage(0, 0);

    const int NSTG = CC/32;
    int a_row  = wm*32 + (lane & 15);
    int a_coff = (lane >> 4) * 16;
    int b_row  = (lane & 7) + ((lane >> 1) & 8);
    int b_coff = (lane & 8) * 2;

#pragma unroll 1
    for (int s = 0; s < NSTG; s++) {
        if (s + 1 < NSTG) load_stage(s + 1, (s + 1)*32);
        if (s + 1 < NSTG) cpa_wait<1>(); else cpa_wait<0>();
        __syncthreads();
        uint32_t bAh = smb + (s & 1)*STGB;
        uint32_t bAl = bAh + BUFB, bW = bAh + 2*BUFB;
#pragma unroll
        for (int ks = 0; ks < 2; ks++) {
            int kb = ks*32;
            uint32_t ah[2][4], al[2][4], bw[8][2];
            ldsm4(ah[0][0], ah[0][1], ah[0][2], ah[0][3], bAh + (a_row)*PITCH     + kb + a_coff);
            ldsm4(ah[1][0], ah[1][1], ah[1][2], ah[1][3], bAh + (a_row+16)*PITCH + kb + a_coff);
            ldsm4(al[0][0], al[0][1], al[0][2], al[0][3], bAl + (a_row)*PITCH     + kb + a_coff);
            ldsm4(al[1][0], al[1][1], al[1][2], al[1][3], bAl + (a_row+16)*PITCH + kb + a_coff);
#pragma unroll
            for (int p = 0; p < 4; p++) {
                int nr = wn*64 + p*16 + b_row;
                ldsm4(bw[2*p][0], bw[2*p][1], bw[2*p+1][0], bw[2*p+1][1],
                      bW + nr*PITCH + kb + b_coff);
            }
#pragma unroll
            for (int mi = 0; mi < 2; mi++)
#pragma unroll
                for (int ni = 0; ni < 8; ni++) {
                    mmaf16(acc[mi][ni], ah[mi], bw[ni]);
                    mmaf16(acc[mi][ni], al[mi], bw[ni]);
                }
        }
        __syncthreads();
    }

#pragma unroll
    for (int mi = 0; mi < 2; mi++) {
        int row = am0 + wm*32 + mi*16 + (lane >> 2);
#pragma unroll
        for (int ni = 0; ni < 8; ni++) {
            int col = wn0 + wn*64 + ni*8 + 2*(lane & 3);
            float b0 = bias[col], b1 = bias[col+1];
            *(float2*)(C + (size_t)row*CC + col)     = make_float2(acc[mi][ni][0]+b0, acc[mi][ni][1]+b1);
            *(float2*)(C + (size_t)(row+8)*CC + col) = make_float2(acc[mi][ni][2]+b0, acc[mi][ni][3]+b1);
        }
    }
}

// ---------------------------------------------------------------------------
// TC flash attention: Q single f16 now (1-pass QK^T).
// smem: Q 16KB staged; 2 stages x 32KB KV.
// ---------------------------------------------------------------------------
__global__ __launch_bounds__(256, 1)
void attn_mma() {
    extern __shared__ __align__(16) char smraw[];
    uint32_t smb = smem_u32(smraw);
    int qt = blockIdx.x, bh = blockIdx.y;
    int t = threadIdx.x, lane = t & 31, w = t >> 5;
    const __half* qp = g_q + (size_t)bh*SEQ*HD + (size_t)qt*128*HD;
    const __half* kp = g_k + (size_t)bh*SEQ*HD;
    const __half* vp = g_v + (size_t)bh*SEQ*HD;

#pragma unroll
    for (int i = 0; i < 4; i++) {
        int c = t + i*256;
        int row = c >> 3, ch = c & 7;
        cpa16(smb + swzb(row, ch*16), qp + (size_t)row*HD + ch*8);
    }
    cpa_commit();

    auto load_kv = [&](int kt, int stage) {
        uint32_t base = smb + stage*0x8000;
#pragma unroll
        for (int i = 0; i < 4; i++) {
            int c = t + i*256;
            int row = c >> 3, ch = c & 7;
            uint32_t off = swzb(row, ch*16);
            const size_t go = (size_t)(kt*128 + row)*HD + ch*8;
            cpa16(base + 0x0000 + off, kp + go);
            cpa16(base + 0x4000 + off, vp + go);
        }
        cpa_commit();
    };

    load_kv(0, 1);
    cpa_wait<1>();
    __syncthreads();

    uint32_t qf[4][4];
    int arow = w*16 + (lane & 15);
    int acb0 = (lane >> 4) << 4;
#pragma unroll
    for (int ks = 0; ks < 4; ks++) {
        uint32_t off = swzb(arow, ks*32 + acb0);
        ldsm4(qf[ks][0], qf[ks][1], qf[ks][2], qf[ks][3], smb + off);
    }
    __syncthreads();
    load_kv(1, 0);

    float O[8][4];
#pragma unroll
    for (int nd = 0; nd < 8; nd++)
#pragma unroll
        for (int e = 0; e < 4; e++) O[nd][e] = 0.f;
    float m0 = -1e30f, m1 = -1e30f, l0 = 0.f, l1 = 0.f;

    int krow_b = (lane & 7) + ((lane >> 1) & 8);
    int kcb_b  = (lane & 8) << 1;
    int vrow_b = lane & 15;
    int vcb_b  = (lane >> 4) << 4;

#pragma unroll 1
    for (int kt = 0; kt < 8; kt++) {
        if (kt == 7) cpa_wait<0>(); else cpa_wait<1>();
        __syncthreads();
        uint32_t base = smb + ((kt + 1) & 1)*0x8000;
        uint32_t bK = base, bV = base + 0x4000;

        float sc[16][4];
#pragma unroll
        for (int jj = 0; jj < 16; jj++)
#pragma unroll
            for (int e = 0; e < 4; e++) sc[jj][e] = 0.f;
#pragma unroll
        for (int ks = 0; ks < 4; ks++) {
#pragma unroll
            for (int p = 0; p < 8; p++) {
                uint32_t k4[4];
                int krow = 16*p + krow_b;
                ldsm4(k4[0], k4[1], k4[2], k4[3], bK + swzb(krow, ks*32 + kcb_b));
                mmaf16(sc[2*p],   qf[ks], k4+0);
                mmaf16(sc[2*p+1], qf[ks], k4+2);
            }
        }

        float rm0 = -1e30f, rm1 = -1e30f;
#pragma unroll
        for (int jj = 0; jj < 16; jj++) {
            rm0 = fmaxf(rm0, fmaxf(sc[jj][0], sc[jj][1]));
            rm1 = fmaxf(rm1, fmaxf(sc[jj][2], sc[jj][3]));
        }
        rm0 = fmaxf(rm0, __shfl_xor_sync(0xffffffffu, rm0, 1));
        rm0 = fmaxf(rm0, __shfl_xor_sync(0xffffffffu, rm0, 2));
        rm1 = fmaxf(rm1, __shfl_xor_sync(0xffffffffu, rm1, 1));
        rm1 = fmaxf(rm1, __shfl_xor_sync(0xffffffffu, rm1, 2));
        float mn0 = fmaxf(m0, rm0), mn1 = fmaxf(m1, rm1);
        float a0 = __expf(m0 - mn0), a1 = __expf(m1 - mn1);
        float rs0 = 0.f, rs1 = 0.f;
#pragma unroll
        for (int jj = 0; jj < 16; jj++) {
            sc[jj][0] = __expf(sc[jj][0] - mn0);
            sc[jj][1] = __expf(sc[jj][1] - mn0);
            sc[jj][2] = __expf(sc[jj][2] - mn1);
            sc[jj][3] = __expf(sc[jj][3] - mn1);
            rs0 += sc[jj][0] + sc[jj][1];
            rs1 += sc[jj][2] + sc[jj][3];
        }
        rs0 += __shfl_xor_sync(0xffffffffu, rs0, 1);
        rs0 += __shfl_xor_sync(0xffffffffu, rs0, 2);
        rs1 += __shfl_xor_sync(0xffffffffu, rs1, 1);
        rs1 += __shfl_xor_sync(0xffffffffu, rs1, 2);
        l0 = l0*a0 + rs0; l1 = l1*a1 + rs1;
        m0 = mn0; m1 = mn1;
#pragma unroll
        for (int nd = 0; nd < 8; nd++) {
            O[nd][0] *= a0; O[nd][1] *= a0;
            O[nd][2] *= a1; O[nd][3] *= a1;
        }

        uint32_t pf[8][4];
#pragma unroll
        for (int jj = 0; jj < 8; jj++) {
            pf[jj][0] = h2pack(sc[2*jj][0],   sc[2*jj][1]);
            pf[jj][1] = h2pack(sc[2*jj][2],   sc[2*jj][3]);
            pf[jj][2] = h2pack(sc[2*jj+1][0], sc[2*jj+1][1]);
            pf[jj][3] = h2pack(sc[2*jj+1][2], sc[2*jj+1][3]);
        }

#pragma unroll
        for (int ks2 = 0; ks2 < 8; ks2++) {
#pragma unroll
            for (int pp = 0; pp < 4; pp++) {
                uint32_t v4[4];
                int vrow = ks2*16 + vrow_b;
                ldsm4t(v4[0], v4[1], v4[2], v4[3], bV + swzb(vrow, pp*32 + vcb_b));
                mmaf16(O[2*pp],   pf[ks2], v4+0);
                mmaf16(O[2*pp+1], pf[ks2], v4+2);
            }
        }
        __syncthreads();
        if (kt + 2 < 8) load_kv(kt + 2, (kt + 1) & 1);
    }

    float inv0 = 1.f / l0, inv1 = 1.f / l1;
    int g = lane >> 2, t2 = (lane & 3)*2;
    int bb = bh / NH, h = bh - bb*NH;
    int n0 = qt*128 + w*16 + g;
#pragma unroll
    for (int nd = 0; nd < 8; nd++) {
        int col = h*64 + nd*8 + t2;
        size_t o0 = ((size_t)bb*SEQ + n0)*CC + col;
        size_t o1 = ((size_t)bb*SEQ + n0 + 8)*CC + col;
        __half h0,l0b,h1,l1b,h2v,l2,h3,l3;
        hsplit(O[nd][0]*inv0, h0, l0b); hsplit(O[nd][1]*inv0, h1, l1b);
        hsplit(O[nd][2]*inv1, h2v, l2); hsplit(O[nd][3]*inv1, h3, l3);
        *(__half2*)(g_aoh + o0) = __half2(h0,h1);
        *(__half2*)(g_aol + o0) = __half2(l0b,l1b);
        *(__half2*)(g_aoh + o1) = __half2(h2v,h3);
        *(__half2*)(g_aol + o1) = __half2(l2,l3);
    }
}

// ---------------------------------------------------------------------------
extern "C" void kernel_launch(void* const* d_in, const int* in_sizes, int n_in,
                              void* d_out, int out_size) {
    const float* x      = (const float*)d_in[0];
    const float* y      = (const float*)d_in[1];
    const float* q_w    = (const float*)d_in[2];
    const float* q_b    = (const float*)d_in[3];
    const float* kv_w   = (const float*)d_in[4];
    const float* kv_b   = (const float*)d_in[5];
    const float* proj_w = (const float*)d_in[6];
    const float* proj_b = (const float*)d_in[7];
    const float* ln_g   = (const float*)d_in[8];
    const float* ln_b   = (const float*)d_in[9];
    float* out = (float*)d_out;

    void *paoh, *paol, *pp;
    cudaGetSymbolAddress(&paoh, g_aoh);
    cudaGetSymbolAddress(&paol, g_aol);
    cudaGetSymbolAddress(&pp,   g_p);

    prep_x<<<1184, 256>>>(x);
    prep_w<<<1184, 256>>>(q_w, kv_w, proj_w);
    ln_kernel<<<MM, 256>>>(y, ln_g, ln_b);

    int smq = 2*QSTG;   // 51200
    cudaFuncSetAttribute(qkv_fused, cudaFuncAttributeMaxDynamicSharedMemorySize, smq);
    qkv_fused<<<dim3(36, 64), 256, smq>>>(q_b, kv_b);

    int sma = 2*0x8000 + 0x4000;   // Q(16K) + 2 KV stages... Q lives in stage area before loop
    // NOTE: Q staged at smb overlaps stage0 KV region only before load_kv(1,0);
    // Q frags are in regs by then. 2*0x8000 is sufficient.
    sma = 2*0x8000;
    cudaFuncSetAttribute(attn_mma, cudaFuncAttributeMaxDynamicSharedMemorySize, sma);
    attn_mma<<<dim3(8, 96), 256, sma>>>();

    int smp = 2*STGB;
    cudaFuncSetAttribute(hgemm_proj, cudaFuncAttributeMaxDynamicSharedMemorySize, smp);
    hgemm_proj<<<dim3(6, 64), 256, smp>>>(
        (const __half*)paoh, (const __half*)paol, (const __half*)pp,
        out, proj_b);
}

// round 11
// speedup vs baseline: 5.5188x; 1.0948x over previous
#include <cuda_runtime.h>
#include <cuda_fp16.h>
#include <cstdint>

#define SEQ  1024
#define CC   768
#define NH   12
#define HD   64
#define MM   8192
#define NQKV 2304

// ---------------- scratch (device globals) ----------------------------------
__device__ __half g_x[MM*CC];                     // x f16
__device__ __half g_y[MM*CC];                     // y2 (post-LN) f16
__device__ __half g_w[NQKV*CC];                   // concat(q_w, kv_w) f16
__device__ __half g_p[CC*CC];                     // proj_w f16
__device__ __half g_q[MM*CC];                     // q (x0.125) f16
__device__ __half g_k[MM*CC];                     // k f16
__device__ __half g_v[MM*CC];                     // v f16
__device__ __half g_aoh[MM*CC], g_aol[MM*CC];     // attn out f16 hi/lo

// ---------------- helpers ----------------------------------------------------
__device__ __forceinline__ uint32_t smem_u32(const void* p) {
    uint32_t a;
    asm("{ .reg .u64 t; cvta.to.shared.u64 t, %1; cvt.u32.u64 %0, t; }" : "=r"(a) : "l"(p));
    return a;
}
__device__ __forceinline__ void cpa16(uint32_t s, const void* g) {
    asm volatile("cp.async.cg.shared.global [%0], [%1], 16;" :: "r"(s), "l"(g));
}
__device__ __forceinline__ void cpa_commit() { asm volatile("cp.async.commit_group;"); }
template<int N> __device__ __forceinline__ void cpa_wait() {
    asm volatile("cp.async.wait_group %0;" :: "n"(N));
}
__device__ __forceinline__ void ldsm4(uint32_t& r0, uint32_t& r1, uint32_t& r2, uint32_t& r3,
                                      uint32_t addr) {
    asm volatile("ldmatrix.sync.aligned.m8n8.x4.shared.b16 {%0,%1,%2,%3}, [%4];"
                 : "=r"(r0), "=r"(r1), "=r"(r2), "=r"(r3) : "r"(addr));
}
__device__ __forceinline__ void ldsm4t(uint32_t& r0, uint32_t& r1, uint32_t& r2, uint32_t& r3,
                                       uint32_t addr) {
    asm volatile("ldmatrix.sync.aligned.m8n8.x4.trans.shared.b16 {%0,%1,%2,%3}, [%4];"
                 : "=r"(r0), "=r"(r1), "=r"(r2), "=r"(r3) : "r"(addr));
}
__device__ __forceinline__ void mmaf16(float* c, const uint32_t* a, const uint32_t* b) {
    asm volatile("mma.sync.aligned.m16n8k16.row.col.f32.f16.f16.f32 "
                 "{%0,%1,%2,%3}, {%4,%5,%6,%7}, {%8,%9}, {%0,%1,%2,%3};"
                 : "+f"(c[0]), "+f"(c[1]), "+f"(c[2]), "+f"(c[3])
                 : "r"(a[0]), "r"(a[1]), "r"(a[2]), "r"(a[3]), "r"(b[0]), "r"(b[1]));
}
__device__ __forceinline__ void hsplit(float f, __half& h, __half& l) {
    h = __float2half_rn(f);
    l = __float2half_rn(f - __half2float(h));
}
__device__ __forceinline__ uint32_t h2pack(float a, float b) {
    __half2 h = __floats2half2_rn(a, b);
    return *(uint32_t*)&h;
}
__device__ __forceinline__ float sigmoidf_(float x) { return 1.f/(1.f+__expf(-x)); }
__device__ __forceinline__ uint32_t swzb(int row, int cb) {
    return (uint32_t)(row*128 + ((((cb) >> 4) ^ (row & 7)) << 4));
}

// ---------------------------------------------------------------------------
// merged prep: x, q_w, kv_w, proj_w -> f16
// ---------------------------------------------------------------------------
__global__ void prep_all(const float* __restrict__ x, const float* __restrict__ qw,
                         const float* __restrict__ kvw, const float* __restrict__ pw) {
    const int NX = MM*CC, QW = CC*CC, KVW = 2*CC*CC, PW = CC*CC;
    const int T0 = NX, T1 = NX + QW, T2 = T1 + KVW, TOT = T2 + PW;
    for (int i = blockIdx.x*blockDim.x + threadIdx.x; i < TOT; i += gridDim.x*blockDim.x) {
        if (i < T0)      g_x[i] = __float2half_rn(x[i]);
        else if (i < T1) g_w[i - T0] = __float2half_rn(qw[i - T0]);
        else if (i < T2) g_w[i - T0] = __float2half_rn(kvw[i - T1]);
        else             g_p[i - T2] = __float2half_rn(pw[i - T2]);
    }
}

__global__ void ln_kernel(const float* __restrict__ y,
                          const float* __restrict__ gam, const float* __restrict__ bet) {
    int m = blockIdx.x, bb = m >> 10, n = m & 1023;
    const float* yp = y + (size_t)bb*CC*SEQ + n;
    float v[3]; float s = 0.f, s2 = 0.f;
#pragma unroll
    for (int i = 0; i < 3; i++) {
        int c = threadIdx.x + i*256;
        float t = yp[(size_t)c*SEQ];
        v[i] = t; s += t; s2 += t*t;
    }
#pragma unroll
    for (int o = 16; o > 0; o >>= 1) {
        s  += __shfl_xor_sync(0xffffffffu, s,  o);
        s2 += __shfl_xor_sync(0xffffffffu, s2, o);
    }
    __shared__ float rb[2][8];
    if ((threadIdx.x & 31) == 0) { rb[0][threadIdx.x>>5] = s; rb[1][threadIdx.x>>5] = s2; }
    __syncthreads();
    float ts = 0.f, ts2 = 0.f;
#pragma unroll
    for (int i = 0; i < 8; i++) { ts += rb[0][i]; ts2 += rb[1][i]; }
    float mean = ts*(1.f/CC), var = ts2*(1.f/CC) - mean*mean;
    float rstd = rsqrtf(var + 1e-5f);
#pragma unroll
    for (int i = 0; i < 3; i++) {
        int c = threadIdx.x + i*256;
        float o = (v[i]-mean)*rstd*gam[c] + bet[c];
        g_y[(size_t)m*CC + c] = __float2half_rn(o);
    }
}

// ---------------------------------------------------------------------------
// FUSED qkv GEMM + gating. Block 128m x 64n (one head). K staged 64 now
// (12 stages, half the barriers). Pitch 144B keeps ldsm conflict-free.
// smem/stage: x(18432)+y(18432)+w(9216) = 46080; x2 stages = 92160.
// ---------------------------------------------------------------------------
#define PITCH2 144
#define BUFX  18432
#define BUFW2 9216
#define QSTG  (2*BUFX + BUFW2)   // 46080

__global__ __launch_bounds__(256, 2)
void qkv_fused(const float* __restrict__ qb, const float* __restrict__ kvb) {
    extern __shared__ __align__(16) char smraw[];
    uint32_t smb = smem_u32(smraw);
    int t = threadIdx.x, lane = t & 31, w = t >> 5;
    int wm = w >> 1, wn = w & 1;
    int bx = blockIdx.x;               // 0..35 (head section)
    int m0 = blockIdx.y * 128;
    int j0 = bx * 64;

    const __half* sx = g_x + (size_t)m0*CC;
    const __half* sy = g_y + (size_t)m0*CC;
    const __half* sw = g_w + (size_t)j0*CC;

    auto load_stage = [&](int s, int k0) {
        uint32_t base = smb + (s & 1)*QSTG;
#pragma unroll
        for (int i = 0; i < 4; i++) {                 // x and y tiles: 1024 chunks each
            int c = t + i*256;
            int row = c >> 3, ch = c & 7;
            cpa16(base + row*PITCH2 + ch*16,          sx + (size_t)row*CC + k0 + ch*8);
            cpa16(base + BUFX + row*PITCH2 + ch*16,   sy + (size_t)row*CC + k0 + ch*8);
        }
#pragma unroll
        for (int i = 0; i < 2; i++) {                 // w tile: 512 chunks
            int c = t + i*256;
            int row = c >> 3, ch = c & 7;
            cpa16(base + 2*BUFX + row*PITCH2 + ch*16, sw + (size_t)row*CC + k0 + ch*8);
        }
        cpa_commit();
    };

    float accx[2][4][4], accy[2][4][4];
#pragma unroll
    for (int mi = 0; mi < 2; mi++)
#pragma unroll
        for (int ni = 0; ni < 4; ni++)
#pragma unroll
            for (int e = 0; e < 4; e++) { accx[mi][ni][e] = 0.f; accy[mi][ni][e] = 0.f; }

    load_stage(0, 0);

    const int NSTG = CC/64;   // 12
    int a_row  = wm*32 + (lane & 15);
    int a_coff = (lane >> 4) * 16;
    int b_row  = (lane & 7) + ((lane >> 1) & 8);
    int b_coff = (lane & 8) * 2;

#pragma unroll 1
    for (int s = 0; s < NSTG; s++) {
        if (s + 1 < NSTG) load_stage(s + 1, (s + 1)*64);
        if (s + 1 < NSTG) cpa_wait<1>(); else cpa_wait<0>();
        __syncthreads();
        uint32_t bX = smb + (s & 1)*QSTG;
        uint32_t bY = bX + BUFX, bW = bX + 2*BUFX;
#pragma unroll
        for (int ks = 0; ks < 4; ks++) {
            int kb = ks*32;
            uint32_t xx[2][4], yy[2][4], bw[4][2];
            ldsm4(xx[0][0], xx[0][1], xx[0][2], xx[0][3], bX + (a_row)*PITCH2     + kb + a_coff);
            ldsm4(xx[1][0], xx[1][1], xx[1][2], xx[1][3], bX + (a_row+16)*PITCH2 + kb + a_coff);
            ldsm4(yy[0][0], yy[0][1], yy[0][2], yy[0][3], bY + (a_row)*PITCH2     + kb + a_coff);
            ldsm4(yy[1][0], yy[1][1], yy[1][2], yy[1][3], bY + (a_row+16)*PITCH2 + kb + a_coff);
#pragma unroll
            for (int p = 0; p < 2; p++) {
                int nr = wn*32 + p*16 + b_row;
                ldsm4(bw[2*p][0], bw[2*p][1], bw[2*p+1][0], bw[2*p+1][1],
                      bW + nr*PITCH2 + kb + b_coff);
            }
#pragma unroll
            for (int mi = 0; mi < 2; mi++)
#pragma unroll
                for (int ni = 0; ni < 4; ni++) {
                    mmaf16(accx[mi][ni], xx[mi], bw[ni]);
                    mmaf16(accy[mi][ni], yy[mi], bw[ni]);
                }
        }
        __syncthreads();
    }

    // epilogue: gate + direct scatter
    int sec = bx / 12;                // 0=q, 1=k, 2=v
    int h   = bx - sec*12;
#pragma unroll
    for (int mi = 0; mi < 2; mi++) {
#pragma unroll
        for (int e2 = 0; e2 < 2; e2++) {
            int r = m0 + wm*32 + mi*16 + (lane >> 2) + e2*8;
            int bb = r >> 10, n = r & 1023;
            size_t obase = (((size_t)bb*NH + h)*SEQ + n)*HD;
#pragma unroll
            for (int ni = 0; ni < 4; ni++) {
                int d = wn*32 + ni*8 + 2*(lane & 3);
                float ax0 = accx[mi][ni][2*e2], ax1 = accx[mi][ni][2*e2+1];
                float ay0 = accy[mi][ni][2*e2], ay1 = accy[mi][ni][2*e2+1];
                if (sec == 0) {
                    float b0 = qb[j0 + d], b1 = qb[j0 + d + 1];
                    float o0 = 0.125f*(ax0+b0)*(1.f + sigmoidf_(ay0+b0));
                    float o1 = 0.125f*(ax1+b1)*(1.f + sigmoidf_(ay1+b1));
                    *(__half2*)(g_q + obase + d) = __floats2half2_rn(o0, o1);
                } else {
                    float b0 = kvb[j0 - CC + d], b1 = kvb[j0 - CC + d + 1];
                    float o0 = sigmoidf_(ay0+b0)*(ax0+b0+1.f);
                    float o1 = sigmoidf_(ay1+b1)*(ax1+b1+1.f);
                    __half* dst = (sec == 1) ? g_k : g_v;
                    *(__half2*)(dst + obase + d) = __floats2half2_rn(o0, o1);
                }
            }
        }
    }
}

// ---------------------------------------------------------------------------
// proj GEMM (A hi/lo 2-pass, unchanged). Block 128x128, K staged 32.
// ---------------------------------------------------------------------------
#define PITCH 80
#define BUFB  10240
#define STGB  (3*BUFB)

__global__ __launch_bounds__(256, 2)
void hgemm_proj(const __half* __restrict__ Ah, const __half* __restrict__ Al,
                const __half* __restrict__ W,
                float* __restrict__ C, const float* __restrict__ bias) {
    extern __shared__ __align__(16) char smraw[];
    uint32_t smb = smem_u32(smraw);
    int t = threadIdx.x, lane = t & 31, w = t >> 5;
    int wm = w >> 1, wn = w & 1;
    int am0 = blockIdx.y * 128, wn0 = blockIdx.x * 128;

    const __half* srcs[3] = { Ah + (size_t)am0*CC, Al + (size_t)am0*CC, W + (size_t)wn0*CC };
    int r0 = t >> 2, c0 = t & 3;
    int r1 = (t + 256) >> 2;

    auto load_stage = [&](int s, int k0) {
        uint32_t base = smb + (s & 1)*STGB;
#pragma unroll
        for (int b = 0; b < 3; b++) {
            cpa16(base + b*BUFB + r0*PITCH + c0*16, srcs[b] + (size_t)r0*CC + k0 + c0*8);
            cpa16(base + b*BUFB + r1*PITCH + c0*16, srcs[b] + (size_t)r1*CC + k0 + c0*8);
        }
        cpa_commit();
    };

    float acc[2][8][4];
#pragma unroll
    for (int mi = 0; mi < 2; mi++)
#pragma unroll
        for (int ni = 0; ni < 8; ni++)
#pragma unroll
            for (int e = 0; e < 4; e++) acc[mi][ni][e] = 0.f;

    load_stage(0, 0);

    const int NSTG = CC/32;
    int a_row  = wm*32 + (lane & 15);
    int a_coff = (lane >> 4) * 16;
    int b_row  = (lane & 7) + ((lane >> 1) & 8);
    int b_coff = (lane & 8) * 2;

#pragma unroll 1
    for (int s = 0; s < NSTG; s++) {
        if (s + 1 < NSTG) load_stage(s + 1, (s + 1)*32);
        if (s + 1 < NSTG) cpa_wait<1>(); else cpa_wait<0>();
        __syncthreads();
        uint32_t bAh = smb + (s & 1)*STGB;
        uint32_t bAl = bAh + BUFB, bW = bAh + 2*BUFB;
#pragma unroll
        for (int ks = 0; ks < 2; ks++) {
            int kb = ks*32;
            uint32_t ah[2][4], al[2][4], bw[8][2];
            ldsm4(ah[0][0], ah[0][1], ah[0][2], ah[0][3], bAh + (a_row)*PITCH     + kb + a_coff);
            ldsm4(ah[1][0], ah[1][1], ah[1][2], ah[1][3], bAh + (a_row+16)*PITCH + kb + a_coff);
            ldsm4(al[0][0], al[0][1], al[0][2], al[0][3], bAl + (a_row)*PITCH     + kb + a_coff);
            ldsm4(al[1][0], al[1][1], al[1][2], al[1][3], bAl + (a_row+16)*PITCH + kb + a_coff);
#pragma unroll
            for (int p = 0; p < 4; p++) {
                int nr = wn*64 + p*16 + b_row;
                ldsm4(bw[2*p][0], bw[2*p][1], bw[2*p+1][0], bw[2*p+1][1],
                      bW + nr*PITCH + kb + b_coff);
            }
#pragma unroll
            for (int mi = 0; mi < 2; mi++)
#pragma unroll
                for (int ni = 0; ni < 8; ni++) {
                    mmaf16(acc[mi][ni], ah[mi], bw[ni]);
                    mmaf16(acc[mi][ni], al[mi], bw[ni]);
                }
        }
        __syncthreads();
    }

#pragma unroll
    for (int mi = 0; mi < 2; mi++) {
        int row = am0 + wm*32 + mi*16 + (lane >> 2);
#pragma unroll
        for (int ni = 0; ni < 8; ni++) {
            int col = wn0 + wn*64 + ni*8 + 2*(lane & 3);
            float b0 = bias[col], b1 = bias[col+1];
            *(float2*)(C + (size_t)row*CC + col)     = make_float2(acc[mi][ni][0]+b0, acc[mi][ni][1]+b1);
            *(float2*)(C + (size_t)(row+8)*CC + col) = make_float2(acc[mi][ni][2]+b0, acc[mi][ni][3]+b1);
        }
    }
}

// ---------------------------------------------------------------------------
// TC flash attention (unchanged from R10): Q single f16, 1-pass QK^T.
// ---------------------------------------------------------------------------
__global__ __launch_bounds__(256, 1)
void attn_mma() {
    extern __shared__ __align__(16) char smraw[];
    uint32_t smb = smem_u32(smraw);
    int qt = blockIdx.x, bh = blockIdx.y;
    int t = threadIdx.x, lane = t & 31, w = t >> 5;
    const __half* qp = g_q + (size_t)bh*SEQ*HD + (size_t)qt*128*HD;
    const __half* kp = g_k + (size_t)bh*SEQ*HD;
    const __half* vp = g_v + (size_t)bh*SEQ*HD;

#pragma unroll
    for (int i = 0; i < 4; i++) {
        int c = t + i*256;
        int row = c >> 3, ch = c & 7;
        cpa16(smb + swzb(row, ch*16), qp + (size_t)row*HD + ch*8);
    }
    cpa_commit();

    auto load_kv = [&](int kt, int stage) {
        uint32_t base = smb + stage*0x8000;
#pragma unroll
        for (int i = 0; i < 4; i++) {
            int c = t + i*256;
            int row = c >> 3, ch = c & 7;
            uint32_t off = swzb(row, ch*16);
            const size_t go = (size_t)(kt*128 + row)*HD + ch*8;
            cpa16(base + 0x0000 + off, kp + go);
            cpa16(base + 0x4000 + off, vp + go);
        }
        cpa_commit();
    };

    load_kv(0, 1);
    cpa_wait<1>();
    __syncthreads();

    uint32_t qf[4][4];
    int arow = w*16 + (lane & 15);
    int acb0 = (lane >> 4) << 4;
#pragma unroll
    for (int ks = 0; ks < 4; ks++) {
        uint32_t off = swzb(arow, ks*32 + acb0);
        ldsm4(qf[ks][0], qf[ks][1], qf[ks][2], qf[ks][3], smb + off);
    }
    __syncthreads();
    load_kv(1, 0);

    float O[8][4];
#pragma unroll
    for (int nd = 0; nd < 8; nd++)
#pragma unroll
        for (int e = 0; e < 4; e++) O[nd][e] = 0.f;
    float m0 = -1e30f, m1 = -1e30f, l0 = 0.f, l1 = 0.f;

    int krow_b = (lane & 7) + ((lane >> 1) & 8);
    int kcb_b  = (lane & 8) << 1;
    int vrow_b = lane & 15;
    int vcb_b  = (lane >> 4) << 4;

#pragma unroll 1
    for (int kt = 0; kt < 8; kt++) {
        if (kt == 7) cpa_wait<0>(); else cpa_wait<1>();
        __syncthreads();
        uint32_t base = smb + ((kt + 1) & 1)*0x8000;
        uint32_t bK = base, bV = base + 0x4000;

        float sc[16][4];
#pragma unroll
        for (int jj = 0; jj < 16; jj++)
#pragma unroll
            for (int e = 0; e < 4; e++) sc[jj][e] = 0.f;
#pragma unroll
        for (int ks = 0; ks < 4; ks++) {
#pragma unroll
            for (int p = 0; p < 8; p++) {
                uint32_t k4[4];
                int krow = 16*p + krow_b;
                ldsm4(k4[0], k4[1], k4[2], k4[3], bK + swzb(krow, ks*32 + kcb_b));
                mmaf16(sc[2*p],   qf[ks], k4+0);
                mmaf16(sc[2*p+1], qf[ks], k4+2);
            }
        }

        float rm0 = -1e30f, rm1 = -1e30f;
#pragma unroll
        for (int jj = 0; jj < 16; jj++) {
            rm0 = fmaxf(rm0, fmaxf(sc[jj][0], sc[jj][1]));
            rm1 = fmaxf(rm1, fmaxf(sc[jj][2], sc[jj][3]));
        }
        rm0 = fmaxf(rm0, __shfl_xor_sync(0xffffffffu, rm0, 1));
        rm0 = fmaxf(rm0, __shfl_xor_sync(0xffffffffu, rm0, 2));
        rm1 = fmaxf(rm1, __shfl_xor_sync(0xffffffffu, rm1, 1));
        rm1 = fmaxf(rm1, __shfl_xor_sync(0xffffffffu, rm1, 2));
        float mn0 = fmaxf(m0, rm0), mn1 = fmaxf(m1, rm1);
        float a0 = __expf(m0 - mn0), a1 = __expf(m1 - mn1);
        float rs0 = 0.f, rs1 = 0.f;
#pragma unroll
        for (int jj = 0; jj < 16; jj++) {
            sc[jj][0] = __expf(sc[jj][0] - mn0);
            sc[jj][1] = __expf(sc[jj][1] - mn0);
            sc[jj][2] = __expf(sc[jj][2] - mn1);
            sc[jj][3] = __expf(sc[jj][3] - mn1);
            rs0 += sc[jj][0] + sc[jj][1];
            rs1 += sc[jj][2] + sc[jj][3];
        }
        rs0 += __shfl_xor_sync(0xffffffffu, rs0, 1);
        rs0 += __shfl_xor_sync(0xffffffffu, rs0, 2);
        rs1 += __shfl_xor_sync(0xffffffffu, rs1, 1);
        rs1 += __shfl_xor_sync(0xffffffffu, rs1, 2);
        l0 = l0*a0 + rs0; l1 = l1*a1 + rs1;
        m0 = mn0; m1 = mn1;
#pragma unroll
        for (int nd = 0; nd < 8; nd++) {
            O[nd][0] *= a0; O[nd][1] *= a0;
            O[nd][2] *= a1; O[nd][3] *= a1;
        }

        uint32_t pf[8][4];
#pragma unroll
        for (int jj = 0; jj < 8; jj++) {
            pf[jj][0] = h2pack(sc[2*jj][0],   sc[2*jj][1]);
            pf[jj][1] = h2pack(sc[2*jj][2],   sc[2*jj][3]);
            pf[jj][2] = h2pack(sc[2*jj+1][0], sc[2*jj+1][1]);
            pf[jj][3] = h2pack(sc[2*jj+1][2], sc[2*jj+1][3]);
        }

#pragma unroll
        for (int ks2 = 0; ks2 < 8; ks2++) {
#pragma unroll
            for (int pp = 0; pp < 4; pp++) {
                uint32_t v4[4];
                int vrow = ks2*16 + vrow_b;
                ldsm4t(v4[0], v4[1], v4[2], v4[3], bV + swzb(vrow, pp*32 + vcb_b));
                mmaf16(O[2*pp],   pf[ks2], v4+0);
                mmaf16(O[2*pp+1], pf[ks2], v4+2);
            }
        }
        __syncthreads();
        if (kt + 2 < 8) load_kv(kt + 2, (kt + 1) & 1);
    }

    float inv0 = 1.f / l0, inv1 = 1.f / l1;
    int g = lane >> 2, t2 = (lane & 3)*2;
    int bb = bh / NH, h = bh - bb*NH;
    int n0 = qt*128 + w*16 + g;
#pragma unroll
    for (int nd = 0; nd < 8; nd++) {
        int col = h*64 + nd*8 + t2;
        size_t o0 = ((size_t)bb*SEQ + n0)*CC + col;
        size_t o1 = ((size_t)bb*SEQ + n0 + 8)*CC + col;
        __half h0,l0b,h1,l1b,h2v,l2,h3,l3;
        hsplit(O[nd][0]*inv0, h0, l0b); hsplit(O[nd][1]*inv0, h1, l1b);
        hsplit(O[nd][2]*inv1, h2v, l2); hsplit(O[nd][3]*inv1, h3, l3);
        *(__half2*)(g_aoh + o0) = __half2(h0,h1);
        *(__half2*)(g_aol + o0) = __half2(l0b,l1b);
        *(__half2*)(g_aoh + o1) = __half2(h2v,h3);
        *(__half2*)(g_aol + o1) = __half2(l2,l3);
    }
}

// ---------------------------------------------------------------------------
extern "C" void kernel_launch(void* const* d_in, const int* in_sizes, int n_in,
                              void* d_out, int out_size) {
    const float* x      = (const float*)d_in[0];
    const float* y      = (const float*)d_in[1];
    const float* q_w    = (const float*)d_in[2];
    const float* q_b    = (const float*)d_in[3];
    const float* kv_w   = (const float*)d_in[4];
    const float* kv_b   = (const float*)d_in[5];
    const float* proj_w = (const float*)d_in[6];
    const float* proj_b = (const float*)d_in[7];
    const float* ln_g   = (const float*)d_in[8];
    const float* ln_b   = (const float*)d_in[9];
    float* out = (float*)d_out;

    void *paoh, *paol, *pp;
    cudaGetSymbolAddress(&paoh, g_aoh);
    cudaGetSymbolAddress(&paol, g_aol);
    cudaGetSymbolAddress(&pp,   g_p);

    prep_all<<<1184, 256>>>(x, q_w, kv_w, proj_w);
    ln_kernel<<<MM, 256>>>(y, ln_g, ln_b);

    int smq = 2*QSTG;   // 92160
    cudaFuncSetAttribute(qkv_fused, cudaFuncAttributeMaxDynamicSharedMemorySize, smq);
    qkv_fused<<<dim3(36, 64), 256, smq>>>(q_b, kv_b);

    int sma = 2*0x8000;
    cudaFuncSetAttribute(attn_mma, cudaFuncAttributeMaxDynamicSharedMemorySize, sma);
    attn_mma<<<dim3(8, 96), 256, sma>>>();

    int smp = 2*STGB;
    cudaFuncSetAttribute(hgemm_proj, cudaFuncAttributeMaxDynamicSharedMemorySize, smp);
    hgemm_proj<<<dim3(6, 64), 256, smp>>>(
        (const __half*)paoh, (const __half*)paol, (const __half*)pp,
        out, proj_b);
}

// round 12
// speedup vs baseline: 6.0634x; 1.0987x over previous
#include <cuda_runtime.h>
#include <cuda_fp16.h>
#include <cstdint>

#define SEQ  1024
#define CC   768
#define NH   12
#define HD   64
#define MM   8192
#define NQKV 2304

// ---------------- scratch (device globals) ----------------------------------
__device__ __half g_x[MM*CC];                     // x f16
__device__ __half g_y[MM*CC];                     // y2 (post-LN) f16
__device__ __half g_w[NQKV*CC];                   // concat(q_w, kv_w) f16
__device__ __half g_p[CC*CC];                     // proj_w f16
__device__ __half g_q[MM*CC];                     // q (x0.125) f16
__device__ __half g_k[MM*CC];                     // k f16
__device__ __half g_v[MM*CC];                     // v f16
__device__ __half g_ao[MM*CC];                    // attn out f16 (single)

// ---------------- helpers ----------------------------------------------------
__device__ __forceinline__ uint32_t smem_u32(const void* p) {
    uint32_t a;
    asm("{ .reg .u64 t; cvta.to.shared.u64 t, %1; cvt.u32.u64 %0, t; }" : "=r"(a) : "l"(p));
    return a;
}
__device__ __forceinline__ void cpa16(uint32_t s, const void* g) {
    asm volatile("cp.async.cg.shared.global [%0], [%1], 16;" :: "r"(s), "l"(g));
}
__device__ __forceinline__ void cpa_commit() { asm volatile("cp.async.commit_group;"); }
template<int N> __device__ __forceinline__ void cpa_wait() {
    asm volatile("cp.async.wait_group %0;" :: "n"(N));
}
__device__ __forceinline__ void ldsm4(uint32_t& r0, uint32_t& r1, uint32_t& r2, uint32_t& r3,
                                      uint32_t addr) {
    asm volatile("ldmatrix.sync.aligned.m8n8.x4.shared.b16 {%0,%1,%2,%3}, [%4];"
                 : "=r"(r0), "=r"(r1), "=r"(r2), "=r"(r3) : "r"(addr));
}
__device__ __forceinline__ void ldsm4t(uint32_t& r0, uint32_t& r1, uint32_t& r2, uint32_t& r3,
                                       uint32_t addr) {
    asm volatile("ldmatrix.sync.aligned.m8n8.x4.trans.shared.b16 {%0,%1,%2,%3}, [%4];"
                 : "=r"(r0), "=r"(r1), "=r"(r2), "=r"(r3) : "r"(addr));
}
__device__ __forceinline__ void mmaf16(float* c, const uint32_t* a, const uint32_t* b) {
    asm volatile("mma.sync.aligned.m16n8k16.row.col.f32.f16.f16.f32 "
                 "{%0,%1,%2,%3}, {%4,%5,%6,%7}, {%8,%9}, {%0,%1,%2,%3};"
                 : "+f"(c[0]), "+f"(c[1]), "+f"(c[2]), "+f"(c[3])
                 : "r"(a[0]), "r"(a[1]), "r"(a[2]), "r"(a[3]), "r"(b[0]), "r"(b[1]));
}
__device__ __forceinline__ uint32_t h2pack(float a, float b) {
    __half2 h = __floats2half2_rn(a, b);
    return *(uint32_t*)&h;
}
__device__ __forceinline__ float sigmoidf_(float x) { return 1.f/(1.f+__expf(-x)); }
__device__ __forceinline__ uint32_t swzb(int row, int cb) {
    return (uint32_t)(row*128 + ((((cb) >> 4) ^ (row & 7)) << 4));
}

// ---------------------------------------------------------------------------
__global__ void prep_all(const float* __restrict__ x, const float* __restrict__ qw,
                         const float* __restrict__ kvw, const float* __restrict__ pw) {
    const int NX = MM*CC, QW = CC*CC, KVW = 2*CC*CC, PW = CC*CC;
    const int T0 = NX, T1 = NX + QW, T2 = T1 + KVW, TOT = T2 + PW;
    for (int i = blockIdx.x*blockDim.x + threadIdx.x; i < TOT; i += gridDim.x*blockDim.x) {
        if (i < T0)      g_x[i] = __float2half_rn(x[i]);
        else if (i < T1) g_w[i - T0] = __float2half_rn(qw[i - T0]);
        else if (i < T2) g_w[i - T0] = __float2half_rn(kvw[i - T1]);
        else             g_p[i - T2] = __float2half_rn(pw[i - T2]);
    }
}

__global__ void ln_kernel(const float* __restrict__ y,
                          const float* __restrict__ gam, const float* __restrict__ bet) {
    int m = blockIdx.x, bb = m >> 10, n = m & 1023;
    const float* yp = y + (size_t)bb*CC*SEQ + n;
    float v[3]; float s = 0.f, s2 = 0.f;
#pragma unroll
    for (int i = 0; i < 3; i++) {
        int c = threadIdx.x + i*256;
        float t = yp[(size_t)c*SEQ];
        v[i] = t; s += t; s2 += t*t;
    }
#pragma unroll
    for (int o = 16; o > 0; o >>= 1) {
        s  += __shfl_xor_sync(0xffffffffu, s,  o);
        s2 += __shfl_xor_sync(0xffffffffu, s2, o);
    }
    __shared__ float rb[2][8];
    if ((threadIdx.x & 31) == 0) { rb[0][threadIdx.x>>5] = s; rb[1][threadIdx.x>>5] = s2; }
    __syncthreads();
    float ts = 0.f, ts2 = 0.f;
#pragma unroll
    for (int i = 0; i < 8; i++) { ts += rb[0][i]; ts2 += rb[1][i]; }
    float mean = ts*(1.f/CC), var = ts2*(1.f/CC) - mean*mean;
    float rstd = rsqrtf(var + 1e-5f);
#pragma unroll
    for (int i = 0; i < 3; i++) {
        int c = threadIdx.x + i*256;
        float o = (v[i]-mean)*rstd*gam[c] + bet[c];
        g_y[(size_t)m*CC + c] = __float2half_rn(o);
    }
}

// ---------------------------------------------------------------------------
// FUSED qkv GEMM + gating (unchanged from R11). K staged 64, 12 stages.
// ---------------------------------------------------------------------------
#define PITCH2 144
#define BUFX  18432
#define BUFW2 9216
#define QSTG  (2*BUFX + BUFW2)   // 46080

__global__ __launch_bounds__(256, 2)
void qkv_fused(const float* __restrict__ qb, const float* __restrict__ kvb) {
    extern __shared__ __align__(16) char smraw[];
    uint32_t smb = smem_u32(smraw);
    int t = threadIdx.x, lane = t & 31, w = t >> 5;
    int wm = w >> 1, wn = w & 1;
    int bx = blockIdx.x;
    int m0 = blockIdx.y * 128;
    int j0 = bx * 64;

    const __half* sx = g_x + (size_t)m0*CC;
    const __half* sy = g_y + (size_t)m0*CC;
    const __half* sw = g_w + (size_t)j0*CC;

    auto load_stage = [&](int s, int k0) {
        uint32_t base = smb + (s & 1)*QSTG;
#pragma unroll
        for (int i = 0; i < 4; i++) {
            int c = t + i*256;
            int row = c >> 3, ch = c & 7;
            cpa16(base + row*PITCH2 + ch*16,          sx + (size_t)row*CC + k0 + ch*8);
            cpa16(base + BUFX + row*PITCH2 + ch*16,   sy + (size_t)row*CC + k0 + ch*8);
        }
#pragma unroll
        for (int i = 0; i < 2; i++) {
            int c = t + i*256;
            int row = c >> 3, ch = c & 7;
            cpa16(base + 2*BUFX + row*PITCH2 + ch*16, sw + (size_t)row*CC + k0 + ch*8);
        }
        cpa_commit();
    };

    float accx[2][4][4], accy[2][4][4];
#pragma unroll
    for (int mi = 0; mi < 2; mi++)
#pragma unroll
        for (int ni = 0; ni < 4; ni++)
#pragma unroll
            for (int e = 0; e < 4; e++) { accx[mi][ni][e] = 0.f; accy[mi][ni][e] = 0.f; }

    load_stage(0, 0);

    const int NSTG = CC/64;
    int a_row  = wm*32 + (lane & 15);
    int a_coff = (lane >> 4) * 16;
    int b_row  = (lane & 7) + ((lane >> 1) & 8);
    int b_coff = (lane & 8) * 2;

#pragma unroll 1
    for (int s = 0; s < NSTG; s++) {
        if (s + 1 < NSTG) load_stage(s + 1, (s + 1)*64);
        if (s + 1 < NSTG) cpa_wait<1>(); else cpa_wait<0>();
        __syncthreads();
        uint32_t bX = smb + (s & 1)*QSTG;
        uint32_t bY = bX + BUFX, bW = bX + 2*BUFX;
#pragma unroll
        for (int ks = 0; ks < 4; ks++) {
            int kb = ks*32;
            uint32_t xx[2][4], yy[2][4], bw[4][2];
            ldsm4(xx[0][0], xx[0][1], xx[0][2], xx[0][3], bX + (a_row)*PITCH2     + kb + a_coff);
            ldsm4(xx[1][0], xx[1][1], xx[1][2], xx[1][3], bX + (a_row+16)*PITCH2 + kb + a_coff);
            ldsm4(yy[0][0], yy[0][1], yy[0][2], yy[0][3], bY + (a_row)*PITCH2     + kb + a_coff);
            ldsm4(yy[1][0], yy[1][1], yy[1][2], yy[1][3], bY + (a_row+16)*PITCH2 + kb + a_coff);
#pragma unroll
            for (int p = 0; p < 2; p++) {
                int nr = wn*32 + p*16 + b_row;
                ldsm4(bw[2*p][0], bw[2*p][1], bw[2*p+1][0], bw[2*p+1][1],
                      bW + nr*PITCH2 + kb + b_coff);
            }
#pragma unroll
            for (int mi = 0; mi < 2; mi++)
#pragma unroll
                for (int ni = 0; ni < 4; ni++) {
                    mmaf16(accx[mi][ni], xx[mi], bw[ni]);
                    mmaf16(accy[mi][ni], yy[mi], bw[ni]);
                }
        }
        __syncthreads();
    }

    int sec = bx / 12;
    int h   = bx - sec*12;
#pragma unroll
    for (int mi = 0; mi < 2; mi++) {
#pragma unroll
        for (int e2 = 0; e2 < 2; e2++) {
            int r = m0 + wm*32 + mi*16 + (lane >> 2) + e2*8;
            int bb = r >> 10, n = r & 1023;
            size_t obase = (((size_t)bb*NH + h)*SEQ + n)*HD;
#pragma unroll
            for (int ni = 0; ni < 4; ni++) {
                int d = wn*32 + ni*8 + 2*(lane & 3);
                float ax0 = accx[mi][ni][2*e2], ax1 = accx[mi][ni][2*e2+1];
                float ay0 = accy[mi][ni][2*e2], ay1 = accy[mi][ni][2*e2+1];
                if (sec == 0) {
                    float b0 = qb[j0 + d], b1 = qb[j0 + d + 1];
                    float o0 = 0.125f*(ax0+b0)*(1.f + sigmoidf_(ay0+b0));
                    float o1 = 0.125f*(ax1+b1)*(1.f + sigmoidf_(ay1+b1));
                    *(__half2*)(g_q + obase + d) = __floats2half2_rn(o0, o1);
                } else {
                    float b0 = kvb[j0 - CC + d], b1 = kvb[j0 - CC + d + 1];
                    float o0 = sigmoidf_(ay0+b0)*(ax0+b0+1.f);
                    float o1 = sigmoidf_(ay1+b1)*(ax1+b1+1.f);
                    __half* dst = (sec == 1) ? g_k : g_v;
                    *(__half2*)(dst + obase + d) = __floats2half2_rn(o0, o1);
                }
            }
        }
    }
}

// ---------------------------------------------------------------------------
// proj GEMM: single-pass A now (ao f16). 2 sub-buffers/stage.
// ---------------------------------------------------------------------------
#define PITCH 80
#define BUFB  10240
#define STGB  (2*BUFB)

__global__ __launch_bounds__(256, 2)
void hgemm_proj(const __half* __restrict__ A, const __half* __restrict__ W,
                float* __restrict__ C, const float* __restrict__ bias) {
    extern __shared__ __align__(16) char smraw[];
    uint32_t smb = smem_u32(smraw);
    int t = threadIdx.x, lane = t & 31, w = t >> 5;
    int wm = w >> 1, wn = w & 1;
    int am0 = blockIdx.y * 128, wn0 = blockIdx.x * 128;

    const __half* srcs[2] = { A + (size_t)am0*CC, W + (size_t)wn0*CC };
    int r0 = t >> 2, c0 = t & 3;
    int r1 = (t + 256) >> 2;

    auto load_stage = [&](int s, int k0) {
        uint32_t base = smb + (s & 1)*STGB;
#pragma unroll
        for (int b = 0; b < 2; b++) {
            cpa16(base + b*BUFB + r0*PITCH + c0*16, srcs[b] + (size_t)r0*CC + k0 + c0*8);
            cpa16(base + b*BUFB + r1*PITCH + c0*16, srcs[b] + (size_t)r1*CC + k0 + c0*8);
        }
        cpa_commit();
    };

    float acc[2][8][4];
#pragma unroll
    for (int mi = 0; mi < 2; mi++)
#pragma unroll
        for (int ni = 0; ni < 8; ni++)
#pragma unroll
            for (int e = 0; e < 4; e++) acc[mi][ni][e] = 0.f;

    load_stage(0, 0);

    const int NSTG = CC/32;
    int a_row  = wm*32 + (lane & 15);
    int a_coff = (lane >> 4) * 16;
    int b_row  = (lane & 7) + ((lane >> 1) & 8);
    int b_coff = (lane & 8) * 2;

#pragma unroll 1
    for (int s = 0; s < NSTG; s++) {
        if (s + 1 < NSTG) load_stage(s + 1, (s + 1)*32);
        if (s + 1 < NSTG) cpa_wait<1>(); else cpa_wait<0>();
        __syncthreads();
        uint32_t bA = smb + (s & 1)*STGB;
        uint32_t bW = bA + BUFB;
#pragma unroll
        for (int ks = 0; ks < 2; ks++) {
            int kb = ks*32;
            uint32_t aa[2][4], bw[8][2];
            ldsm4(aa[0][0], aa[0][1], aa[0][2], aa[0][3], bA + (a_row)*PITCH     + kb + a_coff);
            ldsm4(aa[1][0], aa[1][1], aa[1][2], aa[1][3], bA + (a_row+16)*PITCH + kb + a_coff);
#pragma unroll
            for (int p = 0; p < 4; p++) {
                int nr = wn*64 + p*16 + b_row;
                ldsm4(bw[2*p][0], bw[2*p][1], bw[2*p+1][0], bw[2*p+1][1],
                      bW + nr*PITCH + kb + b_coff);
            }
#pragma unroll
            for (int mi = 0; mi < 2; mi++)
#pragma unroll
                for (int ni = 0; ni < 8; ni++)
                    mmaf16(acc[mi][ni], aa[mi], bw[ni]);
        }
        __syncthreads();
    }

#pragma unroll
    for (int mi = 0; mi < 2; mi++) {
        int row = am0 + wm*32 + mi*16 + (lane >> 2);
#pragma unroll
        for (int ni = 0; ni < 8; ni++) {
            int col = wn0 + wn*64 + ni*8 + 2*(lane & 3);
            float b0 = bias[col], b1 = bias[col+1];
            *(float2*)(C + (size_t)row*CC + col)     = make_float2(acc[mi][ni][0]+b0, acc[mi][ni][1]+b1);
            *(float2*)(C + (size_t)(row+8)*CC + col) = make_float2(acc[mi][ni][2]+b0, acc[mi][ni][3]+b1);
        }
    }
}

// ---------------------------------------------------------------------------
// TC flash attention: 128q x 64k tiles now (2 CTAs/SM target).
// smem: 2 stages x 16KB (K 8KB + V 8KB) = 32KB. Q staged in stage0 region.
// ---------------------------------------------------------------------------
__global__ __launch_bounds__(256, 2)
void attn_mma() {
    extern __shared__ __align__(16) char smraw[];
    uint32_t smb = smem_u32(smraw);
    int qt = blockIdx.x, bh = blockIdx.y;
    int t = threadIdx.x, lane = t & 31, w = t >> 5;
    const __half* qp = g_q + (size_t)bh*SEQ*HD + (size_t)qt*128*HD;
    const __half* kp = g_k + (size_t)bh*SEQ*HD;
    const __half* vp = g_v + (size_t)bh*SEQ*HD;

    // stage Q (16KB) into the two stage buffers (stage0 0..8K = rows 0..63,
    // stage1 8..16K? no — use both stage regions: 32KB total, Q fits in first 16KB)
#pragma unroll
    for (int i = 0; i < 4; i++) {
        int c = t + i*256;
        int row = c >> 3, ch = c & 7;
        cpa16(smb + swzb(row, ch*16), qp + (size_t)row*HD + ch*8);
    }
    cpa_commit();

    auto load_kv = [&](int kt, int stage) {
        uint32_t base = smb + stage*0x4000;
#pragma unroll
        for (int i = 0; i < 2; i++) {
            int c = t + i*256;
            int row = c >> 3, ch = c & 7;     // 64 rows
            uint32_t off = swzb(row, ch*16);
            const size_t go = (size_t)(kt*64 + row)*HD + ch*8;
            cpa16(base + 0x0000 + off, kp + go);
            cpa16(base + 0x2000 + off, vp + go);
        }
        cpa_commit();
    };

    cpa_wait<0>();               // Q resident
    __syncthreads();

    uint32_t qf[4][4];
    int arow = w*16 + (lane & 15);
    int acb0 = (lane >> 4) << 4;
#pragma unroll
    for (int ks = 0; ks < 4; ks++) {
        uint32_t off = swzb(arow, ks*32 + acb0);
        ldsm4(qf[ks][0], qf[ks][1], qf[ks][2], qf[ks][3], smb + off);
    }
    __syncthreads();             // Q consumed; smem reusable
    load_kv(0, 0);
    load_kv(1, 1);

    float O[8][4];
#pragma unroll
    for (int nd = 0; nd < 8; nd++)
#pragma unroll
        for (int e = 0; e < 4; e++) O[nd][e] = 0.f;
    float m0 = -1e30f, m1 = -1e30f, l0 = 0.f, l1 = 0.f;

    int krow_b = (lane & 7) + ((lane >> 1) & 8);
    int kcb_b  = (lane & 8) << 1;
    int vrow_b = lane & 15;
    int vcb_b  = (lane >> 4) << 4;

#pragma unroll 1
    for (int kt = 0; kt < 16; kt++) {
        if (kt >= 14) cpa_wait<0>(); else cpa_wait<1>();
        __syncthreads();
        uint32_t base = smb + (kt & 1)*0x4000;
        uint32_t bK = base, bV = base + 0x2000;

        float sc[8][4];
#pragma unroll
        for (int jj = 0; jj < 8; jj++)
#pragma unroll
            for (int e = 0; e < 4; e++) sc[jj][e] = 0.f;
#pragma unroll
        for (int ks = 0; ks < 4; ks++) {
#pragma unroll
            for (int p = 0; p < 4; p++) {
                uint32_t k4[4];
                int krow = 16*p + krow_b;
                ldsm4(k4[0], k4[1], k4[2], k4[3], bK + swzb(krow, ks*32 + kcb_b));
                mmaf16(sc[2*p],   qf[ks], k4+0);
                mmaf16(sc[2*p+1], qf[ks], k4+2);
            }
        }

        float rm0 = -1e30f, rm1 = -1e30f;
#pragma unroll
        for (int jj = 0; jj < 8; jj++) {
            rm0 = fmaxf(rm0, fmaxf(sc[jj][0], sc[jj][1]));
            rm1 = fmaxf(rm1, fmaxf(sc[jj][2], sc[jj][3]));
        }
        rm0 = fmaxf(rm0, __shfl_xor_sync(0xffffffffu, rm0, 1));
        rm0 = fmaxf(rm0, __shfl_xor_sync(0xffffffffu, rm0, 2));
        rm1 = fmaxf(rm1, __shfl_xor_sync(0xffffffffu, rm1, 1));
        rm1 = fmaxf(rm1, __shfl_xor_sync(0xffffffffu, rm1, 2));
        float mn0 = fmaxf(m0, rm0), mn1 = fmaxf(m1, rm1);
        float a0 = __expf(m0 - mn0), a1 = __expf(m1 - mn1);
        float rs0 = 0.f, rs1 = 0.f;
#pragma unroll
        for (int jj = 0; jj < 8; jj++) {
            sc[jj][0] = __expf(sc[jj][0] - mn0);
            sc[jj][1] = __expf(sc[jj][1] - mn0);
            sc[jj][2] = __expf(sc[jj][2] - mn1);
            sc[jj][3] = __expf(sc[jj][3] - mn1);
            rs0 += sc[jj][0] + sc[jj][1];
            rs1 += sc[jj][2] + sc[jj][3];
        }
        rs0 += __shfl_xor_sync(0xffffffffu, rs0, 1);
        rs0 += __shfl_xor_sync(0xffffffffu, rs0, 2);
        rs1 += __shfl_xor_sync(0xffffffffu, rs1, 1);
        rs1 += __shfl_xor_sync(0xffffffffu, rs1, 2);
        l0 = l0*a0 + rs0; l1 = l1*a1 + rs1;
        m0 = mn0; m1 = mn1;
#pragma unroll
        for (int nd = 0; nd < 8; nd++) {
            O[nd][0] *= a0; O[nd][1] *= a0;
            O[nd][2] *= a1; O[nd][3] *= a1;
        }

        uint32_t pf[4][4];
#pragma unroll
        for (int jj = 0; jj < 4; jj++) {
            pf[jj][0] = h2pack(sc[2*jj][0],   sc[2*jj][1]);
            pf[jj][1] = h2pack(sc[2*jj][2],   sc[2*jj][3]);
            pf[jj][2] = h2pack(sc[2*jj+1][0], sc[2*jj+1][1]);
            pf[jj][3] = h2pack(sc[2*jj+1][2], sc[2*jj+1][3]);
        }

#pragma unroll
        for (int ks2 = 0; ks2 < 4; ks2++) {
#pragma unroll
            for (int pp = 0; pp < 4; pp++) {
                uint32_t v4[4];
                int vrow = ks2*16 + vrow_b;
                ldsm4t(v4[0], v4[1], v4[2], v4[3], bV + swzb(vrow, pp*32 + vcb_b));
                mmaf16(O[2*pp],   pf[ks2], v4+0);
                mmaf16(O[2*pp+1], pf[ks2], v4+2);
            }
        }
        __syncthreads();
        if (kt + 2 < 16) load_kv(kt + 2, kt & 1);
    }

    float inv0 = 1.f / l0, inv1 = 1.f / l1;
    int g = lane >> 2, t2 = (lane & 3)*2;
    int bb = bh / NH, h = bh - bb*NH;
    int n0 = qt*128 + w*16 + g;
#pragma unroll
    for (int nd = 0; nd < 8; nd++) {
        int col = h*64 + nd*8 + t2;
        size_t o0 = ((size_t)bb*SEQ + n0)*CC + col;
        size_t o1 = ((size_t)bb*SEQ + n0 + 8)*CC + col;
        *(__half2*)(g_ao + o0) = __floats2half2_rn(O[nd][0]*inv0, O[nd][1]*inv0);
        *(__half2*)(g_ao + o1) = __floats2half2_rn(O[nd][2]*inv1, O[nd][3]*inv1);
    }
}

// ---------------------------------------------------------------------------
extern "C" void kernel_launch(void* const* d_in, const int* in_sizes, int n_in,
                              void* d_out, int out_size) {
    const float* x      = (const float*)d_in[0];
    const float* y      = (const float*)d_in[1];
    const float* q_w    = (const float*)d_in[2];
    const float* q_b    = (const float*)d_in[3];
    const float* kv_w   = (const float*)d_in[4];
    const float* kv_b   = (const float*)d_in[5];
    const float* proj_w = (const float*)d_in[6];
    const float* proj_b = (const float*)d_in[7];
    const float* ln_g   = (const float*)d_in[8];
    const float* ln_b   = (const float*)d_in[9];
    float* out = (float*)d_out;

    void *pao, *pp;
    cudaGetSymbolAddress(&pao, g_ao);
    cudaGetSymbolAddress(&pp,  g_p);

    prep_all<<<1184, 256>>>(x, q_w, kv_w, proj_w);
    ln_kernel<<<MM, 256>>>(y, ln_g, ln_b);

    int smq = 2*QSTG;   // 92160
    cudaFuncSetAttribute(qkv_fused, cudaFuncAttributeMaxDynamicSharedMemorySize, smq);
    qkv_fused<<<dim3(36, 64), 256, smq>>>(q_b, kv_b);

    int sma = 2*0x4000;   // 32KB (Q staging reuses the same region)
    cudaFuncSetAttribute(attn_mma, cudaFuncAttributeMaxDynamicSharedMemorySize, sma);
    attn_mma<<<dim3(8, 96), 256, sma>>>();

    int smp = 2*STGB;     // 40960
    cudaFuncSetAttribute(hgemm_proj, cudaFuncAttributeMaxDynamicSharedMemorySize, smp);
    hgemm_proj<<<dim3(6, 64), 256, smp>>>(
        (const __half*)pao, (const __half*)pp, out, proj_b);
}

// round 13
// speedup vs baseline: 6.2715x; 1.0343x over previous
#include <cuda_runtime.h>
#include <cuda_fp16.h>
#include <cstdint>

#define SEQ  1024
#define CC   768
#define NH   12
#define HD   64
#define MM   8192
#define NQKV 2304

// ---------------- scratch (device globals) ----------------------------------
__device__ __half g_x[MM*CC];
__device__ __half g_y[MM*CC];
__device__ __half g_w[NQKV*CC];
__device__ __half g_p[CC*CC];
__device__ __half g_q[MM*CC];                     // q * 0.125*log2(e)
__device__ __half g_k[MM*CC];
__device__ __half g_v[MM*CC];
__device__ __half g_ao[MM*CC];

#define LOG2E 1.4426950408889634f

// ---------------- helpers ----------------------------------------------------
__device__ __forceinline__ uint32_t smem_u32(const void* p) {
    uint32_t a;
    asm("{ .reg .u64 t; cvta.to.shared.u64 t, %1; cvt.u32.u64 %0, t; }" : "=r"(a) : "l"(p));
    return a;
}
__device__ __forceinline__ void cpa16(uint32_t s, const void* g) {
    asm volatile("cp.async.cg.shared.global [%0], [%1], 16;" :: "r"(s), "l"(g));
}
__device__ __forceinline__ void cpa_commit() { asm volatile("cp.async.commit_group;"); }
template<int N> __device__ __forceinline__ void cpa_wait() {
    asm volatile("cp.async.wait_group %0;" :: "n"(N));
}
__device__ __forceinline__ void ldsm4(uint32_t& r0, uint32_t& r1, uint32_t& r2, uint32_t& r3,
                                      uint32_t addr) {
    asm volatile("ldmatrix.sync.aligned.m8n8.x4.shared.b16 {%0,%1,%2,%3}, [%4];"
                 : "=r"(r0), "=r"(r1), "=r"(r2), "=r"(r3) : "r"(addr));
}
__device__ __forceinline__ void ldsm4t(uint32_t& r0, uint32_t& r1, uint32_t& r2, uint32_t& r3,
                                       uint32_t addr) {
    asm volatile("ldmatrix.sync.aligned.m8n8.x4.trans.shared.b16 {%0,%1,%2,%3}, [%4];"
                 : "=r"(r0), "=r"(r1), "=r"(r2), "=r"(r3) : "r"(addr));
}
__device__ __forceinline__ void mmaf16(float* c, const uint32_t* a, const uint32_t* b) {
    asm volatile("mma.sync.aligned.m16n8k16.row.col.f32.f16.f16.f32 "
                 "{%0,%1,%2,%3}, {%4,%5,%6,%7}, {%8,%9}, {%0,%1,%2,%3};"
                 : "+f"(c[0]), "+f"(c[1]), "+f"(c[2]), "+f"(c[3])
                 : "r"(a[0]), "r"(a[1]), "r"(a[2]), "r"(a[3]), "r"(b[0]), "r"(b[1]));
}
__device__ __forceinline__ uint32_t h2pack(float a, float b) {
    __half2 h = __floats2half2_rn(a, b);
    return *(uint32_t*)&h;
}
__device__ __forceinline__ float sigmoidf_(float x) { return 1.f/(1.f+__expf(-x)); }
__device__ __forceinline__ uint32_t swzb(int row, int cb) {
    return (uint32_t)(row*128 + ((((cb) >> 4) ^ (row & 7)) << 4));
}

// ---------------------------------------------------------------------------
__global__ void prep_all(const float* __restrict__ x, const float* __restrict__ qw,
                         const float* __restrict__ kvw, const float* __restrict__ pw) {
    const int NX = MM*CC, QW = CC*CC, KVW = 2*CC*CC, PW = CC*CC;
    const int T0 = NX, T1 = NX + QW, T2 = T1 + KVW, TOT = T2 + PW;
    for (int i = blockIdx.x*blockDim.x + threadIdx.x; i < TOT; i += gridDim.x*blockDim.x) {
        if (i < T0)      g_x[i] = __float2half_rn(x[i]);
        else if (i < T1) g_w[i - T0] = __float2half_rn(qw[i - T0]);
        else if (i < T2) g_w[i - T0] = __float2half_rn(kvw[i - T1]);
        else             g_p[i - T2] = __float2half_rn(pw[i - T2]);
    }
}

__global__ void ln_kernel(const float* __restrict__ y,
                          const float* __restrict__ gam, const float* __restrict__ bet) {
    int m = blockIdx.x, bb = m >> 10, n = m & 1023;
    const float* yp = y + (size_t)bb*CC*SEQ + n;
    float v[3]; float s = 0.f, s2 = 0.f;
#pragma unroll
    for (int i = 0; i < 3; i++) {
        int c = threadIdx.x + i*256;
        float t = yp[(size_t)c*SEQ];
        v[i] = t; s += t; s2 += t*t;
    }
#pragma unroll
    for (int o = 16; o > 0; o >>= 1) {
        s  += __shfl_xor_sync(0xffffffffu, s,  o);
        s2 += __shfl_xor_sync(0xffffffffu, s2, o);
    }
    __shared__ float rb[2][8];
    if ((threadIdx.x & 31) == 0) { rb[0][threadIdx.x>>5] = s; rb[1][threadIdx.x>>5] = s2; }
    __syncthreads();
    float ts = 0.f, ts2 = 0.f;
#pragma unroll
    for (int i = 0; i < 8; i++) { ts += rb[0][i]; ts2 += rb[1][i]; }
    float mean = ts*(1.f/CC), var = ts2*(1.f/CC) - mean*mean;
    float rstd = rsqrtf(var + 1e-5f);
#pragma unroll
    for (int i = 0; i < 3; i++) {
        int c = threadIdx.x + i*256;
        float o = (v[i]-mean)*rstd*gam[c] + bet[c];
        g_y[(size_t)m*CC + c] = __float2half_rn(o);
    }
}

// ---------------------------------------------------------------------------
// FUSED qkv GEMM + gating. K staged 64, SINGLE sync per stage.
// ---------------------------------------------------------------------------
#define PITCH2 144
#define BUFX  18432
#define BUFW2 9216
#define QSTG  (2*BUFX + BUFW2)   // 46080

__global__ __launch_bounds__(256, 2)
void qkv_fused(const float* __restrict__ qb, const float* __restrict__ kvb) {
    extern __shared__ __align__(16) char smraw[];
    uint32_t smb = smem_u32(smraw);
    int t = threadIdx.x, lane = t & 31, w = t >> 5;
    int wm = w >> 1, wn = w & 1;
    int bx = blockIdx.x;
    int m0 = blockIdx.y * 128;
    int j0 = bx * 64;

    const __half* sx = g_x + (size_t)m0*CC;
    const __half* sy = g_y + (size_t)m0*CC;
    const __half* sw = g_w + (size_t)j0*CC;

    auto load_stage = [&](int s, int k0) {
        uint32_t base = smb + (s & 1)*QSTG;
#pragma unroll
        for (int i = 0; i < 4; i++) {
            int c = t + i*256;
            int row = c >> 3, ch = c & 7;
            cpa16(base + row*PITCH2 + ch*16,          sx + (size_t)row*CC + k0 + ch*8);
            cpa16(base + BUFX + row*PITCH2 + ch*16,   sy + (size_t)row*CC + k0 + ch*8);
        }
#pragma unroll
        for (int i = 0; i < 2; i++) {
            int c = t + i*256;
            int row = c >> 3, ch = c & 7;
            cpa16(base + 2*BUFX + row*PITCH2 + ch*16, sw + (size_t)row*CC + k0 + ch*8);
        }
        cpa_commit();
    };

    float accx[2][4][4], accy[2][4][4];
#pragma unroll
    for (int mi = 0; mi < 2; mi++)
#pragma unroll
        for (int ni = 0; ni < 4; ni++)
#pragma unroll
            for (int e = 0; e < 4; e++) { accx[mi][ni][e] = 0.f; accy[mi][ni][e] = 0.f; }

    load_stage(0, 0);

    const int NSTG = CC/64;   // 12
    int a_row  = wm*32 + (lane & 15);
    int a_coff = (lane >> 4) * 16;
    int b_row  = (lane & 7) + ((lane >> 1) & 8);
    int b_coff = (lane & 8) * 2;

#pragma unroll 1
    for (int s = 0; s < NSTG; s++) {
        cpa_wait<0>();
        __syncthreads();
        if (s + 1 < NSTG) load_stage(s + 1, (s + 1)*64);   // writes other stage; safe post-sync
        uint32_t bX = smb + (s & 1)*QSTG;
        uint32_t bY = bX + BUFX, bW = bX + 2*BUFX;
#pragma unroll
        for (int ks = 0; ks < 4; ks++) {
            int kb = ks*32;
            uint32_t xx[2][4], yy[2][4], bw[4][2];
            ldsm4(xx[0][0], xx[0][1], xx[0][2], xx[0][3], bX + (a_row)*PITCH2     + kb + a_coff);
            ldsm4(xx[1][0], xx[1][1], xx[1][2], xx[1][3], bX + (a_row+16)*PITCH2 + kb + a_coff);
            ldsm4(yy[0][0], yy[0][1], yy[0][2], yy[0][3], bY + (a_row)*PITCH2     + kb + a_coff);
            ldsm4(yy[1][0], yy[1][1], yy[1][2], yy[1][3], bY + (a_row+16)*PITCH2 + kb + a_coff);
#pragma unroll
            for (int p = 0; p < 2; p++) {
                int nr = wn*32 + p*16 + b_row;
                ldsm4(bw[2*p][0], bw[2*p][1], bw[2*p+1][0], bw[2*p+1][1],
                      bW + nr*PITCH2 + kb + b_coff);
            }
#pragma unroll
            for (int mi = 0; mi < 2; mi++)
#pragma unroll
                for (int ni = 0; ni < 4; ni++) {
                    mmaf16(accx[mi][ni], xx[mi], bw[ni]);
                    mmaf16(accy[mi][ni], yy[mi], bw[ni]);
                }
        }
    }

    int sec = bx / 12;
    int h   = bx - sec*12;
#pragma unroll
    for (int mi = 0; mi < 2; mi++) {
#pragma unroll
        for (int e2 = 0; e2 < 2; e2++) {
            int r = m0 + wm*32 + mi*16 + (lane >> 2) + e2*8;
            int bb = r >> 10, n = r & 1023;
            size_t obase = (((size_t)bb*NH + h)*SEQ + n)*HD;
#pragma unroll
            for (int ni = 0; ni < 4; ni++) {
                int d = wn*32 + ni*8 + 2*(lane & 3);
                float ax0 = accx[mi][ni][2*e2], ax1 = accx[mi][ni][2*e2+1];
                float ay0 = accy[mi][ni][2*e2], ay1 = accy[mi][ni][2*e2+1];
                if (sec == 0) {
                    float b0 = qb[j0 + d], b1 = qb[j0 + d + 1];
                    float o0 = (0.125f*LOG2E)*(ax0+b0)*(1.f + sigmoidf_(ay0+b0));
                    float o1 = (0.125f*LOG2E)*(ax1+b1)*(1.f + sigmoidf_(ay1+b1));
                    *(__half2*)(g_q + obase + d) = __floats2half2_rn(o0, o1);
                } else {
                    float b0 = kvb[j0 - CC + d], b1 = kvb[j0 - CC + d + 1];
                    float o0 = sigmoidf_(ay0+b0)*(ax0+b0+1.f);
                    float o1 = sigmoidf_(ay1+b1)*(ax1+b1+1.f);
                    __half* dst = (sec == 1) ? g_k : g_v;
                    *(__half2*)(dst + obase + d) = __floats2half2_rn(o0, o1);
                }
            }
        }
    }
}

// ---------------------------------------------------------------------------
// proj GEMM: single-pass A, K staged 64, single sync per stage.
// ---------------------------------------------------------------------------
#define BUFP  18432
#define PSTG  (2*BUFP)   // 36864

__global__ __launch_bounds__(256, 2)
void hgemm_proj(const __half* __restrict__ A, const __half* __restrict__ W,
                float* __restrict__ C, const float* __restrict__ bias) {
    extern __shared__ __align__(16) char smraw[];
    uint32_t smb = smem_u32(smraw);
    int t = threadIdx.x, lane = t & 31, w = t >> 5;
    int wm = w >> 1, wn = w & 1;
    int am0 = blockIdx.y * 128, wn0 = blockIdx.x * 128;

    const __half* sa = A + (size_t)am0*CC;
    const __half* sw = W + (size_t)wn0*CC;

    auto load_stage = [&](int s, int k0) {
        uint32_t base = smb + (s & 1)*PSTG;
#pragma unroll
        for (int i = 0; i < 4; i++) {
            int c = t + i*256;
            int row = c >> 3, ch = c & 7;
            cpa16(base + row*PITCH2 + ch*16,        sa + (size_t)row*CC + k0 + ch*8);
            cpa16(base + BUFP + row*PITCH2 + ch*16, sw + (size_t)row*CC + k0 + ch*8);
        }
        cpa_commit();
    };

    float acc[2][8][4];
#pragma unroll
    for (int mi = 0; mi < 2; mi++)
#pragma unroll
        for (int ni = 0; ni < 8; ni++)
#pragma unroll
            for (int e = 0; e < 4; e++) acc[mi][ni][e] = 0.f;

    load_stage(0, 0);

    const int NSTG = CC/64;   // 12
    int a_row  = wm*32 + (lane & 15);
    int a_coff = (lane >> 4) * 16;
    int b_row  = (lane & 7) + ((lane >> 1) & 8);
    int b_coff = (lane & 8) * 2;

#pragma unroll 1
    for (int s = 0; s < NSTG; s++) {
        cpa_wait<0>();
        __syncthreads();
        if (s + 1 < NSTG) load_stage(s + 1, (s + 1)*64);
        uint32_t bA = smb + (s & 1)*PSTG;
        uint32_t bW = bA + BUFP;
#pragma unroll
        for (int ks = 0; ks < 4; ks++) {
            int kb = ks*32;
            uint32_t aa[2][4], bw[8][2];
            ldsm4(aa[0][0], aa[0][1], aa[0][2], aa[0][3], bA + (a_row)*PITCH2     + kb + a_coff);
            ldsm4(aa[1][0], aa[1][1], aa[1][2], aa[1][3], bA + (a_row+16)*PITCH2 + kb + a_coff);
#pragma unroll
            for (int p = 0; p < 4; p++) {
                int nr = wn*64 + p*16 + b_row;
                ldsm4(bw[2*p][0], bw[2*p][1], bw[2*p+1][0], bw[2*p+1][1],
                      bW + nr*PITCH2 + kb + b_coff);
            }
#pragma unroll
            for (int mi = 0; mi < 2; mi++)
#pragma unroll
                for (int ni = 0; ni < 8; ni++)
                    mmaf16(acc[mi][ni], aa[mi], bw[ni]);
        }
    }

#pragma unroll
    for (int mi = 0; mi < 2; mi++) {
        int row = am0 + wm*32 + mi*16 + (lane >> 2);
#pragma unroll
        for (int ni = 0; ni < 8; ni++) {
            int col = wn0 + wn*64 + ni*8 + 2*(lane & 3);
            float b0 = bias[col], b1 = bias[col+1];
            *(float2*)(C + (size_t)row*CC + col)     = make_float2(acc[mi][ni][0]+b0, acc[mi][ni][1]+b1);
            *(float2*)(C + (size_t)(row+8)*CC + col) = make_float2(acc[mi][ni][2]+b0, acc[mi][ni][3]+b1);
        }
    }
}

// ---------------------------------------------------------------------------
// TC flash attention: 128q x 64k tiles, 4-stage pipeline, 1 sync/iter, exp2.
// smem: 4 stages x 16KB = 64KB.
// ---------------------------------------------------------------------------
__global__ __launch_bounds__(256, 2)
void attn_mma() {
    extern __shared__ __align__(16) char smraw[];
    uint32_t smb = smem_u32(smraw);
    int qt = blockIdx.x, bh = blockIdx.y;
    int t = threadIdx.x, lane = t & 31, w = t >> 5;
    const __half* qp = g_q + (size_t)bh*SEQ*HD + (size_t)qt*128*HD;
    const __half* kp = g_k + (size_t)bh*SEQ*HD;
    const __half* vp = g_v + (size_t)bh*SEQ*HD;

    // stage Q (16KB, occupies stage0 region)
#pragma unroll
    for (int i = 0; i < 4; i++) {
        int c = t + i*256;
        int row = c >> 3, ch = c & 7;
        cpa16(smb + swzb(row, ch*16), qp + (size_t)row*HD + ch*8);
    }
    cpa_commit();

    auto load_kv = [&](int kt) {
        uint32_t base = smb + (kt & 3)*0x4000;
#pragma unroll
        for (int i = 0; i < 2; i++) {
            int c = t + i*256;
            int row = c >> 3, ch = c & 7;
            uint32_t off = swzb(row, ch*16);
            const size_t go = (size_t)(kt*64 + row)*HD + ch*8;
            cpa16(base + 0x0000 + off, kp + go);
            cpa16(base + 0x2000 + off, vp + go);
        }
        cpa_commit();
    };

    cpa_wait<0>();
    __syncthreads();

    uint32_t qf[4][4];
    int arow = w*16 + (lane & 15);
    int acb0 = (lane >> 4) << 4;
#pragma unroll
    for (int ks = 0; ks < 4; ks++) {
        uint32_t off = swzb(arow, ks*32 + acb0);
        ldsm4(qf[ks][0], qf[ks][1], qf[ks][2], qf[ks][3], smb + off);
    }
    __syncthreads();             // Q consumed; stage region reusable
    load_kv(0); load_kv(1); load_kv(2);

    float O[8][4];
#pragma unroll
    for (int nd = 0; nd < 8; nd++)
#pragma unroll
        for (int e = 0; e < 4; e++) O[nd][e] = 0.f;
    float m0 = -1e30f, m1 = -1e30f, l0 = 0.f, l1 = 0.f;

    int krow_b = (lane & 7) + ((lane >> 1) & 8);
    int kcb_b  = (lane & 8) << 1;
    int vrow_b = lane & 15;
    int vcb_b  = (lane >> 4) << 4;

#pragma unroll 1
    for (int kt = 0; kt < 16; kt++) {
        cpa_wait<2>();
        __syncthreads();
        if (kt + 3 < 16) load_kv(kt + 3);   // writes stage (kt+3)&3, last read at kt-1: safe
        uint32_t base = smb + (kt & 3)*0x4000;
        uint32_t bK = base, bV = base + 0x2000;

        float sc[8][4];
#pragma unroll
        for (int jj = 0; jj < 8; jj++)
#pragma unroll
            for (int e = 0; e < 4; e++) sc[jj][e] = 0.f;
#pragma unroll
        for (int ks = 0; ks < 4; ks++) {
#pragma unroll
            for (int p = 0; p < 4; p++) {
                uint32_t k4[4];
                int krow = 16*p + krow_b;
                ldsm4(k4[0], k4[1], k4[2], k4[3], bK + swzb(krow, ks*32 + kcb_b));
                mmaf16(sc[2*p],   qf[ks], k4+0);
                mmaf16(sc[2*p+1], qf[ks], k4+2);
            }
        }

        float rm0 = -1e30f, rm1 = -1e30f;
#pragma unroll
        for (int jj = 0; jj < 8; jj++) {
            rm0 = fmaxf(rm0, fmaxf(sc[jj][0], sc[jj][1]));
            rm1 = fmaxf(rm1, fmaxf(sc[jj][2], sc[jj][3]));
        }
        rm0 = fmaxf(rm0, __shfl_xor_sync(0xffffffffu, rm0, 1));
        rm0 = fmaxf(rm0, __shfl_xor_sync(0xffffffffu, rm0, 2));
        rm1 = fmaxf(rm1, __shfl_xor_sync(0xffffffffu, rm1, 1));
        rm1 = fmaxf(rm1, __shfl_xor_sync(0xffffffffu, rm1, 2));
        float mn0 = fmaxf(m0, rm0), mn1 = fmaxf(m1, rm1);
        float a0 = exp2f(m0 - mn0), a1 = exp2f(m1 - mn1);
        float rs0 = 0.f, rs1 = 0.f;
#pragma unroll
        for (int jj = 0; jj < 8; jj++) {
            sc[jj][0] = exp2f(sc[jj][0] - mn0);
            sc[jj][1] = exp2f(sc[jj][1] - mn0);
            sc[jj][2] = exp2f(sc[jj][2] - mn1);
            sc[jj][3] = exp2f(sc[jj][3] - mn1);
            rs0 += sc[jj][0] + sc[jj][1];
            rs1 += sc[jj][2] + sc[jj][3];
        }
        rs0 += __shfl_xor_sync(0xffffffffu, rs0, 1);
        rs0 += __shfl_xor_sync(0xffffffffu, rs0, 2);
        rs1 += __shfl_xor_sync(0xffffffffu, rs1, 1);
        rs1 += __shfl_xor_sync(0xffffffffu, rs1, 2);
        l0 = l0*a0 + rs0; l1 = l1*a1 + rs1;
        m0 = mn0; m1 = mn1;
#pragma unroll
        for (int nd = 0; nd < 8; nd++) {
            O[nd][0] *= a0; O[nd][1] *= a0;
            O[nd][2] *= a1; O[nd][3] *= a1;
        }

        uint32_t pf[4][4];
#pragma unroll
        for (int jj = 0; jj < 4; jj++) {
            pf[jj][0] = h2pack(sc[2*jj][0],   sc[2*jj][1]);
            pf[jj][1] = h2pack(sc[2*jj][2],   sc[2*jj][3]);
            pf[jj][2] = h2pack(sc[2*jj+1][0], sc[2*jj+1][1]);
            pf[jj][3] = h2pack(sc[2*jj+1][2], sc[2*jj+1][3]);
        }

#pragma unroll
        for (int ks2 = 0; ks2 < 4; ks2++) {
#pragma unroll
            for (int pp = 0; pp < 4; pp++) {
                uint32_t v4[4];
                int vrow = ks2*16 + vrow_b;
                ldsm4t(v4[0], v4[1], v4[2], v4[3], bV + swzb(vrow, pp*32 + vcb_b));
                mmaf16(O[2*pp],   pf[ks2], v4+0);
                mmaf16(O[2*pp+1], pf[ks2], v4+2);
            }
        }
    }

    float inv0 = 1.f / l0, inv1 = 1.f / l1;
    int g = lane >> 2, t2 = (lane & 3)*2;
    int bb = bh / NH, h = bh - bb*NH;
    int n0 = qt*128 + w*16 + g;
#pragma unroll
    for (int nd = 0; nd < 8; nd++) {
        int col = h*64 + nd*8 + t2;
        size_t o0 = ((size_t)bb*SEQ + n0)*CC + col;
        size_t o1 = ((size_t)bb*SEQ + n0 + 8)*CC + col;
        *(__half2*)(g_ao + o0) = __floats2half2_rn(O[nd][0]*inv0, O[nd][1]*inv0);
        *(__half2*)(g_ao + o1) = __floats2half2_rn(O[nd][2]*inv1, O[nd][3]*inv1);
    }
}

// ---------------------------------------------------------------------------
extern "C" void kernel_launch(void* const* d_in, const int* in_sizes, int n_in,
                              void* d_out, int out_size) {
    const float* x      = (const float*)d_in[0];
    const float* y      = (const float*)d_in[1];
    const float* q_w    = (const float*)d_in[2];
    const float* q_b    = (const float*)d_in[3];
    const float* kv_w   = (const float*)d_in[4];
    const float* kv_b   = (const float*)d_in[5];
    const float* proj_w = (const float*)d_in[6];
    const float* proj_b = (const float*)d_in[7];
    const float* ln_g   = (const float*)d_in[8];
    const float* ln_b   = (const float*)d_in[9];
    float* out = (float*)d_out;

    void *pao, *pp;
    cudaGetSymbolAddress(&pao, g_ao);
    cudaGetSymbolAddress(&pp,  g_p);

    prep_all<<<1184, 256>>>(x, q_w, kv_w, proj_w);
    ln_kernel<<<MM, 256>>>(y, ln_g, ln_b);

    int smq = 2*QSTG;   // 92160
    cudaFuncSetAttribute(qkv_fused, cudaFuncAttributeMaxDynamicSharedMemorySize, smq);
    qkv_fused<<<dim3(36, 64), 256, smq>>>(q_b, kv_b);

    int sma = 4*0x4000;   // 65536
    cudaFuncSetAttribute(attn_mma, cudaFuncAttributeMaxDynamicSharedMemorySize, sma);
    attn_mma<<<dim3(8, 96), 256, sma>>>();

    int smp = 2*PSTG;     // 73728
    cudaFuncSetAttribute(hgemm_proj, cudaFuncAttributeMaxDynamicSharedMemorySize, smp);
    hgemm_proj<<<dim3(6, 64), 256, smp>>>(
        (const __half*)pao, (const __half*)pp, out, proj_b);
}

// round 14
// speedup vs baseline: 6.3424x; 1.0113x over previous
#include <cuda_runtime.h>
#include <cuda_fp16.h>
#include <cstdint>

#define SEQ  1024
#define CC   768
#define NH   12
#define HD   64
#define MM   8192
#define NQKV 2304

__device__ __half g_x[MM*CC];
__device__ __half g_y[MM*CC];
__device__ __half g_w[NQKV*CC];
__device__ __half g_p[CC*CC];
__device__ __half g_q[MM*CC];                     // q * 0.125*log2(e)
__device__ __half g_k[MM*CC];
__device__ __half g_v[MM*CC];
__device__ __half g_ao[MM*CC];

#define LOG2E 1.4426950408889634f

// ---------------- helpers ----------------------------------------------------
__device__ __forceinline__ uint32_t smem_u32(const void* p) {
    uint32_t a;
    asm("{ .reg .u64 t; cvta.to.shared.u64 t, %1; cvt.u32.u64 %0, t; }" : "=r"(a) : "l"(p));
    return a;
}
__device__ __forceinline__ void cpa16(uint32_t s, const void* g) {
    asm volatile("cp.async.cg.shared.global [%0], [%1], 16;" :: "r"(s), "l"(g));
}
__device__ __forceinline__ void cpa_commit() { asm volatile("cp.async.commit_group;"); }
template<int N> __device__ __forceinline__ void cpa_wait() {
    asm volatile("cp.async.wait_group %0;" :: "n"(N));
}
__device__ __forceinline__ void ldsm4(uint32_t& r0, uint32_t& r1, uint32_t& r2, uint32_t& r3,
                                      uint32_t addr) {
    asm volatile("ldmatrix.sync.aligned.m8n8.x4.shared.b16 {%0,%1,%2,%3}, [%4];"
                 : "=r"(r0), "=r"(r1), "=r"(r2), "=r"(r3) : "r"(addr));
}
__device__ __forceinline__ void ldsm4t(uint32_t& r0, uint32_t& r1, uint32_t& r2, uint32_t& r3,
                                       uint32_t addr) {
    asm volatile("ldmatrix.sync.aligned.m8n8.x4.trans.shared.b16 {%0,%1,%2,%3}, [%4];"
                 : "=r"(r0), "=r"(r1), "=r"(r2), "=r"(r3) : "r"(addr));
}
__device__ __forceinline__ void mmaf16(float* c, const uint32_t* a, const uint32_t* b) {
    asm volatile("mma.sync.aligned.m16n8k16.row.col.f32.f16.f16.f32 "
                 "{%0,%1,%2,%3}, {%4,%5,%6,%7}, {%8,%9}, {%0,%1,%2,%3};"
                 : "+f"(c[0]), "+f"(c[1]), "+f"(c[2]), "+f"(c[3])
                 : "r"(a[0]), "r"(a[1]), "r"(a[2]), "r"(a[3]), "r"(b[0]), "r"(b[1]));
}
__device__ __forceinline__ uint32_t h2pack(float a, float b) {
    __half2 h = __floats2half2_rn(a, b);
    return *(uint32_t*)&h;
}
__device__ __forceinline__ uint32_t ex2h2(uint32_t in) {
    uint32_t r;
    asm("ex2.approx.f16x2 %0, %1;" : "=r"(r) : "r"(in));
    return r;
}
__device__ __forceinline__ float sigmoidf_(float x) { return 1.f/(1.f+__expf(-x)); }
__device__ __forceinline__ uint32_t swzb(int row, int cb) {
    return (uint32_t)(row*128 + ((((cb) >> 4) ^ (row & 7)) << 4));
}

// ---------------------------------------------------------------------------
__global__ void prep_all(const float* __restrict__ x, const float* __restrict__ qw,
                         const float* __restrict__ kvw, const float* __restrict__ pw) {
    const int NX = MM*CC, QW = CC*CC, KVW = 2*CC*CC, PW = CC*CC;
    const int T0 = NX, T1 = NX + QW, T2 = T1 + KVW, TOT = T2 + PW;
    for (int i = blockIdx.x*blockDim.x + threadIdx.x; i < TOT; i += gridDim.x*blockDim.x) {
        if (i < T0)      g_x[i] = __float2half_rn(x[i]);
        else if (i < T1) g_w[i - T0] = __float2half_rn(qw[i - T0]);
        else if (i < T2) g_w[i - T0] = __float2half_rn(kvw[i - T1]);
        else             g_p[i - T2] = __float2half_rn(pw[i - T2]);
    }
}

__global__ void ln_kernel(const float* __restrict__ y,
                          const float* __restrict__ gam, const float* __restrict__ bet) {
    int m = blockIdx.x, bb = m >> 10, n = m & 1023;
    const float* yp = y + (size_t)bb*CC*SEQ + n;
    float v[3]; float s = 0.f, s2 = 0.f;
#pragma unroll
    for (int i = 0; i < 3; i++) {
        int c = threadIdx.x + i*256;
        float t = yp[(size_t)c*SEQ];
        v[i] = t; s += t; s2 += t*t;
    }
#pragma unroll
    for (int o = 16; o > 0; o >>= 1) {
        s  += __shfl_xor_sync(0xffffffffu, s,  o);
        s2 += __shfl_xor_sync(0xffffffffu, s2, o);
    }
    __shared__ float rb[2][8];
    if ((threadIdx.x & 31) == 0) { rb[0][threadIdx.x>>5] = s; rb[1][threadIdx.x>>5] = s2; }
    __syncthreads();
    float ts = 0.f, ts2 = 0.f;
#pragma unroll
    for (int i = 0; i < 8; i++) { ts += rb[0][i]; ts2 += rb[1][i]; }
    float mean = ts*(1.f/CC), var = ts2*(1.f/CC) - mean*mean;
    float rstd = rsqrtf(var + 1e-5f);
#pragma unroll
    for (int i = 0; i < 3; i++) {
        int c = threadIdx.x + i*256;
        float o = (v[i]-mean)*rstd*gam[c] + bet[c];
        g_y[(size_t)m*CC + c] = __float2half_rn(o);
    }
}

// ---------------------------------------------------------------------------
// FUSED qkv GEMM + gating. 512 threads (16 warps = 8M x 2N), warp tile 16x32.
// K staged 64, single sync per stage. 2 CTAs/SM -> 32 warps/SM.
// ---------------------------------------------------------------------------
#define PITCH2 144
#define BUFX  18432
#define BUFW2 9216
#define QSTG  (2*BUFX + BUFW2)   // 46080

__global__ __launch_bounds__(512, 2)
void qkv_fused(const float* __restrict__ qb, const float* __restrict__ kvb) {
    extern __shared__ __align__(16) char smraw[];
    uint32_t smb = smem_u32(smraw);
    int t = threadIdx.x, lane = t & 31, w = t >> 5;
    int wm = w >> 1, wn = w & 1;          // wm 0..7, wn 0..1
    int bx = blockIdx.x;
    int m0 = blockIdx.y * 128;
    int j0 = bx * 64;

    const __half* sx = g_x + (size_t)m0*CC;
    const __half* sy = g_y + (size_t)m0*CC;
    const __half* sw = g_w + (size_t)j0*CC;

    auto load_stage = [&](int s, int k0) {
        uint32_t base = smb + (s & 1)*QSTG;
#pragma unroll
        for (int i = 0; i < 2; i++) {               // x, y: 1024 chunks each
            int c = t + i*512;
            int row = c >> 3, ch = c & 7;
            cpa16(base + row*PITCH2 + ch*16,        sx + (size_t)row*CC + k0 + ch*8);
            cpa16(base + BUFX + row*PITCH2 + ch*16, sy + (size_t)row*CC + k0 + ch*8);
        }
        {                                           // w: 512 chunks
            int row = t >> 3, ch = t & 7;
            cpa16(base + 2*BUFX + row*PITCH2 + ch*16, sw + (size_t)row*CC + k0 + ch*8);
        }
        cpa_commit();
    };

    float accx[4][4], accy[4][4];
#pragma unroll
    for (int ni = 0; ni < 4; ni++)
#pragma unroll
        for (int e = 0; e < 4; e++) { accx[ni][e] = 0.f; accy[ni][e] = 0.f; }

    load_stage(0, 0);

    const int NSTG = CC/64;   // 12
    int a_row  = wm*16 + (lane & 15);
    int a_coff = (lane >> 4) * 16;
    int b_row  = (lane & 7) + ((lane >> 1) & 8);
    int b_coff = (lane & 8) * 2;

#pragma unroll 1
    for (int s = 0; s < NSTG; s++) {
        cpa_wait<0>();
        __syncthreads();
        if (s + 1 < NSTG) load_stage(s + 1, (s + 1)*64);
        uint32_t bX = smb + (s & 1)*QSTG;
        uint32_t bY = bX + BUFX, bW = bX + 2*BUFX;
#pragma unroll
        for (int ks = 0; ks < 4; ks++) {
            int kb = ks*32;
            uint32_t xx[4], yy[4], bw[4][2];
            ldsm4(xx[0], xx[1], xx[2], xx[3], bX + a_row*PITCH2 + kb + a_coff);
            ldsm4(yy[0], yy[1], yy[2], yy[3], bY + a_row*PITCH2 + kb + a_coff);
#pragma unroll
            for (int p = 0; p < 2; p++) {
                int nr = wn*32 + p*16 + b_row;
                ldsm4(bw[2*p][0], bw[2*p][1], bw[2*p+1][0], bw[2*p+1][1],
                      bW + nr*PITCH2 + kb + b_coff);
            }
#pragma unroll
            for (int ni = 0; ni < 4; ni++) {
                mmaf16(accx[ni], xx, bw[ni]);
                mmaf16(accy[ni], yy, bw[ni]);
            }
        }
    }

    int sec = bx / 12;
    int h   = bx - sec*12;
#pragma unroll
    for (int e2 = 0; e2 < 2; e2++) {
        int r = m0 + wm*16 + (lane >> 2) + e2*8;
        int bb = r >> 10, n = r & 1023;
        size_t obase = (((size_t)bb*NH + h)*SEQ + n)*HD;
#pragma unroll
        for (int ni = 0; ni < 4; ni++) {
            int d = wn*32 + ni*8 + 2*(lane & 3);
            float ax0 = accx[ni][2*e2], ax1 = accx[ni][2*e2+1];
            float ay0 = accy[ni][2*e2], ay1 = accy[ni][2*e2+1];
            if (sec == 0) {
                float b0 = qb[j0 + d], b1 = qb[j0 + d + 1];
                float o0 = (0.125f*LOG2E)*(ax0+b0)*(1.f + sigmoidf_(ay0+b0));
                float o1 = (0.125f*LOG2E)*(ax1+b1)*(1.f + sigmoidf_(ay1+b1));
                *(__half2*)(g_q + obase + d) = __floats2half2_rn(o0, o1);
            } else {
                float b0 = kvb[j0 - CC + d], b1 = kvb[j0 - CC + d + 1];
                float o0 = sigmoidf_(ay0+b0)*(ax0+b0+1.f);
                float o1 = sigmoidf_(ay1+b1)*(ax1+b1+1.f);
                __half* dst = (sec == 1) ? g_k : g_v;
                *(__half2*)(dst + obase + d) = __floats2half2_rn(o0, o1);
            }
        }
    }
}

// ---------------------------------------------------------------------------
// proj GEMM (unchanged from R13).
// ---------------------------------------------------------------------------
#define BUFP  18432
#define PSTG  (2*BUFP)

__global__ __launch_bounds__(256, 2)
void hgemm_proj(const __half* __restrict__ A, const __half* __restrict__ W,
                float* __restrict__ C, const float* __restrict__ bias) {
    extern __shared__ __align__(16) char smraw[];
    uint32_t smb = smem_u32(smraw);
    int t = threadIdx.x, lane = t & 31, w = t >> 5;
    int wm = w >> 1, wn = w & 1;
    int am0 = blockIdx.y * 128, wn0 = blockIdx.x * 128;

    const __half* sa = A + (size_t)am0*CC;
    const __half* sw = W + (size_t)wn0*CC;

    auto load_stage = [&](int s, int k0) {
        uint32_t base = smb + (s & 1)*PSTG;
#pragma unroll
        for (int i = 0; i < 4; i++) {
            int c = t + i*256;
            int row = c >> 3, ch = c & 7;
            cpa16(base + row*PITCH2 + ch*16,        sa + (size_t)row*CC + k0 + ch*8);
            cpa16(base + BUFP + row*PITCH2 + ch*16, sw + (size_t)row*CC + k0 + ch*8);
        }
        cpa_commit();
    };

    float acc[2][8][4];
#pragma unroll
    for (int mi = 0; mi < 2; mi++)
#pragma unroll
        for (int ni = 0; ni < 8; ni++)
#pragma unroll
            for (int e = 0; e < 4; e++) acc[mi][ni][e] = 0.f;

    load_stage(0, 0);

    const int NSTG = CC/64;
    int a_row  = wm*32 + (lane & 15);
    int a_coff = (lane >> 4) * 16;
    int b_row  = (lane & 7) + ((lane >> 1) & 8);
    int b_coff = (lane & 8) * 2;

#pragma unroll 1
    for (int s = 0; s < NSTG; s++) {
        cpa_wait<0>();
        __syncthreads();
        if (s + 1 < NSTG) load_stage(s + 1, (s + 1)*64);
        uint32_t bA = smb + (s & 1)*PSTG;
        uint32_t bW = bA + BUFP;
#pragma unroll
        for (int ks = 0; ks < 4; ks++) {
            int kb = ks*32;
            uint32_t aa[2][4], bw[8][2];
            ldsm4(aa[0][0], aa[0][1], aa[0][2], aa[0][3], bA + (a_row)*PITCH2     + kb + a_coff);
            ldsm4(aa[1][0], aa[1][1], aa[1][2], aa[1][3], bA + (a_row+16)*PITCH2 + kb + a_coff);
#pragma unroll
            for (int p = 0; p < 4; p++) {
                int nr = wn*64 + p*16 + b_row;
                ldsm4(bw[2*p][0], bw[2*p][1], bw[2*p+1][0], bw[2*p+1][1],
                      bW + nr*PITCH2 + kb + b_coff);
            }
#pragma unroll
            for (int mi = 0; mi < 2; mi++)
#pragma unroll
                for (int ni = 0; ni < 8; ni++)
                    mmaf16(acc[mi][ni], aa[mi], bw[ni]);
        }
    }

#pragma unroll
    for (int mi = 0; mi < 2; mi++) {
        int row = am0 + wm*32 + mi*16 + (lane >> 2);
#pragma unroll
        for (int ni = 0; ni < 8; ni++) {
            int col = wn0 + wn*64 + ni*8 + 2*(lane & 3);
            float b0 = bias[col], b1 = bias[col+1];
            *(float2*)(C + (size_t)row*CC + col)     = make_float2(acc[mi][ni][0]+b0, acc[mi][ni][1]+b1);
            *(float2*)(C + (size_t)(row+8)*CC + col) = make_float2(acc[mi][ni][2]+b0, acc[mi][ni][3]+b1);
        }
    }
}

// ---------------------------------------------------------------------------
// TC flash attention: f16x2 ex2 for P, l via ones-MMA (tensor-pipe row sums).
// 128q x 64k tiles, 4-stage pipeline, 1 sync/iter.
// ---------------------------------------------------------------------------
__global__ __launch_bounds__(256, 2)
void attn_mma() {
    extern __shared__ __align__(16) char smraw[];
    uint32_t smb = smem_u32(smraw);
    int qt = blockIdx.x, bh = blockIdx.y;
    int t = threadIdx.x, lane = t & 31, w = t >> 5;
    const __half* qp = g_q + (size_t)bh*SEQ*HD + (size_t)qt*128*HD;
    const __half* kp = g_k + (size_t)bh*SEQ*HD;
    const __half* vp = g_v + (size_t)bh*SEQ*HD;

#pragma unroll
    for (int i = 0; i < 4; i++) {
        int c = t + i*256;
        int row = c >> 3, ch = c & 7;
        cpa16(smb + swzb(row, ch*16), qp + (size_t)row*HD + ch*8);
    }
    cpa_commit();

    auto load_kv = [&](int kt) {
        uint32_t base = smb + (kt & 3)*0x4000;
#pragma unroll
        for (int i = 0; i < 2; i++) {
            int c = t + i*256;
            int row = c >> 3, ch = c & 7;
            uint32_t off = swzb(row, ch*16);
            const size_t go = (size_t)(kt*64 + row)*HD + ch*8;
            cpa16(base + 0x0000 + off, kp + go);
            cpa16(base + 0x2000 + off, vp + go);
        }
        cpa_commit();
    };

    cpa_wait<0>();
    __syncthreads();

    uint32_t qf[4][4];
    int arow = w*16 + (lane & 15);
    int acb0 = (lane >> 4) << 4;
#pragma unroll
    for (int ks = 0; ks < 4; ks++) {
        uint32_t off = swzb(arow, ks*32 + acb0);
        ldsm4(qf[ks][0], qf[ks][1], qf[ks][2], qf[ks][3], smb + off);
    }
    __syncthreads();
    load_kv(0); load_kv(1); load_kv(2);

    float O[8][4], lacc[4];
#pragma unroll
    for (int nd = 0; nd < 8; nd++)
#pragma unroll
        for (int e = 0; e < 4; e++) O[nd][e] = 0.f;
#pragma unroll
    for (int e = 0; e < 4; e++) lacc[e] = 0.f;
    float m0 = -1e30f, m1 = -1e30f;

    const uint32_t ONES2 = 0x3C003C00u;          // (1.0h, 1.0h)
    uint32_t onesb[2] = { ONES2, ONES2 };

    int krow_b = (lane & 7) + ((lane >> 1) & 8);
    int kcb_b  = (lane & 8) << 1;
    int vrow_b = lane & 15;
    int vcb_b  = (lane >> 4) << 4;

#pragma unroll 1
    for (int kt = 0; kt < 16; kt++) {
        cpa_wait<2>();
        __syncthreads();
        if (kt + 3 < 16) load_kv(kt + 3);
        uint32_t base = smb + (kt & 3)*0x4000;
        uint32_t bK = base, bV = base + 0x2000;

        float sc[8][4];
#pragma unroll
        for (int jj = 0; jj < 8; jj++)
#pragma unroll
            for (int e = 0; e < 4; e++) sc[jj][e] = 0.f;
#pragma unroll
        for (int ks = 0; ks < 4; ks++) {
#pragma unroll
            for (int p = 0; p < 4; p++) {
                uint32_t k4[4];
                int krow = 16*p + krow_b;
                ldsm4(k4[0], k4[1], k4[2], k4[3], bK + swzb(krow, ks*32 + kcb_b));
                mmaf16(sc[2*p],   qf[ks], k4+0);
                mmaf16(sc[2*p+1], qf[ks], k4+2);
            }
        }

        // row max (rows g, g+8)
        float rm0 = -1e30f, rm1 = -1e30f;
#pragma unroll
        for (int jj = 0; jj < 8; jj++) {
            rm0 = fmaxf(rm0, fmaxf(sc[jj][0], sc[jj][1]));
            rm1 = fmaxf(rm1, fmaxf(sc[jj][2], sc[jj][3]));
        }
        rm0 = fmaxf(rm0, __shfl_xor_sync(0xffffffffu, rm0, 1));
        rm0 = fmaxf(rm0, __shfl_xor_sync(0xffffffffu, rm0, 2));
        rm1 = fmaxf(rm1, __shfl_xor_sync(0xffffffffu, rm1, 1));
        rm1 = fmaxf(rm1, __shfl_xor_sync(0xffffffffu, rm1, 2));
        float mn0 = fmaxf(m0, rm0), mn1 = fmaxf(m1, rm1);
        float a0 = exp2f(m0 - mn0), a1 = exp2f(m1 - mn1);
        m0 = mn0; m1 = mn1;
#pragma unroll
        for (int nd = 0; nd < 8; nd++) {
            O[nd][0] *= a0; O[nd][1] *= a0;
            O[nd][2] *= a1; O[nd][3] *= a1;
        }
        lacc[0] *= a0; lacc[1] *= a0; lacc[2] *= a1; lacc[3] *= a1;

        // P = exp2(sc - mn) directly in f16x2
        uint32_t pf[4][4];
#pragma unroll
        for (int jj = 0; jj < 4; jj++) {
            pf[jj][0] = ex2h2(h2pack(sc[2*jj][0]-mn0,   sc[2*jj][1]-mn0));
            pf[jj][1] = ex2h2(h2pack(sc[2*jj][2]-mn1,   sc[2*jj][3]-mn1));
            pf[jj][2] = ex2h2(h2pack(sc[2*jj+1][0]-mn0, sc[2*jj+1][1]-mn0));
            pf[jj][3] = ex2h2(h2pack(sc[2*jj+1][2]-mn1, sc[2*jj+1][3]-mn1));
        }

        // l += P @ ones  (tensor pipe does the row-sum reduction)
#pragma unroll
        for (int ks2 = 0; ks2 < 4; ks2++)
            mmaf16(lacc, pf[ks2], onesb);

        // O += P V
#pragma unroll
        for (int ks2 = 0; ks2 < 4; ks2++) {
#pragma unroll
            for (int pp = 0; pp < 4; pp++) {
                uint32_t v4[4];
                int vrow = ks2*16 + vrow_b;
                ldsm4t(v4[0], v4[1], v4[2], v4[3], bV + swzb(vrow, pp*32 + vcb_b));
                mmaf16(O[2*pp],   pf[ks2], v4+0);
                mmaf16(O[2*pp+1], pf[ks2], v4+2);
            }
        }
    }

    float inv0 = 1.f / lacc[0], inv1 = 1.f / lacc[2];
    int g = lane >> 2, t2 = (lane & 3)*2;
    int bb = bh / NH, h = bh - bb*NH;
    int n0 = qt*128 + w*16 + g;
#pragma unroll
    for (int nd = 0; nd < 8; nd++) {
        int col = h*64 + nd*8 + t2;
        size_t o0 = ((size_t)bb*SEQ + n0)*CC + col;
        size_t o1 = ((size_t)bb*SEQ + n0 + 8)*CC + col;
        *(__half2*)(g_ao + o0) = __floats2half2_rn(O[nd][0]*inv0, O[nd][1]*inv0);
        *(__half2*)(g_ao + o1) = __floats2half2_rn(O[nd][2]*inv1, O[nd][3]*inv1);
    }
}

// ---------------------------------------------------------------------------
extern "C" void kernel_launch(void* const* d_in, const int* in_sizes, int n_in,
                              void* d_out, int out_size) {
    const float* x      = (const float*)d_in[0];
    const float* y      = (const float*)d_in[1];
    const float* q_w    = (const float*)d_in[2];
    const float* q_b    = (const float*)d_in[3];
    const float* kv_w   = (const float*)d_in[4];
    const float* kv_b   = (const float*)d_in[5];
    const float* proj_w = (const float*)d_in[6];
    const float* proj_b = (const float*)d_in[7];
    const float* ln_g   = (const float*)d_in[8];
    const float* ln_b   = (const float*)d_in[9];
    float* out = (float*)d_out;

    void *pao, *pp;
    cudaGetSymbolAddress(&pao, g_ao);
    cudaGetSymbolAddress(&pp,  g_p);

    prep_all<<<1184, 256>>>(x, q_w, kv_w, proj_w);
    ln_kernel<<<MM, 256>>>(y, ln_g, ln_b);

    int smq = 2*QSTG;   // 92160
    cudaFuncSetAttribute(qkv_fused, cudaFuncAttributeMaxDynamicSharedMemorySize, smq);
    qkv_fused<<<dim3(36, 64), 512, smq>>>(q_b, kv_b);

    int sma = 4*0x4000;
    cudaFuncSetAttribute(attn_mma, cudaFuncAttributeMaxDynamicSharedMemorySize, sma);
    attn_mma<<<dim3(8, 96), 256, sma>>>();

    int smp = 2*PSTG;
    cudaFuncSetAttribute(hgemm_proj, cudaFuncAttributeMaxDynamicSharedMemorySize, smp);
    hgemm_proj<<<dim3(6, 64), 256, smp>>>(
        (const __half*)pao, (const __half*)pp, out, proj_b);
}

// round 15
// speedup vs baseline: 6.6863x; 1.0542x over previous
#include <cuda_runtime.h>
#include <cuda_fp16.h>
#include <cstdint>

#define SEQ  1024
#define CC   768
#define NH   12
#define HD   64
#define MM   8192
#define NQKV 2304

__device__ __half g_x[MM*CC];
__device__ __half g_y[MM*CC];
__device__ __half g_w[NQKV*CC];
__device__ __half g_p[CC*CC];
__device__ __half g_q[MM*CC];                     // q * 0.125*log2(e)
__device__ __half g_k[MM*CC];
__device__ __half g_v[MM*CC];
__device__ __half g_ao[MM*CC];

#define LOG2E 1.4426950408889634f

// ---------------- helpers ----------------------------------------------------
__device__ __forceinline__ uint32_t smem_u32(const void* p) {
    uint32_t a;
    asm("{ .reg .u64 t; cvta.to.shared.u64 t, %1; cvt.u32.u64 %0, t; }" : "=r"(a) : "l"(p));
    return a;
}
__device__ __forceinline__ void cpa16(uint32_t s, const void* g) {
    asm volatile("cp.async.cg.shared.global [%0], [%1], 16;" :: "r"(s), "l"(g));
}
__device__ __forceinline__ void cpa_commit() { asm volatile("cp.async.commit_group;"); }
template<int N> __device__ __forceinline__ void cpa_wait() {
    asm volatile("cp.async.wait_group %0;" :: "n"(N));
}
__device__ __forceinline__ void ldsm4(uint32_t& r0, uint32_t& r1, uint32_t& r2, uint32_t& r3,
                                      uint32_t addr) {
    asm volatile("ldmatrix.sync.aligned.m8n8.x4.shared.b16 {%0,%1,%2,%3}, [%4];"
                 : "=r"(r0), "=r"(r1), "=r"(r2), "=r"(r3) : "r"(addr));
}
__device__ __forceinline__ void ldsm4t(uint32_t& r0, uint32_t& r1, uint32_t& r2, uint32_t& r3,
                                       uint32_t addr) {
    asm volatile("ldmatrix.sync.aligned.m8n8.x4.trans.shared.b16 {%0,%1,%2,%3}, [%4];"
                 : "=r"(r0), "=r"(r1), "=r"(r2), "=r"(r3) : "r"(addr));
}
__device__ __forceinline__ void mmaf16(float* c, const uint32_t* a, const uint32_t* b) {
    asm volatile("mma.sync.aligned.m16n8k16.row.col.f32.f16.f16.f32 "
                 "{%0,%1,%2,%3}, {%4,%5,%6,%7}, {%8,%9}, {%0,%1,%2,%3};"
                 : "+f"(c[0]), "+f"(c[1]), "+f"(c[2]), "+f"(c[3])
                 : "r"(a[0]), "r"(a[1]), "r"(a[2]), "r"(a[3]), "r"(b[0]), "r"(b[1]));
}
__device__ __forceinline__ uint32_t h2pack(float a, float b) {
    __half2 h = __floats2half2_rn(a, b);
    return *(uint32_t*)&h;
}
__device__ __forceinline__ uint32_t ex2h2(uint32_t in) {
    uint32_t r;
    asm("ex2.approx.f16x2 %0, %1;" : "=r"(r) : "r"(in));
    return r;
}
__device__ __forceinline__ float sigmoidf_(float x) { return 1.f/(1.f+__expf(-x)); }
__device__ __forceinline__ uint32_t swzb(int row, int cb) {
    return (uint32_t)(row*128 + ((((cb) >> 4) ^ (row & 7)) << 4));
}

// ---------------------------------------------------------------------------
__global__ void prep_all(const float* __restrict__ x, const float* __restrict__ qw,
                         const float* __restrict__ kvw, const float* __restrict__ pw) {
    const int NX = MM*CC, QW = CC*CC, KVW = 2*CC*CC, PW = CC*CC;
    const int T0 = NX, T1 = NX + QW, T2 = T1 + KVW, TOT = T2 + PW;
    for (int i = blockIdx.x*blockDim.x + threadIdx.x; i < TOT; i += gridDim.x*blockDim.x) {
        if (i < T0)      g_x[i] = __float2half_rn(x[i]);
        else if (i < T1) g_w[i - T0] = __float2half_rn(qw[i - T0]);
        else if (i < T2) g_w[i - T0] = __float2half_rn(kvw[i - T1]);
        else             g_p[i - T2] = __float2half_rn(pw[i - T2]);
    }
}

// ---------------------------------------------------------------------------
// Coalesced LN: block = (b, 32 hw positions). Tile-transpose in fp32 smem
// (pitch 773 floats -> conflict-free both phases), warp-reduced stats,
// coalesced f16 writes.
// ---------------------------------------------------------------------------
#define LNP 773

__global__ void ln_kernel(const float* __restrict__ y,
                          const float* __restrict__ gam, const float* __restrict__ bet) {
    extern __shared__ float sv[];           // 32 * LNP floats
    __shared__ float sstat[32][2];
    int b = blockIdx.y, hw0 = blockIdx.x*32;
    const float* yb = y + (size_t)b*CC*SEQ + hw0;
    int t = threadIdx.x, w = t >> 5, lane = t & 31;

    // load: coalesced along hw (32 consecutive floats per (c) row)
#pragma unroll 8
    for (int i = 0; i < 96; i++) {
        int li = t + i*256;
        int c = li >> 5, j = li & 31;
        sv[j*LNP + c] = yb[(size_t)c*SEQ + j];
    }
    __syncthreads();

    // stats: warp w handles rows 4w..4w+3
#pragma unroll
    for (int rr = 0; rr < 4; rr++) {
        int r = w*4 + rr;
        float s = 0.f, s2 = 0.f;
#pragma unroll
        for (int c = lane; c < CC; c += 32) {
            float v = sv[r*LNP + c];
            s += v; s2 += v*v;
        }
#pragma unroll
        for (int o = 16; o > 0; o >>= 1) {
            s  += __shfl_xor_sync(0xffffffffu, s,  o);
            s2 += __shfl_xor_sync(0xffffffffu, s2, o);
        }
        if (lane == 0) {
            float mean = s*(1.f/CC), var = s2*(1.f/CC) - mean*mean;
            sstat[r][0] = mean;
            sstat[r][1] = rsqrtf(var + 1e-5f);
        }
    }
    __syncthreads();

    // normalize + write coalesced (row-major f16)
#pragma unroll
    for (int rr = 0; rr < 4; rr++) {
        int r = w*4 + rr;
        float mean = sstat[r][0], rstd = sstat[r][1];
        size_t mrow = ((size_t)b*SEQ + hw0 + r)*CC;
#pragma unroll
        for (int c2 = lane; c2 < 384; c2 += 32) {
            int c = c2*2;
            float o0 = (sv[r*LNP + c]   - mean)*rstd*gam[c]   + bet[c];
            float o1 = (sv[r*LNP + c+1] - mean)*rstd*gam[c+1] + bet[c+1];
            *(__half2*)(g_y + mrow + c) = __floats2half2_rn(o0, o1);
        }
    }
}

// ---------------------------------------------------------------------------
// FUSED qkv GEMM + gating. 256 threads (R13 config). K staged 64, 1 sync/stage.
// ---------------------------------------------------------------------------
#define PITCH2 144
#define BUFX  18432
#define BUFW2 9216
#define QSTG  (2*BUFX + BUFW2)   // 46080

__global__ __launch_bounds__(256, 2)
void qkv_fused(const float* __restrict__ qb, const float* __restrict__ kvb) {
    extern __shared__ __align__(16) char smraw[];
    uint32_t smb = smem_u32(smraw);
    int t = threadIdx.x, lane = t & 31, w = t >> 5;
    int wm = w >> 1, wn = w & 1;
    int bx = blockIdx.x;
    int m0 = blockIdx.y * 128;
    int j0 = bx * 64;

    const __half* sx = g_x + (size_t)m0*CC;
    const __half* sy = g_y + (size_t)m0*CC;
    const __half* sw = g_w + (size_t)j0*CC;

    auto load_stage = [&](int s, int k0) {
        uint32_t base = smb + (s & 1)*QSTG;
#pragma unroll
        for (int i = 0; i < 4; i++) {
            int c = t + i*256;
            int row = c >> 3, ch = c & 7;
            cpa16(base + row*PITCH2 + ch*16,          sx + (size_t)row*CC + k0 + ch*8);
            cpa16(base + BUFX + row*PITCH2 + ch*16,   sy + (size_t)row*CC + k0 + ch*8);
        }
#pragma unroll
        for (int i = 0; i < 2; i++) {
            int c = t + i*256;
            int row = c >> 3, ch = c & 7;
            cpa16(base + 2*BUFX + row*PITCH2 + ch*16, sw + (size_t)row*CC + k0 + ch*8);
        }
        cpa_commit();
    };

    float accx[2][4][4], accy[2][4][4];
#pragma unroll
    for (int mi = 0; mi < 2; mi++)
#pragma unroll
        for (int ni = 0; ni < 4; ni++)
#pragma unroll
            for (int e = 0; e < 4; e++) { accx[mi][ni][e] = 0.f; accy[mi][ni][e] = 0.f; }

    load_stage(0, 0);

    const int NSTG = CC/64;   // 12
    int a_row  = wm*32 + (lane & 15);
    int a_coff = (lane >> 4) * 16;
    int b_row  = (lane & 7) + ((lane >> 1) & 8);
    int b_coff = (lane & 8) * 2;

#pragma unroll 1
    for (int s = 0; s < NSTG; s++) {
        cpa_wait<0>();
        __syncthreads();
        if (s + 1 < NSTG) load_stage(s + 1, (s + 1)*64);
        uint32_t bX = smb + (s & 1)*QSTG;
        uint32_t bY = bX + BUFX, bW = bX + 2*BUFX;
#pragma unroll
        for (int ks = 0; ks < 4; ks++) {
            int kb = ks*32;
            uint32_t xx[2][4], yy[2][4], bw[4][2];
            ldsm4(xx[0][0], xx[0][1], xx[0][2], xx[0][3], bX + (a_row)*PITCH2     + kb + a_coff);
            ldsm4(xx[1][0], xx[1][1], xx[1][2], xx[1][3], bX + (a_row+16)*PITCH2 + kb + a_coff);
            ldsm4(yy[0][0], yy[0][1], yy[0][2], yy[0][3], bY + (a_row)*PITCH2     + kb + a_coff);
            ldsm4(yy[1][0], yy[1][1], yy[1][2], yy[1][3], bY + (a_row+16)*PITCH2 + kb + a_coff);
#pragma unroll
            for (int p = 0; p < 2; p++) {
                int nr = wn*32 + p*16 + b_row;
                ldsm4(bw[2*p][0], bw[2*p][1], bw[2*p+1][0], bw[2*p+1][1],
                      bW + nr*PITCH2 + kb + b_coff);
            }
#pragma unroll
            for (int mi = 0; mi < 2; mi++)
#pragma unroll
                for (int ni = 0; ni < 4; ni++) {
                    mmaf16(accx[mi][ni], xx[mi], bw[ni]);
                    mmaf16(accy[mi][ni], yy[mi], bw[ni]);
                }
        }
    }

    int sec = bx / 12;
    int h   = bx - sec*12;
#pragma unroll
    for (int mi = 0; mi < 2; mi++) {
#pragma unroll
        for (int e2 = 0; e2 < 2; e2++) {
            int r = m0 + wm*32 + mi*16 + (lane >> 2) + e2*8;
            int bb = r >> 10, n = r & 1023;
            size_t obase = (((size_t)bb*NH + h)*SEQ + n)*HD;
#pragma unroll
            for (int ni = 0; ni < 4; ni++) {
                int d = wn*32 + ni*8 + 2*(lane & 3);
                float ax0 = accx[mi][ni][2*e2], ax1 = accx[mi][ni][2*e2+1];
                float ay0 = accy[mi][ni][2*e2], ay1 = accy[mi][ni][2*e2+1];
                if (sec == 0) {
                    float b0 = qb[j0 + d], b1 = qb[j0 + d + 1];
                    float o0 = (0.125f*LOG2E)*(ax0+b0)*(1.f + sigmoidf_(ay0+b0));
                    float o1 = (0.125f*LOG2E)*(ax1+b1)*(1.f + sigmoidf_(ay1+b1));
                    *(__half2*)(g_q + obase + d) = __floats2half2_rn(o0, o1);
                } else {
                    float b0 = kvb[j0 - CC + d], b1 = kvb[j0 - CC + d + 1];
                    float o0 = sigmoidf_(ay0+b0)*(ax0+b0+1.f);
                    float o1 = sigmoidf_(ay1+b1)*(ax1+b1+1.f);
                    __half* dst = (sec == 1) ? g_k : g_v;
                    *(__half2*)(dst + obase + d) = __floats2half2_rn(o0, o1);
                }
            }
        }
    }
}

// ---------------------------------------------------------------------------
// proj GEMM (unchanged).
// ---------------------------------------------------------------------------
#define BUFP  18432
#define PSTG  (2*BUFP)

__global__ __launch_bounds__(256, 2)
void hgemm_proj(const __half* __restrict__ A, const __half* __restrict__ W,
                float* __restrict__ C, const float* __restrict__ bias) {
    extern __shared__ __align__(16) char smraw[];
    uint32_t smb = smem_u32(smraw);
    int t = threadIdx.x, lane = t & 31, w = t >> 5;
    int wm = w >> 1, wn = w & 1;
    int am0 = blockIdx.y * 128, wn0 = blockIdx.x * 128;

    const __half* sa = A + (size_t)am0*CC;
    const __half* sw = W + (size_t)wn0*CC;

    auto load_stage = [&](int s, int k0) {
        uint32_t base = smb + (s & 1)*PSTG;
#pragma unroll
        for (int i = 0; i < 4; i++) {
            int c = t + i*256;
            int row = c >> 3, ch = c & 7;
            cpa16(base + row*PITCH2 + ch*16,        sa + (size_t)row*CC + k0 + ch*8);
            cpa16(base + BUFP + row*PITCH2 + ch*16, sw + (size_t)row*CC + k0 + ch*8);
        }
        cpa_commit();
    };

    float acc[2][8][4];
#pragma unroll
    for (int mi = 0; mi < 2; mi++)
#pragma unroll
        for (int ni = 0; ni < 8; ni++)
#pragma unroll
            for (int e = 0; e < 4; e++) acc[mi][ni][e] = 0.f;

    load_stage(0, 0);

    const int NSTG = CC/64;
    int a_row  = wm*32 + (lane & 15);
    int a_coff = (lane >> 4) * 16;
    int b_row  = (lane & 7) + ((lane >> 1) & 8);
    int b_coff = (lane & 8) * 2;

#pragma unroll 1
    for (int s = 0; s < NSTG; s++) {
        cpa_wait<0>();
        __syncthreads();
        if (s + 1 < NSTG) load_stage(s + 1, (s + 1)*64);
        uint32_t bA = smb + (s & 1)*PSTG;
        uint32_t bW = bA + BUFP;
#pragma unroll
        for (int ks = 0; ks < 4; ks++) {
            int kb = ks*32;
            uint32_t aa[2][4], bw[8][2];
            ldsm4(aa[0][0], aa[0][1], aa[0][2], aa[0][3], bA + (a_row)*PITCH2     + kb + a_coff);
            ldsm4(aa[1][0], aa[1][1], aa[1][2], aa[1][3], bA + (a_row+16)*PITCH2 + kb + a_coff);
#pragma unroll
            for (int p = 0; p < 4; p++) {
                int nr = wn*64 + p*16 + b_row;
                ldsm4(bw[2*p][0], bw[2*p][1], bw[2*p+1][0], bw[2*p+1][1],
                      bW + nr*PITCH2 + kb + b_coff);
            }
#pragma unroll
            for (int mi = 0; mi < 2; mi++)
#pragma unroll
                for (int ni = 0; ni < 8; ni++)
                    mmaf16(acc[mi][ni], aa[mi], bw[ni]);
        }
    }

#pragma unroll
    for (int mi = 0; mi < 2; mi++) {
        int row = am0 + wm*32 + mi*16 + (lane >> 2);
#pragma unroll
        for (int ni = 0; ni < 8; ni++) {
            int col = wn0 + wn*64 + ni*8 + 2*(lane & 3);
            float b0 = bias[col], b1 = bias[col+1];
            *(float2*)(C + (size_t)row*CC + col)     = make_float2(acc[mi][ni][0]+b0, acc[mi][ni][1]+b1);
            *(float2*)(C + (size_t)(row+8)*CC + col) = make_float2(acc[mi][ni][2]+b0, acc[mi][ni][3]+b1);
        }
    }
}

// ---------------------------------------------------------------------------
// TC flash attention (unchanged from R14): f16x2 ex2 P, ones-MMA row sums.
// ---------------------------------------------------------------------------
__global__ __launch_bounds__(256, 2)
void attn_mma() {
    extern __shared__ __align__(16) char smraw[];
    uint32_t smb = smem_u32(smraw);
    int qt = blockIdx.x, bh = blockIdx.y;
    int t = threadIdx.x, lane = t & 31, w = t >> 5;
    const __half* qp = g_q + (size_t)bh*SEQ*HD + (size_t)qt*128*HD;
    const __half* kp = g_k + (size_t)bh*SEQ*HD;
    const __half* vp = g_v + (size_t)bh*SEQ*HD;

#pragma unroll
    for (int i = 0; i < 4; i++) {
        int c = t + i*256;
        int row = c >> 3, ch = c & 7;
        cpa16(smb + swzb(row, ch*16), qp + (size_t)row*HD + ch*8);
    }
    cpa_commit();

    auto load_kv = [&](int kt) {
        uint32_t base = smb + (kt & 3)*0x4000;
#pragma unroll
        for (int i = 0; i < 2; i++) {
            int c = t + i*256;
            int row = c >> 3, ch = c & 7;
            uint32_t off = swzb(row, ch*16);
            const size_t go = (size_t)(kt*64 + row)*HD + ch*8;
            cpa16(base + 0x0000 + off, kp + go);
            cpa16(base + 0x2000 + off, vp + go);
        }
        cpa_commit();
    };

    cpa_wait<0>();
    __syncthreads();

    uint32_t qf[4][4];
    int arow = w*16 + (lane & 15);
    int acb0 = (lane >> 4) << 4;
#pragma unroll
    for (int ks = 0; ks < 4; ks++) {
        uint32_t off = swzb(arow, ks*32 + acb0);
        ldsm4(qf[ks][0], qf[ks][1], qf[ks][2], qf[ks][3], smb + off);
    }
    __syncthreads();
    load_kv(0); load_kv(1); load_kv(2);

    float O[8][4], lacc[4];
#pragma unroll
    for (int nd = 0; nd < 8; nd++)
#pragma unroll
        for (int e = 0; e < 4; e++) O[nd][e] = 0.f;
#pragma unroll
    for (int e = 0; e < 4; e++) lacc[e] = 0.f;
    float m0 = -1e30f, m1 = -1e30f;

    const uint32_t ONES2 = 0x3C003C00u;
    uint32_t onesb[2] = { ONES2, ONES2 };

    int krow_b = (lane & 7) + ((lane >> 1) & 8);
    int kcb_b  = (lane & 8) << 1;
    int vrow_b = lane & 15;
    int vcb_b  = (lane >> 4) << 4;

#pragma unroll 1
    for (int kt = 0; kt < 16; kt++) {
        cpa_wait<2>();
        __syncthreads();
        if (kt + 3 < 16) load_kv(kt + 3);
        uint32_t base = smb + (kt & 3)*0x4000;
        uint32_t bK = base, bV = base + 0x2000;

        float sc[8][4];
#pragma unroll
        for (int jj = 0; jj < 8; jj++)
#pragma unroll
            for (int e = 0; e < 4; e++) sc[jj][e] = 0.f;
#pragma unroll
        for (int ks = 0; ks < 4; ks++) {
#pragma unroll
            for (int p = 0; p < 4; p++) {
                uint32_t k4[4];
                int krow = 16*p + krow_b;
                ldsm4(k4[0], k4[1], k4[2], k4[3], bK + swzb(krow, ks*32 + kcb_b));
                mmaf16(sc[2*p],   qf[ks], k4+0);
                mmaf16(sc[2*p+1], qf[ks], k4+2);
            }
        }

        float rm0 = -1e30f, rm1 = -1e30f;
#pragma unroll
        for (int jj = 0; jj < 8; jj++) {
            rm0 = fmaxf(rm0, fmaxf(sc[jj][0], sc[jj][1]));
            rm1 = fmaxf(rm1, fmaxf(sc[jj][2], sc[jj][3]));
        }
        rm0 = fmaxf(rm0, __shfl_xor_sync(0xffffffffu, rm0, 1));
        rm0 = fmaxf(rm0, __shfl_xor_sync(0xffffffffu, rm0, 2));
        rm1 = fmaxf(rm1, __shfl_xor_sync(0xffffffffu, rm1, 1));
        rm1 = fmaxf(rm1, __shfl_xor_sync(0xffffffffu, rm1, 2));
        float mn0 = fmaxf(m0, rm0), mn1 = fmaxf(m1, rm1);
        float a0 = exp2f(m0 - mn0), a1 = exp2f(m1 - mn1);
        m0 = mn0; m1 = mn1;
#pragma unroll
        for (int nd = 0; nd < 8; nd++) {
            O[nd][0] *= a0; O[nd][1] *= a0;
            O[nd][2] *= a1; O[nd][3] *= a1;
        }
        lacc[0] *= a0; lacc[1] *= a0; lacc[2] *= a1; lacc[3] *= a1;

        uint32_t pf[4][4];
#pragma unroll
        for (int jj = 0; jj < 4; jj++) {
            pf[jj][0] = ex2h2(h2pack(sc[2*jj][0]-mn0,   sc[2*jj][1]-mn0));
            pf[jj][1] = ex2h2(h2pack(sc[2*jj][2]-mn1,   sc[2*jj][3]-mn1));
            pf[jj][2] = ex2h2(h2pack(sc[2*jj+1][0]-mn0, sc[2*jj+1][1]-mn0));
            pf[jj][3] = ex2h2(h2pack(sc[2*jj+1][2]-mn1, sc[2*jj+1][3]-mn1));
        }

#pragma unroll
        for (int ks2 = 0; ks2 < 4; ks2++)
            mmaf16(lacc, pf[ks2], onesb);

#pragma unroll
        for (int ks2 = 0; ks2 < 4; ks2++) {
#pragma unroll
            for (int pp = 0; pp < 4; pp++) {
                uint32_t v4[4];
                int vrow = ks2*16 + vrow_b;
                ldsm4t(v4[0], v4[1], v4[2], v4[3], bV + swzb(vrow, pp*32 + vcb_b));
                mmaf16(O[2*pp],   pf[ks2], v4+0);
                mmaf16(O[2*pp+1], pf[ks2], v4+2);
            }
        }
    }

    float inv0 = 1.f / lacc[0], inv1 = 1.f / lacc[2];
    int g = lane >> 2, t2 = (lane & 3)*2;
    int bb = bh / NH, h = bh - bb*NH;
    int n0 = qt*128 + w*16 + g;
#pragma unroll
    for (int nd = 0; nd < 8; nd++) {
        int col = h*64 + nd*8 + t2;
        size_t o0 = ((size_t)bb*SEQ + n0)*CC + col;
        size_t o1 = ((size_t)bb*SEQ + n0 + 8)*CC + col;
        *(__half2*)(g_ao + o0) = __floats2half2_rn(O[nd][0]*inv0, O[nd][1]*inv0);
        *(__half2*)(g_ao + o1) = __floats2half2_rn(O[nd][2]*inv1, O[nd][3]*inv1);
    }
}

// ---------------------------------------------------------------------------
extern "C" void kernel_launch(void* const* d_in, const int* in_sizes, int n_in,
                              void* d_out, int out_size) {
    const float* x      = (const float*)d_in[0];
    const float* y      = (const float*)d_in[1];
    const float* q_w    = (const float*)d_in[2];
    const float* q_b    = (const float*)d_in[3];
    const float* kv_w   = (const float*)d_in[4];
    const float* kv_b   = (const float*)d_in[5];
    const float* proj_w = (const float*)d_in[6];
    const float* proj_b = (const float*)d_in[7];
    const float* ln_g   = (const float*)d_in[8];
    const float* ln_b   = (const float*)d_in[9];
    float* out = (float*)d_out;

    void *pao, *pp;
    cudaGetSymbolAddress(&pao, g_ao);
    cudaGetSymbolAddress(&pp,  g_p);

    prep_all<<<1184, 256>>>(x, q_w, kv_w, proj_w);

    int smln = 32*LNP*(int)sizeof(float);   // 98944
    cudaFuncSetAttribute(ln_kernel, cudaFuncAttributeMaxDynamicSharedMemorySize, smln);
    ln_kernel<<<dim3(32, 8), 256, smln>>>(y, ln_g, ln_b);

    int smq = 2*QSTG;
    cudaFuncSetAttribute(qkv_fused, cudaFuncAttributeMaxDynamicSharedMemorySize, smq);
    qkv_fused<<<dim3(36, 64), 256, smq>>>(q_b, kv_b);

    int sma = 4*0x4000;
    cudaFuncSetAttribute(attn_mma, cudaFuncAttributeMaxDynamicSharedMemorySize, sma);
    attn_mma<<<dim3(8, 96), 256, sma>>>();

    int smp = 2*PSTG;
    cudaFuncSetAttribute(hgemm_proj, cudaFuncAttributeMaxDynamicSharedMemorySize, smp);
    hgemm_proj<<<dim3(6, 64), 256, smp>>>(
        (const __half*)pao, (const __half*)pp, out, proj_b);
}